// round 3
// baseline (speedup 1.0000x reference)
#include <cuda_runtime.h>
#include <math.h>

#define BB 16384
#define XD 2000
#define HD 100
#define ZD 20
#define KTOT (2*XD)      // 4000
#define LN_EPS 1e-5f

// ---------------- scratch (static device globals; no allocations) -------------
__device__ float g_h1 [(size_t)BB*HD];
__device__ float g_h1g[(size_t)BB*HD];
__device__ float g_th [(size_t)BB*HD];
__device__ float g_ld [(size_t)BB*XD];
__device__ float g_tld[(size_t)BB*XD];
__device__ float g_beta [XD];
__device__ float g_gamma[XD];

// ---------------- helpers -----------------------------------------------------
__device__ __forceinline__ float softplusf(float x) {
    return fmaxf(x, 0.f) + log1pf(expf(-fabsf(x)));
}
__device__ __forceinline__ float sigmoidf(float x) {
    return 1.f / (1.f + expf(-x));
}
__device__ __forceinline__ float geluf(float x) {
    return 0.5f * x * (1.f + erff(x * 0.70710678118654752f));
}
__device__ __forceinline__ float wsum(float v) {
#pragma unroll
    for (int o = 16; o; o >>= 1) v += __shfl_xor_sync(0xffffffffu, v, o);
    return v;
}

// packed f32x2 FMA: d.lo += a.lo*b.lo ; d.hi += a.hi*b.hi  (bit-identical to fmaf)
#define FMA2(d, a, b) asm("fma.rn.f32x2 %0, %1, %2, %0;" : "+l"(d) : "l"(a), "l"(b))

__device__ __forceinline__ float2 unpk(unsigned long long v) {
    float2 r;
    asm("mov.b64 {%0, %1}, %2;" : "=f"(r.x), "=f"(r.y) : "l"(v));
    return r;
}

// ---------------- k0: beta/gamma precompute ----------------------------------
__global__ void k0_rates(const float* __restrict__ lb, const float* __restrict__ lg) {
    int i = blockIdx.x * blockDim.x + threadIdx.x;
    if (i < XD) {
        g_beta[i]  = softplusf(lb[i]);   // * DT (=1)
        g_gamma[i] = softplusf(lg[i]);
    }
}

// ---------------- k1: h1 = gelu(LN([s,u]@W1 + b1)) ----------------------------
// M=32 rows/block, N=128 (100 valid). KC=32 double-buffered stages.
// A stored transposed [k][m]; W stored DUPLICATED ({w,w} pairs) so the inner
// loop is 8 FFMA2 + 3 LDS.128 per k.
#define KC 32
#define K1_SMEM_FLOATS (2*KC*36 + 2*KC*264)
__global__ void __launch_bounds__(256) k1_enc1(
    const float* __restrict__ s, const float* __restrict__ u,
    const float* __restrict__ w1, const float* __restrict__ b1)
{
    extern __shared__ float sm1[];
    float (*Ast)[KC][36]  = (float (*)[KC][36])sm1;                 // [buf][k][m]
    float (*Wd )[KC][264] = (float (*)[KC][264])(sm1 + 2*KC*36);    // [buf][k][dup n]

    int tid = threadIdx.x;
    int tn = tid & 31, tm = tid >> 5;
    int m0 = blockIdx.x * 32;

    // zero dup-pad region [200,256) in both buffers (cols >= 100)
    for (int i = tid; i < 2 * KC * 56; i += 256) {
        int b = i / (KC * 56);
        int r = (i / 56) % KC;
        int c = 200 + (i % 56);
        Wd[b][r][c] = 0.f;
    }

    // staging thread mapping
    int aM  = tid >> 3;            // 0..31 row within tile
    int aK4 = (tid & 7) * 4;       // 0..28 k offset (float4)
    int wRow[4], wC4[4];
#pragma unroll
    for (int t = 0; t < 4; t++) {
        int lin = tid + t * 256;   // t==3 only valid for tid<32 (800 float4/stage)
        wRow[t] = lin / 25;
        wC4 [t] = (lin - wRow[t] * 25) * 4;
    }

    float4 aReg;
    float4 wReg[4];

    // prefetch stage 0
    {
        int gk = aK4;
        const float* base = (gk < XD) ? &s[(size_t)(m0 + aM) * XD + gk]
                                      : &u[(size_t)(m0 + aM) * XD + gk - XD];
        aReg = *(const float4*)base;
#pragma unroll
        for (int t = 0; t < 3; t++)
            wReg[t] = *(const float4*)&w1[(size_t)wRow[t] * HD + wC4[t]];
        if (tid < 32)
            wReg[3] = *(const float4*)&w1[(size_t)wRow[3] * HD + wC4[3]];
    }

    unsigned long long accp[2][4];
#pragma unroll
    for (int p = 0; p < 2; p++)
#pragma unroll
        for (int j = 0; j < 4; j++) accp[p][j] = 0ull;

    float bv[4] = {0.f, 0.f, 0.f, 0.f};
    if (tn < 25) {
        float4 b = *(const float4*)&b1[tn * 4];
        bv[0] = b.x; bv[1] = b.y; bv[2] = b.z; bv[3] = b.w;
    }

    int buf = 0;
    for (int kb = 0; kb < KTOT; kb += KC) {
        // STS current stage (A transposed; W duplicated)
        Ast[buf][aK4 + 0][aM] = aReg.x;
        Ast[buf][aK4 + 1][aM] = aReg.y;
        Ast[buf][aK4 + 2][aM] = aReg.z;
        Ast[buf][aK4 + 3][aM] = aReg.w;
#pragma unroll
        for (int t = 0; t < 3; t++) {
            float4 v = wReg[t];
            *(float4*)&Wd[buf][wRow[t]][wC4[t] * 2]     = make_float4(v.x, v.x, v.y, v.y);
            *(float4*)&Wd[buf][wRow[t]][wC4[t] * 2 + 4] = make_float4(v.z, v.z, v.w, v.w);
        }
        if (tid < 32) {
            float4 v = wReg[3];
            *(float4*)&Wd[buf][wRow[3]][wC4[3] * 2]     = make_float4(v.x, v.x, v.y, v.y);
            *(float4*)&Wd[buf][wRow[3]][wC4[3] * 2 + 4] = make_float4(v.z, v.z, v.w, v.w);
        }
        __syncthreads();

        // prefetch next stage
        int kn = kb + KC;
        if (kn < KTOT) {
            int gk = kn + aK4;
            const float* base = (gk < XD) ? &s[(size_t)(m0 + aM) * XD + gk]
                                          : &u[(size_t)(m0 + aM) * XD + gk - XD];
            aReg = *(const float4*)base;
#pragma unroll
            for (int t = 0; t < 3; t++)
                wReg[t] = *(const float4*)&w1[(size_t)(kn + wRow[t]) * HD + wC4[t]];
            if (tid < 32)
                wReg[3] = *(const float4*)&w1[(size_t)(kn + wRow[3]) * HD + wC4[3]];
        }

        // compute: 8 FFMA2 + 3 LDS.128 per k
#pragma unroll
        for (int k = 0; k < KC; k++) {
            ulonglong2 ap = *(const ulonglong2*)&Ast[buf][k][tm * 4];
            ulonglong2 wa = *(const ulonglong2*)&Wd [buf][k][tn * 8];
            ulonglong2 wb = *(const ulonglong2*)&Wd [buf][k][tn * 8 + 4];
            FMA2(accp[0][0], ap.x, wa.x);
            FMA2(accp[0][1], ap.x, wa.y);
            FMA2(accp[0][2], ap.x, wb.x);
            FMA2(accp[0][3], ap.x, wb.y);
            FMA2(accp[1][0], ap.y, wa.x);
            FMA2(accp[1][1], ap.y, wa.y);
            FMA2(accp[1][2], ap.y, wb.x);
            FMA2(accp[1][3], ap.y, wb.y);
        }
        __syncthreads();
        buf ^= 1;
    }

    // unpack: rows tm*4 + 2p + e, cols tn*4 + j
    float acc[4][4];
#pragma unroll
    for (int p = 0; p < 2; p++)
#pragma unroll
        for (int j = 0; j < 4; j++) {
            float2 v = unpk(accp[p][j]);
            acc[2 * p][j] = v.x;
            acc[2 * p + 1][j] = v.y;
        }

    // per-row LN + GELU
#pragma unroll
    for (int i = 0; i < 4; i++) {
        int m = m0 + tm * 4 + i;
        float x[4], sm = 0.f, sq = 0.f;
#pragma unroll
        for (int j = 0; j < 4; j++) {
            x[j] = acc[i][j] + bv[j];
            sm += x[j];
            sq += x[j] * x[j];
        }
        sm = wsum(sm); sq = wsum(sq);
        float mean = sm * (1.f / HD);
        float var  = sq * (1.f / HD) - mean * mean;
        float rs = rsqrtf(var + LN_EPS);
        if (tn < 25) {
            float4 o;
            o.x = geluf((x[0] - mean) * rs);
            o.y = geluf((x[1] - mean) * rs);
            o.z = geluf((x[2] - mean) * rs);
            o.w = geluf((x[3] - mean) * rs);
            *(float4*)&g_h1[(size_t)m * HD + tn * 4] = o;
        }
    }
}

// ---------------- k2: everything small, one warp per row ----------------------
#define K2_SMEM_FLOATS (22380 + 8*264)
__global__ void __launch_bounds__(256) k2_mid(
    const float* __restrict__ eps_z, const float* __restrict__ eps_d,
    const float* __restrict__ w2, const float* __restrict__ b2,
    const float* __restrict__ wmu, const float* __restrict__ bmu,
    const float* __restrict__ wlv, const float* __restrict__ blv,
    const float* __restrict__ edw1, const float* __restrict__ edb1,
    const float* __restrict__ edwmu, const float* __restrict__ edbmu,
    const float* __restrict__ edwlv, const float* __restrict__ edblv,
    const float* __restrict__ dzw1, const float* __restrict__ dzb1,
    float* __restrict__ o_z, float* __restrict__ o_dz,
    float* __restrict__ o_muz, float* __restrict__ o_scz,
    float* __restrict__ o_mud, float* __restrict__ o_scd)
{
    extern __shared__ float sm2[];
    float* sw2    = sm2;              // 10000
    float* swmu   = sw2 + 10000;      // 2000
    float* swlv   = swmu + 2000;      // 2000
    float* sb2    = swlv + 2000;      // 100
    float* sbmu   = sb2 + 100;        // 20
    float* sblv   = sbmu + 20;        // 20
    float* sedw1  = sblv + 20;        // 2000
    float* sedb1  = sedw1 + 2000;     // 100
    float* sedwmu = sedb1 + 100;      // 2000
    float* sedbmu = sedwmu + 2000;    // 20
    float* sedwlv = sedbmu + 20;      // 2000
    float* sedblv = sedwlv + 2000;    // 20
    float* sdzw1  = sedblv + 20;      // 2000
    float* sdzb1  = sdzw1 + 2000;     // 100
    float* wbuf   = sdzb1 + 100;      // 8 warps * 264

    {
        int t = threadIdx.x, nt = blockDim.x;
        for (int i = t; i < 10000; i += nt) sw2[i] = w2[i];
        for (int i = t; i < 2000; i += nt) { swmu[i] = wmu[i]; swlv[i] = wlv[i]; }
        for (int i = t; i < 2000; i += nt) { sedw1[i] = edw1[i]; sdzw1[i] = dzw1[i]; }
        for (int i = t; i < 2000; i += nt) { sedwmu[i] = edwmu[i]; sedwlv[i] = edwlv[i]; }
        for (int i = t; i < 100; i += nt) { sb2[i] = b2[i]; sedb1[i] = edb1[i]; sdzb1[i] = dzb1[i]; }
        if (t < 20) { sbmu[t] = bmu[t]; sblv[t] = blv[t]; sedbmu[t] = edbmu[t]; sedblv[t] = edblv[t]; }
    }
    __syncthreads();

    int wid = threadIdx.x >> 5, lane = threadIdx.x & 31;
    float* B0 = wbuf + wid * 264;
    float* B1 = B0 + 132;
    int nwarps = gridDim.x * 8;

    for (int r = blockIdx.x * 8 + wid; r < BB; r += nwarps) {
        for (int i = lane; i < HD; i += 32) B0[i] = g_h1[(size_t)r * HD + i];
        __syncwarp();

        // ---- h2 = gelu(LN(h1@w2 + b2)) ----
        float x[4];
#pragma unroll
        for (int j = 0; j < 4; j++) {
            int n = lane + 32 * j;
            float acc = 0.f;
            if (n < HD) {
                acc = sb2[n];
                for (int k = 0; k < HD; k++) acc += B0[k] * sw2[k * HD + n];
            }
            x[j] = acc;
        }
        float smv = x[0] + x[1] + x[2] + x[3];
        float sqv = x[0]*x[0] + x[1]*x[1] + x[2]*x[2] + x[3]*x[3];
        smv = wsum(smv); sqv = wsum(sqv);
        float mean = smv * (1.f / HD);
        float rs = rsqrtf(sqv * (1.f / HD) - mean * mean + LN_EPS);
#pragma unroll
        for (int j = 0; j < 4; j++) {
            int n = lane + 32 * j;
            if (n < HD) B1[n] = geluf((x[j] - mean) * rs);
        }
        __syncwarp();

        // ---- z heads ----
        if (lane < ZD) {
            float mu = sbmu[lane], lv = sblv[lane];
            for (int k = 0; k < HD; k++) {
                float h = B1[k];
                mu += h * swmu[k * ZD + lane];
                lv += h * swlv[k * ZD + lane];
            }
            float sc = softplusf(lv);
            float z = mu + sc * eps_z[(size_t)r * ZD + lane];
            o_z  [(size_t)r * ZD + lane] = z;
            o_muz[(size_t)r * ZD + lane] = mu;
            o_scz[(size_t)r * ZD + lane] = sc;
            B0[lane] = z;
        }
        __syncwarp();

        // ---- hd = gelu(LN(z@ed_w1 + b)) ----
#pragma unroll
        for (int j = 0; j < 4; j++) {
            int n = lane + 32 * j;
            float acc = 0.f;
            if (n < HD) {
                acc = sedb1[n];
                for (int k = 0; k < ZD; k++) acc += B0[k] * sedw1[k * HD + n];
            }
            x[j] = acc;
        }
        smv = x[0] + x[1] + x[2] + x[3];
        sqv = x[0]*x[0] + x[1]*x[1] + x[2]*x[2] + x[3]*x[3];
        smv = wsum(smv); sqv = wsum(sqv);
        mean = smv * (1.f / HD);
        rs = rsqrtf(sqv * (1.f / HD) - mean * mean + LN_EPS);
#pragma unroll
        for (int j = 0; j < 4; j++) {
            int n = lane + 32 * j;
            if (n < HD) B1[n] = geluf((x[j] - mean) * rs);
        }
        __syncwarp();

        // ---- d heads ----
        if (lane < ZD) {
            float mu = sedbmu[lane], lv = sedblv[lane];
            for (int k = 0; k < HD; k++) {
                float h = B1[k];
                mu += h * sedwmu[k * ZD + lane];
                lv += h * sedwlv[k * ZD + lane];
            }
            float sc = softplusf(lv);
            float dz = mu + sc * eps_d[(size_t)r * ZD + lane];
            o_dz [(size_t)r * ZD + lane] = dz;
            o_mud[(size_t)r * ZD + lane] = mu;
            o_scd[(size_t)r * ZD + lane] = sc;
            B0[32 + lane] = dz;
        }
        __syncwarp();

        // ---- decoder layer 1 with JVP ----
        float a[4], t[4];
#pragma unroll
        for (int j = 0; j < 4; j++) {
            int n = lane + 32 * j;
            float aa = 0.f, tt = 0.f;
            if (n < HD) {
                aa = sdzb1[n];
                for (int k = 0; k < ZD; k++) {
                    float w = sdzw1[k * HD + n];
                    aa += B0[k] * w;
                    tt += B0[32 + k] * w;
                }
            }
            a[j] = aa; t[j] = tt;
        }
        float sa = a[0]+a[1]+a[2]+a[3];
        float saa = a[0]*a[0]+a[1]*a[1]+a[2]*a[2]+a[3]*a[3];
        float st = t[0]+t[1]+t[2]+t[3];
        float sat = a[0]*t[0]+a[1]*t[1]+a[2]*t[2]+a[3]*t[3];
        sa = wsum(sa); saa = wsum(saa); st = wsum(st); sat = wsum(sat);
        float m  = sa * (1.f / HD);
        float v  = saa * (1.f / HD) - m * m;
        float r2 = rsqrtf(v + LN_EPS);
        float dm = st * (1.f / HD);
        float dv = 2.f * (sat * (1.f / HD) - m * dm);
#pragma unroll
        for (int j = 0; j < 4; j++) {
            int n = lane + 32 * j;
            if (n < HD) {
                float y  = (a[j] - m) * r2;
                float dy = r2 * (t[j] - dm) - 0.5f * y * r2 * r2 * dv;
                float Phi = 0.5f * (1.f + erff(y * 0.70710678118654752f));
                float phi = 0.3989422804014327f * expf(-0.5f * y * y);
                g_h1g[(size_t)r * HD + n] = y * Phi;
                g_th [(size_t)r * HD + n] = (Phi + y * phi) * dy;
            }
        }
        __syncwarp();
    }
}

// ---------------- k3: big decoder GEMM (primal + tangent), FFMA2 --------------
// Tile M=64, N=64. W dup-stored [k][{w,w}...] (100x132), H/T transposed [k][m]
// (100x68 each). Inner loop: 16 FFMA2 + 4 LDS.128 per k.
#define K3_SMEM_FLOATS (100*132 + 2*100*68)
__global__ void __launch_bounds__(256, 2) k3_dec(
    const float* __restrict__ w2, const float* __restrict__ b2)
{
    extern __shared__ float sm3[];
    float (*Wd)[132] = (float (*)[132])sm3;                       // 100 x 132 (dup)
    float (*Hs)[68]  = (float (*)[68])(sm3 + 100 * 132);          // [k][m]
    float (*Ts)[68]  = (float (*)[68])(sm3 + 100 * 132 + 100 * 68);

    int tid = threadIdx.x;
    int tn = tid & 15, tm = tid >> 4;
    int n0 = blockIdx.x * 64;
    int m0 = blockIdx.y * 64;

    // stage W dup: 100 k x 64 cols -> [k][2c],[2c+1]
    for (int lin = tid; lin < 1600; lin += 256) {
        int k = lin >> 4, c4 = (lin & 15) * 4;
        float4 v = make_float4(0.f, 0.f, 0.f, 0.f);
        if (n0 + c4 < XD) v = *(const float4*)&w2[(size_t)k * XD + n0 + c4];
        *(float4*)&Wd[k][c4 * 2]     = make_float4(v.x, v.x, v.y, v.y);
        *(float4*)&Wd[k][c4 * 2 + 4] = make_float4(v.z, v.z, v.w, v.w);
    }
    // stage H, T transposed: read float4 along k, scatter to [k][m]
    for (int lin = tid; lin < 1600; lin += 256) {
        int m = lin / 25, k4 = (lin - m * 25) * 4;
        float4 h = *(const float4*)&g_h1g[(size_t)(m0 + m) * HD + k4];
        float4 t = *(const float4*)&g_th [(size_t)(m0 + m) * HD + k4];
        Hs[k4 + 0][m] = h.x; Hs[k4 + 1][m] = h.y; Hs[k4 + 2][m] = h.z; Hs[k4 + 3][m] = h.w;
        Ts[k4 + 0][m] = t.x; Ts[k4 + 1][m] = t.y; Ts[k4 + 2][m] = t.z; Ts[k4 + 3][m] = t.w;
    }
    __syncthreads();

    unsigned long long aH[2][4], aT[2][4];
#pragma unroll
    for (int p = 0; p < 2; p++)
#pragma unroll
        for (int j = 0; j < 4; j++) { aH[p][j] = 0ull; aT[p][j] = 0ull; }

#pragma unroll 4
    for (int k = 0; k < HD; k++) {
        ulonglong2 hp = *(const ulonglong2*)&Hs[k][tm * 4];
        ulonglong2 tp = *(const ulonglong2*)&Ts[k][tm * 4];
        ulonglong2 wa = *(const ulonglong2*)&Wd[k][tn * 8];
        ulonglong2 wb = *(const ulonglong2*)&Wd[k][tn * 8 + 4];
        FMA2(aH[0][0], hp.x, wa.x); FMA2(aH[0][1], hp.x, wa.y);
        FMA2(aH[0][2], hp.x, wb.x); FMA2(aH[0][3], hp.x, wb.y);
        FMA2(aH[1][0], hp.y, wa.x); FMA2(aH[1][1], hp.y, wa.y);
        FMA2(aH[1][2], hp.y, wb.x); FMA2(aH[1][3], hp.y, wb.y);
        FMA2(aT[0][0], tp.x, wa.x); FMA2(aT[0][1], tp.x, wa.y);
        FMA2(aT[0][2], tp.x, wb.x); FMA2(aT[0][3], tp.x, wb.y);
        FMA2(aT[1][0], tp.y, wa.x); FMA2(aT[1][1], tp.y, wa.y);
        FMA2(aT[1][2], tp.y, wb.x); FMA2(aT[1][3], tp.y, wb.y);
    }

    int nc = n0 + tn * 4;
    if (nc >= XD) return;
    float4 bb = *(const float4*)&b2[nc];
    float bj[4] = {bb.x, bb.y, bb.z, bb.w};

    float a[4][4], t[4][4];
#pragma unroll
    for (int p = 0; p < 2; p++)
#pragma unroll
        for (int j = 0; j < 4; j++) {
            float2 vh = unpk(aH[p][j]);
            float2 vt = unpk(aT[p][j]);
            a[2 * p][j] = vh.x; a[2 * p + 1][j] = vh.y;
            t[2 * p][j] = vt.x; t[2 * p + 1][j] = vt.y;
        }

#pragma unroll
    for (int i = 0; i < 4; i++) {
        int row = m0 + tm * 4 + i;
        float4 lo, to; float av;
        av = a[i][0] + bj[0]; lo.x = softplusf(av); to.x = sigmoidf(av) * t[i][0];
        av = a[i][1] + bj[1]; lo.y = softplusf(av); to.y = sigmoidf(av) * t[i][1];
        av = a[i][2] + bj[2]; lo.z = softplusf(av); to.z = sigmoidf(av) * t[i][2];
        av = a[i][3] + bj[3]; lo.w = softplusf(av); to.w = sigmoidf(av) * t[i][3];
        *(float4*)&g_ld [(size_t)row * XD + nc] = lo;
        *(float4*)&g_tld[(size_t)row * XD + nc] = to;
    }
}

// ---------------- k4: per-row sums + finalize ---------------------------------
__global__ void __launch_bounds__(256) k4_fin(
    float* __restrict__ o_shat, float* __restrict__ o_diff, float* __restrict__ o_pu)
{
    __shared__ float red[16];
    int r = blockIdx.x;
    int tid = threadIdx.x;

    float4 l[2], tl[2];
    float sl = 0.f, st = 0.f;
#pragma unroll
    for (int j = 0; j < 2; j++) {
        int c = (tid + j * 256) * 4;
        if (c < XD) {
            l [j] = *(const float4*)&g_ld [(size_t)r * XD + c];
            tl[j] = *(const float4*)&g_tld[(size_t)r * XD + c];
            sl += l [j].x + l [j].y + l [j].z + l [j].w;
            st += tl[j].x + tl[j].y + tl[j].z + tl[j].w;
        }
    }
    sl = wsum(sl); st = wsum(st);
    int wid = tid >> 5, lane = tid & 31;
    if (lane == 0) { red[wid] = sl; red[8 + wid] = st; }
    __syncthreads();
    sl = red[0]+red[1]+red[2]+red[3]+red[4]+red[5]+red[6]+red[7];
    st = red[8]+red[9]+red[10]+red[11]+red[12]+red[13]+red[14]+red[15];

    float m  = sl * (1.f / XD);
    float mt = st * (1.f / XD);
    float rm = 1.f / m;
    float cm = mt * rm * rm;

#pragma unroll
    for (int j = 0; j < 2; j++) {
        int c = (tid + j * 256) * 4;
        if (c < XD) {
            float4 be = *(const float4*)&g_beta[c];
            float4 ga = *(const float4*)&g_gamma[c];
            float4 sh, df, pu;
            sh.x = l[j].x * rm; df.x = 0.01f * (tl[j].x * rm - l[j].x * cm);
            sh.y = l[j].y * rm; df.y = 0.01f * (tl[j].y * rm - l[j].y * cm);
            sh.z = l[j].z * rm; df.z = 0.01f * (tl[j].z * rm - l[j].z * cm);
            sh.w = l[j].w * rm; df.w = 0.01f * (tl[j].w * rm - l[j].w * cm);
            pu.x = fmaxf((df.x + sh.x * ga.x) / be.x, 0.f);
            pu.y = fmaxf((df.y + sh.y * ga.y) / be.y, 0.f);
            pu.z = fmaxf((df.z + sh.z * ga.z) / be.z, 0.f);
            pu.w = fmaxf((df.w + sh.w * ga.w) / be.w, 0.f);
            *(float4*)&o_shat[(size_t)r * XD + c] = sh;
            *(float4*)&o_diff[(size_t)r * XD + c] = df;
            *(float4*)&o_pu  [(size_t)r * XD + c] = pu;
        }
    }
}

// ---------------- launcher ----------------------------------------------------
extern "C" void kernel_launch(void* const* d_in, const int* in_sizes, int n_in,
                              void* d_out, int out_size)
{
    const float* s      = (const float*)d_in[0];
    const float* u      = (const float*)d_in[1];
    const float* eps_z  = (const float*)d_in[2];
    const float* eps_d  = (const float*)d_in[3];
    const float* ez_w1  = (const float*)d_in[4];
    const float* ez_b1  = (const float*)d_in[5];
    const float* ez_w2  = (const float*)d_in[6];
    const float* ez_b2  = (const float*)d_in[7];
    const float* ez_wmu = (const float*)d_in[8];
    const float* ez_bmu = (const float*)d_in[9];
    const float* ez_wlv = (const float*)d_in[10];
    const float* ez_blv = (const float*)d_in[11];
    const float* ed_w1  = (const float*)d_in[12];
    const float* ed_b1  = (const float*)d_in[13];
    const float* ed_wmu = (const float*)d_in[14];
    const float* ed_bmu = (const float*)d_in[15];
    const float* ed_wlv = (const float*)d_in[16];
    const float* ed_blv = (const float*)d_in[17];
    const float* dz_w1  = (const float*)d_in[18];
    const float* dz_b1  = (const float*)d_in[19];
    const float* dz_w2  = (const float*)d_in[20];
    const float* dz_b2  = (const float*)d_in[21];
    const float* logb   = (const float*)d_in[22];
    const float* logg   = (const float*)d_in[23];

    float* out = (float*)d_out;
    float* o_z    = out;
    float* o_dz   = o_z    + (size_t)BB * ZD;
    float* o_muz  = o_dz   + (size_t)BB * ZD;
    float* o_scz  = o_muz  + (size_t)BB * ZD;
    float* o_mud  = o_scz  + (size_t)BB * ZD;
    float* o_scd  = o_mud  + (size_t)BB * ZD;
    float* o_shat = o_scd  + (size_t)BB * ZD;
    float* o_diff = o_shat + (size_t)BB * XD;
    float* o_pu   = o_diff + (size_t)BB * XD;

    const int smem1 = K1_SMEM_FLOATS * 4;
    const int smem2 = K2_SMEM_FLOATS * 4;
    const int smem3 = K3_SMEM_FLOATS * 4;
    cudaFuncSetAttribute(k1_enc1, cudaFuncAttributeMaxDynamicSharedMemorySize, smem1);
    cudaFuncSetAttribute(k2_mid, cudaFuncAttributeMaxDynamicSharedMemorySize, smem2);
    cudaFuncSetAttribute(k3_dec, cudaFuncAttributeMaxDynamicSharedMemorySize, smem3);

    k0_rates<<<8, 256>>>(logb, logg);
    k1_enc1<<<BB / 32, 256, smem1>>>(s, u, ez_w1, ez_b1);
    k2_mid<<<512, 256, smem2>>>(eps_z, eps_d,
                                ez_w2, ez_b2, ez_wmu, ez_bmu, ez_wlv, ez_blv,
                                ed_w1, ed_b1, ed_wmu, ed_bmu, ed_wlv, ed_blv,
                                dz_w1, dz_b1,
                                o_z, o_dz, o_muz, o_scz, o_mud, o_scd);
    dim3 g3(32, 256);
    k3_dec<<<g3, 256, smem3>>>(dz_w2, dz_b2);
    k4_fin<<<BB, 256>>>(o_shat, o_diff, o_pu);
}

// round 4
// speedup vs baseline: 1.8276x; 1.8276x over previous
#include <cuda_runtime.h>
#include <math.h>

#define BB 16384
#define XD 2000
#define HD 100
#define ZD 20
#define KTOT (2*XD)      // 4000
#define LN_EPS 1e-5f

// ---------------- scratch (static device globals; no allocations) -------------
__device__ float g_h1 [(size_t)BB*HD];
__device__ float g_h1g[(size_t)BB*HD];
__device__ float g_th [(size_t)BB*HD];
__device__ float g_ld [(size_t)BB*XD];
__device__ float g_tld[(size_t)BB*XD];
__device__ float g_beta [XD];
__device__ float g_gamma[XD];

// ---------------- helpers -----------------------------------------------------
__device__ __forceinline__ float softplusf(float x) {
    return fmaxf(x, 0.f) + log1pf(expf(-fabsf(x)));
}
__device__ __forceinline__ float sigmoidf(float x) {
    return 1.f / (1.f + expf(-x));
}
__device__ __forceinline__ float geluf(float x) {
    return 0.5f * x * (1.f + erff(x * 0.70710678118654752f));
}
__device__ __forceinline__ float wsum(float v) {
#pragma unroll
    for (int o = 16; o; o >>= 1) v += __shfl_xor_sync(0xffffffffu, v, o);
    return v;
}

// packed f32x2 FMA: d.lo += a.lo*b.lo ; d.hi += a.hi*b.hi  (bit-identical to fmaf)
#define FMA2(d, a, b) asm("fma.rn.f32x2 %0, %1, %2, %0;" : "+l"(d) : "l"(a), "l"(b))

__device__ __forceinline__ float2 unpk(unsigned long long v) {
    float2 r;
    asm("mov.b64 {%0, %1}, %2;" : "=f"(r.x), "=f"(r.y) : "l"(v));
    return r;
}

// ---------------- k0: beta/gamma precompute ----------------------------------
__global__ void k0_rates(const float* __restrict__ lb, const float* __restrict__ lg) {
    int i = blockIdx.x * blockDim.x + threadIdx.x;
    if (i < XD) {
        g_beta[i]  = softplusf(lb[i]);   // * DT (=1)
        g_gamma[i] = softplusf(lg[i]);
    }
}

// ---------------- k1: h1 = gelu(LN([s,u]@W1 + b1)) ----------------------------
// M=64 rows/block (256 blocks), N=128 (100 valid). KC=32 double-buffered.
// A stored DUP-transposed [k][{a,a} per row] (read only as broadcast);
// W stored plain [k][n] (contiguous per-lane float4, conflict-free).
// Inner loop per k: 16 FFMA2 + 4 broadcast LDS.128 + 1 contiguous LDS.128.
#define KC 32
#define K1_SMEM_FLOATS (2*KC*132 + 2*KC*132)
__global__ void __launch_bounds__(256, 2) k1_enc1(
    const float* __restrict__ s, const float* __restrict__ u,
    const float* __restrict__ w1, const float* __restrict__ b1)
{
    extern __shared__ float sm1[];
    float (*Ad)[KC][132] = (float (*)[KC][132])sm1;               // [buf][k][2m dup]
    float (*Ws)[KC][132] = (float (*)[KC][132])(sm1 + 2*KC*132);  // [buf][k][n]

    int tid = threadIdx.x;
    int tn = tid & 31, tm = tid >> 5;
    int m0 = blockIdx.x * 64;

    // zero W pad cols [100,128) in both buffers (read by tn>=25)
    for (int i = tid; i < 2 * KC * 28; i += 256) {
        int b = i / (KC * 28);
        int r = (i / 28) % KC;
        int c = 100 + (i % 28);
        Ws[b][r][c] = 0.f;
    }

    // A staging: 64 rows x KC k = 512 float4 -> 2 per thread
    int aM[2], aK4[2];
#pragma unroll
    for (int t = 0; t < 2; t++) {
        int idx = tid + t * 256;
        aM [t] = idx >> 3;
        aK4[t] = (idx & 7) * 4;
    }
    // W staging: KC x 100 = 800 float4 -> 3/thread + 32 extra
    int wRow[4], wC4[4];
#pragma unroll
    for (int t = 0; t < 4; t++) {
        int lin = tid + t * 256;
        wRow[t] = lin / 25;
        wC4 [t] = (lin - wRow[t] * 25) * 4;
    }

    float4 aReg[2];
    float4 wReg[4];

    // prefetch stage 0
#pragma unroll
    for (int t = 0; t < 2; t++) {
        int gk = aK4[t];
        const float* base = (gk < XD) ? &s[(size_t)(m0 + aM[t]) * XD + gk]
                                      : &u[(size_t)(m0 + aM[t]) * XD + gk - XD];
        aReg[t] = *(const float4*)base;
    }
#pragma unroll
    for (int t = 0; t < 3; t++)
        wReg[t] = *(const float4*)&w1[(size_t)wRow[t] * HD + wC4[t]];
    if (tid < 32)
        wReg[3] = *(const float4*)&w1[(size_t)wRow[3] * HD + wC4[3]];

    unsigned long long acc[8][2];
#pragma unroll
    for (int i = 0; i < 8; i++) { acc[i][0] = 0ull; acc[i][1] = 0ull; }

    float bv[4] = {0.f, 0.f, 0.f, 0.f};
    if (tn < 25) {
        float4 b = *(const float4*)&b1[tn * 4];
        bv[0] = b.x; bv[1] = b.y; bv[2] = b.z; bv[3] = b.w;
    }

    int buf = 0;
    for (int kb = 0; kb < KTOT; kb += KC) {
        // store current stage: A dup pairs, W plain
#pragma unroll
        for (int t = 0; t < 2; t++) {
            float v[4] = {aReg[t].x, aReg[t].y, aReg[t].z, aReg[t].w};
#pragma unroll
            for (int e = 0; e < 4; e++) {
                float2 d; d.x = v[e]; d.y = v[e];
                *(float2*)&Ad[buf][aK4[t] + e][2 * aM[t]] = d;
            }
        }
#pragma unroll
        for (int t = 0; t < 3; t++)
            *(float4*)&Ws[buf][wRow[t]][wC4[t]] = wReg[t];
        if (tid < 32)
            *(float4*)&Ws[buf][wRow[3]][wC4[3]] = wReg[3];
        __syncthreads();

        // prefetch next stage
        int kn = kb + KC;
        if (kn < KTOT) {
#pragma unroll
            for (int t = 0; t < 2; t++) {
                int gk = kn + aK4[t];
                const float* base = (gk < XD) ? &s[(size_t)(m0 + aM[t]) * XD + gk]
                                              : &u[(size_t)(m0 + aM[t]) * XD + gk - XD];
                aReg[t] = *(const float4*)base;
            }
#pragma unroll
            for (int t = 0; t < 3; t++)
                wReg[t] = *(const float4*)&w1[(size_t)(kn + wRow[t]) * HD + wC4[t]];
            if (tid < 32)
                wReg[3] = *(const float4*)&w1[(size_t)(kn + wRow[3]) * HD + wC4[3]];
        }

        // compute: per k, 1 contiguous LDS.128 (W) + 4 broadcast LDS.128 (Adup)
        // + 16 FFMA2
#pragma unroll 8
        for (int k = 0; k < KC; k++) {
            ulonglong2 wp = *(const ulonglong2*)&Ws[buf][k][tn * 4];
            ulonglong2 ap0 = *(const ulonglong2*)&Ad[buf][k][tm * 16];
            ulonglong2 ap1 = *(const ulonglong2*)&Ad[buf][k][tm * 16 + 4];
            ulonglong2 ap2 = *(const ulonglong2*)&Ad[buf][k][tm * 16 + 8];
            ulonglong2 ap3 = *(const ulonglong2*)&Ad[buf][k][tm * 16 + 12];
            FMA2(acc[0][0], ap0.x, wp.x); FMA2(acc[0][1], ap0.x, wp.y);
            FMA2(acc[1][0], ap0.y, wp.x); FMA2(acc[1][1], ap0.y, wp.y);
            FMA2(acc[2][0], ap1.x, wp.x); FMA2(acc[2][1], ap1.x, wp.y);
            FMA2(acc[3][0], ap1.y, wp.x); FMA2(acc[3][1], ap1.y, wp.y);
            FMA2(acc[4][0], ap2.x, wp.x); FMA2(acc[4][1], ap2.x, wp.y);
            FMA2(acc[5][0], ap2.y, wp.x); FMA2(acc[5][1], ap2.y, wp.y);
            FMA2(acc[6][0], ap3.x, wp.x); FMA2(acc[6][1], ap3.x, wp.y);
            FMA2(acc[7][0], ap3.y, wp.x); FMA2(acc[7][1], ap3.y, wp.y);
        }
        buf ^= 1;
    }

    // per-row LN + GELU (8 rows per thread)
#pragma unroll
    for (int i = 0; i < 8; i++) {
        int m = m0 + tm * 8 + i;
        float2 v0 = unpk(acc[i][0]);
        float2 v1 = unpk(acc[i][1]);
        float x[4];
        x[0] = v0.x + bv[0]; x[1] = v0.y + bv[1];
        x[2] = v1.x + bv[2]; x[3] = v1.y + bv[3];
        float sm = x[0] + x[1] + x[2] + x[3];
        float sq = x[0]*x[0] + x[1]*x[1] + x[2]*x[2] + x[3]*x[3];
        sm = wsum(sm); sq = wsum(sq);
        float mean = sm * (1.f / HD);
        float var  = sq * (1.f / HD) - mean * mean;
        float rs = rsqrtf(var + LN_EPS);
        if (tn < 25) {
            float4 o;
            o.x = geluf((x[0] - mean) * rs);
            o.y = geluf((x[1] - mean) * rs);
            o.z = geluf((x[2] - mean) * rs);
            o.w = geluf((x[3] - mean) * rs);
            *(float4*)&g_h1[(size_t)m * HD + tn * 4] = o;
        }
    }
}

// ---------------- k2: everything small, one warp per row ----------------------
#define K2_SMEM_FLOATS (22380 + 8*264)
__global__ void __launch_bounds__(256) k2_mid(
    const float* __restrict__ eps_z, const float* __restrict__ eps_d,
    const float* __restrict__ w2, const float* __restrict__ b2,
    const float* __restrict__ wmu, const float* __restrict__ bmu,
    const float* __restrict__ wlv, const float* __restrict__ blv,
    const float* __restrict__ edw1, const float* __restrict__ edb1,
    const float* __restrict__ edwmu, const float* __restrict__ edbmu,
    const float* __restrict__ edwlv, const float* __restrict__ edblv,
    const float* __restrict__ dzw1, const float* __restrict__ dzb1,
    float* __restrict__ o_z, float* __restrict__ o_dz,
    float* __restrict__ o_muz, float* __restrict__ o_scz,
    float* __restrict__ o_mud, float* __restrict__ o_scd)
{
    extern __shared__ float sm2[];
    float* sw2    = sm2;              // 10000
    float* swmu   = sw2 + 10000;      // 2000
    float* swlv   = swmu + 2000;      // 2000
    float* sb2    = swlv + 2000;      // 100
    float* sbmu   = sb2 + 100;        // 20
    float* sblv   = sbmu + 20;        // 20
    float* sedw1  = sblv + 20;        // 2000
    float* sedb1  = sedw1 + 2000;     // 100
    float* sedwmu = sedb1 + 100;      // 2000
    float* sedbmu = sedwmu + 2000;    // 20
    float* sedwlv = sedbmu + 20;      // 2000
    float* sedblv = sedwlv + 2000;    // 20
    float* sdzw1  = sedblv + 20;      // 2000
    float* sdzb1  = sdzw1 + 2000;     // 100
    float* wbuf   = sdzb1 + 100;      // 8 warps * 264

    {
        int t = threadIdx.x, nt = blockDim.x;
        for (int i = t; i < 10000; i += nt) sw2[i] = w2[i];
        for (int i = t; i < 2000; i += nt) { swmu[i] = wmu[i]; swlv[i] = wlv[i]; }
        for (int i = t; i < 2000; i += nt) { sedw1[i] = edw1[i]; sdzw1[i] = dzw1[i]; }
        for (int i = t; i < 2000; i += nt) { sedwmu[i] = edwmu[i]; sedwlv[i] = edwlv[i]; }
        for (int i = t; i < 100; i += nt) { sb2[i] = b2[i]; sedb1[i] = edb1[i]; sdzb1[i] = dzb1[i]; }
        if (t < 20) { sbmu[t] = bmu[t]; sblv[t] = blv[t]; sedbmu[t] = edbmu[t]; sedblv[t] = edblv[t]; }
    }
    __syncthreads();

    int wid = threadIdx.x >> 5, lane = threadIdx.x & 31;
    float* B0 = wbuf + wid * 264;
    float* B1 = B0 + 132;
    int nwarps = gridDim.x * 8;

    for (int r = blockIdx.x * 8 + wid; r < BB; r += nwarps) {
        for (int i = lane; i < HD; i += 32) B0[i] = g_h1[(size_t)r * HD + i];
        __syncwarp();

        // ---- h2 = gelu(LN(h1@w2 + b2)): lane<25 owns 4 contiguous cols ----
        float x[4] = {0.f, 0.f, 0.f, 0.f};
        if (lane < 25) {
            float4 bb4 = *(const float4*)&sb2[lane * 4];
            x[0] = bb4.x; x[1] = bb4.y; x[2] = bb4.z; x[3] = bb4.w;
            for (int k = 0; k < HD; k++) {
                float b = B0[k];
                float4 w = *(const float4*)&sw2[k * HD + lane * 4];
                x[0] = fmaf(b, w.x, x[0]);
                x[1] = fmaf(b, w.y, x[1]);
                x[2] = fmaf(b, w.z, x[2]);
                x[3] = fmaf(b, w.w, x[3]);
            }
        }
        float smv = x[0] + x[1] + x[2] + x[3];
        float sqv = x[0]*x[0] + x[1]*x[1] + x[2]*x[2] + x[3]*x[3];
        smv = wsum(smv); sqv = wsum(sqv);
        float mean = smv * (1.f / HD);
        float rs = rsqrtf(sqv * (1.f / HD) - mean * mean + LN_EPS);
        if (lane < 25) {
            float4 o;
            o.x = geluf((x[0] - mean) * rs);
            o.y = geluf((x[1] - mean) * rs);
            o.z = geluf((x[2] - mean) * rs);
            o.w = geluf((x[3] - mean) * rs);
            *(float4*)&B1[lane * 4] = o;
        }
        __syncwarp();

        // ---- z heads ----
        if (lane < ZD) {
            float mu = sbmu[lane], lv = sblv[lane];
            for (int k = 0; k < HD; k++) {
                float h = B1[k];
                mu += h * swmu[k * ZD + lane];
                lv += h * swlv[k * ZD + lane];
            }
            float sc = softplusf(lv);
            float z = mu + sc * eps_z[(size_t)r * ZD + lane];
            o_z  [(size_t)r * ZD + lane] = z;
            o_muz[(size_t)r * ZD + lane] = mu;
            o_scz[(size_t)r * ZD + lane] = sc;
            B0[lane] = z;
        }
        __syncwarp();

        // ---- hd = gelu(LN(z@ed_w1 + b)) : lane<25 owns 4 cols ----
        x[0] = x[1] = x[2] = x[3] = 0.f;
        if (lane < 25) {
            float4 bb4 = *(const float4*)&sedb1[lane * 4];
            x[0] = bb4.x; x[1] = bb4.y; x[2] = bb4.z; x[3] = bb4.w;
            for (int k = 0; k < ZD; k++) {
                float b = B0[k];
                float4 w = *(const float4*)&sedw1[k * HD + lane * 4];
                x[0] = fmaf(b, w.x, x[0]);
                x[1] = fmaf(b, w.y, x[1]);
                x[2] = fmaf(b, w.z, x[2]);
                x[3] = fmaf(b, w.w, x[3]);
            }
        }
        smv = x[0] + x[1] + x[2] + x[3];
        sqv = x[0]*x[0] + x[1]*x[1] + x[2]*x[2] + x[3]*x[3];
        smv = wsum(smv); sqv = wsum(sqv);
        mean = smv * (1.f / HD);
        rs = rsqrtf(sqv * (1.f / HD) - mean * mean + LN_EPS);
        if (lane < 25) {
            float4 o;
            o.x = geluf((x[0] - mean) * rs);
            o.y = geluf((x[1] - mean) * rs);
            o.z = geluf((x[2] - mean) * rs);
            o.w = geluf((x[3] - mean) * rs);
            *(float4*)&B1[lane * 4] = o;
        }
        __syncwarp();

        // ---- d heads ----
        if (lane < ZD) {
            float mu = sedbmu[lane], lv = sedblv[lane];
            for (int k = 0; k < HD; k++) {
                float h = B1[k];
                mu += h * sedwmu[k * ZD + lane];
                lv += h * sedwlv[k * ZD + lane];
            }
            float sc = softplusf(lv);
            float dz = mu + sc * eps_d[(size_t)r * ZD + lane];
            o_dz [(size_t)r * ZD + lane] = dz;
            o_mud[(size_t)r * ZD + lane] = mu;
            o_scd[(size_t)r * ZD + lane] = sc;
            B0[32 + lane] = dz;
        }
        __syncwarp();

        // ---- decoder layer 1 with JVP: lane<25 owns 4 cols ----
        float a[4] = {0.f,0.f,0.f,0.f}, t[4] = {0.f,0.f,0.f,0.f};
        if (lane < 25) {
            float4 bb4 = *(const float4*)&sdzb1[lane * 4];
            a[0] = bb4.x; a[1] = bb4.y; a[2] = bb4.z; a[3] = bb4.w;
            for (int k = 0; k < ZD; k++) {
                float zz = B0[k];
                float dd = B0[32 + k];
                float4 w = *(const float4*)&sdzw1[k * HD + lane * 4];
                a[0] = fmaf(zz, w.x, a[0]); t[0] = fmaf(dd, w.x, t[0]);
                a[1] = fmaf(zz, w.y, a[1]); t[1] = fmaf(dd, w.y, t[1]);
                a[2] = fmaf(zz, w.z, a[2]); t[2] = fmaf(dd, w.z, t[2]);
                a[3] = fmaf(zz, w.w, a[3]); t[3] = fmaf(dd, w.w, t[3]);
            }
        }
        float sa = a[0]+a[1]+a[2]+a[3];
        float saa = a[0]*a[0]+a[1]*a[1]+a[2]*a[2]+a[3]*a[3];
        float st = t[0]+t[1]+t[2]+t[3];
        float sat = a[0]*t[0]+a[1]*t[1]+a[2]*t[2]+a[3]*t[3];
        sa = wsum(sa); saa = wsum(saa); st = wsum(st); sat = wsum(sat);
        float m  = sa * (1.f / HD);
        float v  = saa * (1.f / HD) - m * m;
        float r2 = rsqrtf(v + LN_EPS);
        float dm = st * (1.f / HD);
        float dv = 2.f * (sat * (1.f / HD) - m * dm);
        if (lane < 25) {
            float4 oh, ot;
            float y, dy, Phi, phi;
#pragma unroll
            for (int j = 0; j < 4; j++) {
                y  = (a[j] - m) * r2;
                dy = r2 * (t[j] - dm) - 0.5f * y * r2 * r2 * dv;
                Phi = 0.5f * (1.f + erff(y * 0.70710678118654752f));
                phi = 0.3989422804014327f * expf(-0.5f * y * y);
                ((float*)&oh)[j] = y * Phi;
                ((float*)&ot)[j] = (Phi + y * phi) * dy;
            }
            *(float4*)&g_h1g[(size_t)r * HD + lane * 4] = oh;
            *(float4*)&g_th [(size_t)r * HD + lane * 4] = ot;
        }
        __syncwarp();
    }
}

// ---------------- k3: big decoder GEMM (primal + tangent), packed {h,t} -------
// Tile M=64, N=64. HT interleaved [k][{h,t} per row] (broadcast reads);
// W dup-stored [k][{w,w} per col] (contiguous per-lane reads).
// acc[i][c] = {aH(i,c), aT(i,c)}: 16 FFMA2 + 6 LSU cyc per warp-k. No packs.
#define K3_SMEM_FLOATS (100*136 + 100*136)
__global__ void __launch_bounds__(256, 2) k3_dec(
    const float* __restrict__ w2, const float* __restrict__ b2)
{
    extern __shared__ float sm3[];
    float (*Wd)[136] = (float (*)[136])sm3;                 // [k][2n dup]
    float (*HT)[136] = (float (*)[136])(sm3 + 100 * 136);   // [k][2m interleave]

    int tid = threadIdx.x;
    int tn = tid & 15, tm = tid >> 4;
    int n0 = blockIdx.x * 64;
    int m0 = blockIdx.y * 64;

    // stage W dup: 100 k x 64 cols
    for (int lin = tid; lin < 1600; lin += 256) {
        int k = lin >> 4, c4 = (lin & 15) * 4;
        float4 v = make_float4(0.f, 0.f, 0.f, 0.f);
        if (n0 + c4 < XD) v = *(const float4*)&w2[(size_t)k * XD + n0 + c4];
        *(float4*)&Wd[k][c4 * 2]     = make_float4(v.x, v.x, v.y, v.y);
        *(float4*)&Wd[k][c4 * 2 + 4] = make_float4(v.z, v.z, v.w, v.w);
    }
    // stage HT interleaved: 64 rows x 100 k
    for (int lin = tid; lin < 1600; lin += 256) {
        int m = lin / 25, k4 = (lin - m * 25) * 4;
        float4 h = *(const float4*)&g_h1g[(size_t)(m0 + m) * HD + k4];
        float4 t = *(const float4*)&g_th [(size_t)(m0 + m) * HD + k4];
        float hv[4] = {h.x, h.y, h.z, h.w};
        float tv[4] = {t.x, t.y, t.z, t.w};
#pragma unroll
        for (int e = 0; e < 4; e++) {
            float2 d; d.x = hv[e]; d.y = tv[e];
            *(float2*)&HT[k4 + e][2 * m] = d;
        }
    }
    __syncthreads();

    unsigned long long acc[4][4];
#pragma unroll
    for (int i = 0; i < 4; i++)
#pragma unroll
        for (int c = 0; c < 4; c++) acc[i][c] = 0ull;

#pragma unroll 4
    for (int k = 0; k < HD; k++) {
        ulonglong2 wp0 = *(const ulonglong2*)&Wd[k][tn * 8];       // {w0,w0},{w1,w1}
        ulonglong2 wp1 = *(const ulonglong2*)&Wd[k][tn * 8 + 4];   // {w2,w2},{w3,w3}
        ulonglong2 ht0 = *(const ulonglong2*)&HT[k][tm * 8];       // {h0,t0},{h1,t1}
        ulonglong2 ht1 = *(const ulonglong2*)&HT[k][tm * 8 + 4];   // {h2,t2},{h3,t3}
        FMA2(acc[0][0], ht0.x, wp0.x); FMA2(acc[0][1], ht0.x, wp0.y);
        FMA2(acc[0][2], ht0.x, wp1.x); FMA2(acc[0][3], ht0.x, wp1.y);
        FMA2(acc[1][0], ht0.y, wp0.x); FMA2(acc[1][1], ht0.y, wp0.y);
        FMA2(acc[1][2], ht0.y, wp1.x); FMA2(acc[1][3], ht0.y, wp1.y);
        FMA2(acc[2][0], ht1.x, wp0.x); FMA2(acc[2][1], ht1.x, wp0.y);
        FMA2(acc[2][2], ht1.x, wp1.x); FMA2(acc[2][3], ht1.x, wp1.y);
        FMA2(acc[3][0], ht1.y, wp0.x); FMA2(acc[3][1], ht1.y, wp0.y);
        FMA2(acc[3][2], ht1.y, wp1.x); FMA2(acc[3][3], ht1.y, wp1.y);
    }

    int nc = n0 + tn * 4;
    if (nc >= XD) return;
    float4 bb = *(const float4*)&b2[nc];
    float bj[4] = {bb.x, bb.y, bb.z, bb.w};

#pragma unroll
    for (int i = 0; i < 4; i++) {
        int row = m0 + tm * 4 + i;
        float4 lo, to;
#pragma unroll
        for (int c = 0; c < 4; c++) {
            float2 v = unpk(acc[i][c]);    // {aH, aT}
            float av = v.x + bj[c];
            ((float*)&lo)[c] = softplusf(av);
            ((float*)&to)[c] = sigmoidf(av) * v.y;
        }
        *(float4*)&g_ld [(size_t)row * XD + nc] = lo;
        *(float4*)&g_tld[(size_t)row * XD + nc] = to;
    }
}

// ---------------- k4: per-row sums + finalize ---------------------------------
__global__ void __launch_bounds__(256) k4_fin(
    float* __restrict__ o_shat, float* __restrict__ o_diff, float* __restrict__ o_pu)
{
    __shared__ float red[16];
    int r = blockIdx.x;
    int tid = threadIdx.x;

    float4 l[2], tl[2];
    float sl = 0.f, st = 0.f;
#pragma unroll
    for (int j = 0; j < 2; j++) {
        int c = (tid + j * 256) * 4;
        if (c < XD) {
            l [j] = *(const float4*)&g_ld [(size_t)r * XD + c];
            tl[j] = *(const float4*)&g_tld[(size_t)r * XD + c];
            sl += l [j].x + l [j].y + l [j].z + l [j].w;
            st += tl[j].x + tl[j].y + tl[j].z + tl[j].w;
        }
    }
    sl = wsum(sl); st = wsum(st);
    int wid = tid >> 5, lane = tid & 31;
    if (lane == 0) { red[wid] = sl; red[8 + wid] = st; }
    __syncthreads();
    sl = red[0]+red[1]+red[2]+red[3]+red[4]+red[5]+red[6]+red[7];
    st = red[8]+red[9]+red[10]+red[11]+red[12]+red[13]+red[14]+red[15];

    float m  = sl * (1.f / XD);
    float mt = st * (1.f / XD);
    float rm = 1.f / m;
    float cm = mt * rm * rm;

#pragma unroll
    for (int j = 0; j < 2; j++) {
        int c = (tid + j * 256) * 4;
        if (c < XD) {
            float4 be = *(const float4*)&g_beta[c];
            float4 ga = *(const float4*)&g_gamma[c];
            float4 sh, df, pu;
            sh.x = l[j].x * rm; df.x = 0.01f * (tl[j].x * rm - l[j].x * cm);
            sh.y = l[j].y * rm; df.y = 0.01f * (tl[j].y * rm - l[j].y * cm);
            sh.z = l[j].z * rm; df.z = 0.01f * (tl[j].z * rm - l[j].z * cm);
            sh.w = l[j].w * rm; df.w = 0.01f * (tl[j].w * rm - l[j].w * cm);
            pu.x = fmaxf((df.x + sh.x * ga.x) / be.x, 0.f);
            pu.y = fmaxf((df.y + sh.y * ga.y) / be.y, 0.f);
            pu.z = fmaxf((df.z + sh.z * ga.z) / be.z, 0.f);
            pu.w = fmaxf((df.w + sh.w * ga.w) / be.w, 0.f);
            *(float4*)&o_shat[(size_t)r * XD + c] = sh;
            *(float4*)&o_diff[(size_t)r * XD + c] = df;
            *(float4*)&o_pu  [(size_t)r * XD + c] = pu;
        }
    }
}

// ---------------- launcher ----------------------------------------------------
extern "C" void kernel_launch(void* const* d_in, const int* in_sizes, int n_in,
                              void* d_out, int out_size)
{
    const float* s      = (const float*)d_in[0];
    const float* u      = (const float*)d_in[1];
    const float* eps_z  = (const float*)d_in[2];
    const float* eps_d  = (const float*)d_in[3];
    const float* ez_w1  = (const float*)d_in[4];
    const float* ez_b1  = (const float*)d_in[5];
    const float* ez_w2  = (const float*)d_in[6];
    const float* ez_b2  = (const float*)d_in[7];
    const float* ez_wmu = (const float*)d_in[8];
    const float* ez_bmu = (const float*)d_in[9];
    const float* ez_wlv = (const float*)d_in[10];
    const float* ez_blv = (const float*)d_in[11];
    const float* ed_w1  = (const float*)d_in[12];
    const float* ed_b1  = (const float*)d_in[13];
    const float* ed_wmu = (const float*)d_in[14];
    const float* ed_bmu = (const float*)d_in[15];
    const float* ed_wlv = (const float*)d_in[16];
    const float* ed_blv = (const float*)d_in[17];
    const float* dz_w1  = (const float*)d_in[18];
    const float* dz_b1  = (const float*)d_in[19];
    const float* dz_w2  = (const float*)d_in[20];
    const float* dz_b2  = (const float*)d_in[21];
    const float* logb   = (const float*)d_in[22];
    const float* logg   = (const float*)d_in[23];

    float* out = (float*)d_out;
    float* o_z    = out;
    float* o_dz   = o_z    + (size_t)BB * ZD;
    float* o_muz  = o_dz   + (size_t)BB * ZD;
    float* o_scz  = o_muz  + (size_t)BB * ZD;
    float* o_mud  = o_scz  + (size_t)BB * ZD;
    float* o_scd  = o_mud  + (size_t)BB * ZD;
    float* o_shat = o_scd  + (size_t)BB * ZD;
    float* o_diff = o_shat + (size_t)BB * XD;
    float* o_pu   = o_diff + (size_t)BB * XD;

    const int smem1 = K1_SMEM_FLOATS * 4;
    const int smem2 = K2_SMEM_FLOATS * 4;
    const int smem3 = K3_SMEM_FLOATS * 4;
    cudaFuncSetAttribute(k1_enc1, cudaFuncAttributeMaxDynamicSharedMemorySize, smem1);
    cudaFuncSetAttribute(k2_mid, cudaFuncAttributeMaxDynamicSharedMemorySize, smem2);
    cudaFuncSetAttribute(k3_dec, cudaFuncAttributeMaxDynamicSharedMemorySize, smem3);

    k0_rates<<<8, 256>>>(logb, logg);
    k1_enc1<<<BB / 64, 256, smem1>>>(s, u, ez_w1, ez_b1);
    k2_mid<<<512, 256, smem2>>>(eps_z, eps_d,
                                ez_w2, ez_b2, ez_wmu, ez_bmu, ez_wlv, ez_blv,
                                ed_w1, ed_b1, ed_wmu, ed_bmu, ed_wlv, ed_blv,
                                dz_w1, dz_b1,
                                o_z, o_dz, o_muz, o_scz, o_mud, o_scd);
    dim3 g3(32, 256);
    k3_dec<<<g3, 256, smem3>>>(dz_w2, dz_b2);
    k4_fin<<<BB, 256>>>(o_shat, o_diff, o_pu);
}

// round 5
// speedup vs baseline: 2.3351x; 1.2777x over previous
#include <cuda_runtime.h>
#include <math.h>

#define BB 16384
#define XD 2000
#define HD 100
#define ZD 20
#define KTOT (2*XD)      // 4000
#define LN_EPS 1e-5f

// ---------------- scratch (static device globals; no allocations) -------------
__device__ float g_h1 [(size_t)BB*HD];
__device__ float g_h1g[(size_t)BB*HD];
__device__ float g_th [(size_t)BB*HD];
__device__ float g_ld [(size_t)BB*XD];
__device__ float g_tld[(size_t)BB*XD];
__device__ float g_beta [XD];
__device__ float g_gamma[XD];

// ---------------- helpers -----------------------------------------------------
__device__ __forceinline__ float softplusf(float x) {
    return fmaxf(x, 0.f) + log1pf(expf(-fabsf(x)));
}
__device__ __forceinline__ float sigmoidf(float x) {
    return 1.f / (1.f + expf(-x));
}
__device__ __forceinline__ float geluf(float x) {
    return 0.5f * x * (1.f + erff(x * 0.70710678118654752f));
}
__device__ __forceinline__ float wsum(float v) {
#pragma unroll
    for (int o = 16; o; o >>= 1) v += __shfl_xor_sync(0xffffffffu, v, o);
    return v;
}

// ---------------- k0: beta/gamma precompute ----------------------------------
__global__ void k0_rates(const float* __restrict__ lb, const float* __restrict__ lg) {
    int i = blockIdx.x * blockDim.x + threadIdx.x;
    if (i < XD) {
        g_beta[i]  = softplusf(lb[i]);   // * DT (=1)
        g_gamma[i] = softplusf(lg[i]);
    }
}

// ---------------- k1: h1 = gelu(LN([s,u]@W1 + b1)) ----------------------------
// Tile M=64 (grid 256), N=128 (100 valid). KC=32 double-buffered, one sync/stage.
// A transposed [k][m] (broadcast LDS.128 reads), W plain [k][n] (contiguous).
// Per k: 32 FFMA + 3 LDS.128 = 35 issue slots (91% fma ceiling).
#define KC 32
#define K1_SMEM_FLOATS (2*KC*68 + 2*KC*132)
__global__ void __launch_bounds__(256, 2) k1_enc1(
    const float* __restrict__ s, const float* __restrict__ u,
    const float* __restrict__ w1, const float* __restrict__ b1)
{
    extern __shared__ float sm1[];
    float (*Ast)[KC][68]  = (float (*)[KC][68])sm1;               // [buf][k][m]
    float (*Ws )[KC][132] = (float (*)[KC][132])(sm1 + 2*KC*68);  // [buf][k][n]

    int tid = threadIdx.x;
    int tn = tid & 31, tm = tid >> 5;
    int m0 = blockIdx.x * 64;

    // zero W pad cols [100,128) in both buffers (lanes tn>=25 must accumulate 0)
    for (int i = tid; i < 2 * KC * 28; i += 256) {
        int b = i / (KC * 28);
        int r = (i / 28) % KC;
        int c = 100 + (i % 28);
        Ws[b][r][c] = 0.f;
    }

    // A staging: 64 rows x KC k = 512 float4 -> 2 per thread
    // idx: q = idx&7 selects k-quad, m = idx>>3
    int aM[2], aK4[2];
#pragma unroll
    for (int t = 0; t < 2; t++) {
        int idx = tid + t * 256;
        aM [t] = idx >> 3;
        aK4[t] = (idx & 7) * 4;
    }
    // W staging: KC x 100 = 800 float4 -> 3/thread + 32 extra
    int wRow[4], wC4[4];
#pragma unroll
    for (int t = 0; t < 4; t++) {
        int lin = tid + t * 256;
        wRow[t] = lin / 25;
        wC4 [t] = (lin - wRow[t] * 25) * 4;
    }

    float4 aReg[2];
    float4 wReg[4];

    // prefetch stage 0
#pragma unroll
    for (int t = 0; t < 2; t++) {
        int gk = aK4[t];
        const float* base = (gk < XD) ? &s[(size_t)(m0 + aM[t]) * XD + gk]
                                      : &u[(size_t)(m0 + aM[t]) * XD + gk - XD];
        aReg[t] = *(const float4*)base;
    }
#pragma unroll
    for (int t = 0; t < 3; t++)
        wReg[t] = *(const float4*)&w1[(size_t)wRow[t] * HD + wC4[t]];
    if (tid < 32)
        wReg[3] = *(const float4*)&w1[(size_t)wRow[3] * HD + wC4[3]];

    float acc[8][4];
#pragma unroll
    for (int i = 0; i < 8; i++)
#pragma unroll
        for (int j = 0; j < 4; j++) acc[i][j] = 0.f;

    float bv[4] = {0.f, 0.f, 0.f, 0.f};
    if (tn < 25) {
        float4 b = *(const float4*)&b1[tn * 4];
        bv[0] = b.x; bv[1] = b.y; bv[2] = b.z; bv[3] = b.w;
    }

    int buf = 0;
    for (int kb = 0; kb < KTOT; kb += KC) {
        // STS current stage
#pragma unroll
        for (int t = 0; t < 2; t++) {
            Ast[buf][aK4[t] + 0][aM[t]] = aReg[t].x;
            Ast[buf][aK4[t] + 1][aM[t]] = aReg[t].y;
            Ast[buf][aK4[t] + 2][aM[t]] = aReg[t].z;
            Ast[buf][aK4[t] + 3][aM[t]] = aReg[t].w;
        }
#pragma unroll
        for (int t = 0; t < 3; t++)
            *(float4*)&Ws[buf][wRow[t]][wC4[t]] = wReg[t];
        if (tid < 32)
            *(float4*)&Ws[buf][wRow[3]][wC4[3]] = wReg[3];
        __syncthreads();

        // prefetch next stage
        int kn = kb + KC;
        if (kn < KTOT) {
#pragma unroll
            for (int t = 0; t < 2; t++) {
                int gk = kn + aK4[t];
                const float* base = (gk < XD) ? &s[(size_t)(m0 + aM[t]) * XD + gk]
                                              : &u[(size_t)(m0 + aM[t]) * XD + gk - XD];
                aReg[t] = *(const float4*)base;
            }
#pragma unroll
            for (int t = 0; t < 3; t++)
                wReg[t] = *(const float4*)&w1[(size_t)(kn + wRow[t]) * HD + wC4[t]];
            if (tid < 32)
                wReg[3] = *(const float4*)&w1[(size_t)(kn + wRow[3]) * HD + wC4[3]];
        }

        // compute: per k, 1 contiguous LDS.128 (W) + 2 broadcast LDS.128 (A)
#pragma unroll 8
        for (int k = 0; k < KC; k++) {
            float4 w  = *(const float4*)&Ws [buf][k][tn * 4];
            float4 a0 = *(const float4*)&Ast[buf][k][tm * 8];
            float4 a1 = *(const float4*)&Ast[buf][k][tm * 8 + 4];
            float av[8] = {a0.x, a0.y, a0.z, a0.w, a1.x, a1.y, a1.z, a1.w};
#pragma unroll
            for (int i = 0; i < 8; i++) {
                acc[i][0] = fmaf(av[i], w.x, acc[i][0]);
                acc[i][1] = fmaf(av[i], w.y, acc[i][1]);
                acc[i][2] = fmaf(av[i], w.z, acc[i][2]);
                acc[i][3] = fmaf(av[i], w.w, acc[i][3]);
            }
        }
        buf ^= 1;
    }

    // per-row LN + GELU (8 rows per thread; lanes 25-31 contribute zeros)
#pragma unroll
    for (int i = 0; i < 8; i++) {
        int m = m0 + tm * 8 + i;
        float x[4], sm = 0.f, sq = 0.f;
#pragma unroll
        for (int j = 0; j < 4; j++) {
            x[j] = acc[i][j] + bv[j];
            sm += x[j];
            sq += x[j] * x[j];
        }
        sm = wsum(sm); sq = wsum(sq);
        float mean = sm * (1.f / HD);
        float var  = sq * (1.f / HD) - mean * mean;
        float rs = rsqrtf(var + LN_EPS);
        if (tn < 25) {
            float4 o;
            o.x = geluf((x[0] - mean) * rs);
            o.y = geluf((x[1] - mean) * rs);
            o.z = geluf((x[2] - mean) * rs);
            o.w = geluf((x[3] - mean) * rs);
            *(float4*)&g_h1[(size_t)m * HD + tn * 4] = o;
        }
    }
}

// ---------------- k2: everything small, one warp per row ----------------------
#define K2_SMEM_FLOATS (22380 + 8*264)
__global__ void __launch_bounds__(256) k2_mid(
    const float* __restrict__ eps_z, const float* __restrict__ eps_d,
    const float* __restrict__ w2, const float* __restrict__ b2,
    const float* __restrict__ wmu, const float* __restrict__ bmu,
    const float* __restrict__ wlv, const float* __restrict__ blv,
    const float* __restrict__ edw1, const float* __restrict__ edb1,
    const float* __restrict__ edwmu, const float* __restrict__ edbmu,
    const float* __restrict__ edwlv, const float* __restrict__ edblv,
    const float* __restrict__ dzw1, const float* __restrict__ dzb1,
    float* __restrict__ o_z, float* __restrict__ o_dz,
    float* __restrict__ o_muz, float* __restrict__ o_scz,
    float* __restrict__ o_mud, float* __restrict__ o_scd)
{
    extern __shared__ float sm2[];
    float* sw2    = sm2;              // 10000
    float* swmu   = sw2 + 10000;      // 2000
    float* swlv   = swmu + 2000;      // 2000
    float* sb2    = swlv + 2000;      // 100
    float* sbmu   = sb2 + 100;        // 20
    float* sblv   = sbmu + 20;        // 20
    float* sedw1  = sblv + 20;        // 2000
    float* sedb1  = sedw1 + 2000;     // 100
    float* sedwmu = sedb1 + 100;      // 2000
    float* sedbmu = sedwmu + 2000;    // 20
    float* sedwlv = sedbmu + 20;      // 2000
    float* sedblv = sedwlv + 2000;    // 20
    float* sdzw1  = sedblv + 20;      // 2000
    float* sdzb1  = sdzw1 + 2000;     // 100
    float* wbuf   = sdzb1 + 100;      // 8 warps * 264

    {
        int t = threadIdx.x, nt = blockDim.x;
        for (int i = t; i < 10000; i += nt) sw2[i] = w2[i];
        for (int i = t; i < 2000; i += nt) { swmu[i] = wmu[i]; swlv[i] = wlv[i]; }
        for (int i = t; i < 2000; i += nt) { sedw1[i] = edw1[i]; sdzw1[i] = dzw1[i]; }
        for (int i = t; i < 2000; i += nt) { sedwmu[i] = edwmu[i]; sedwlv[i] = edwlv[i]; }
        for (int i = t; i < 100; i += nt) { sb2[i] = b2[i]; sedb1[i] = edb1[i]; sdzb1[i] = dzb1[i]; }
        if (t < 20) { sbmu[t] = bmu[t]; sblv[t] = blv[t]; sedbmu[t] = edbmu[t]; sedblv[t] = edblv[t]; }
    }
    __syncthreads();

    int wid = threadIdx.x >> 5, lane = threadIdx.x & 31;
    float* B0 = wbuf + wid * 264;
    float* B1 = B0 + 132;
    int nwarps = gridDim.x * 8;

    for (int r = blockIdx.x * 8 + wid; r < BB; r += nwarps) {
        for (int i = lane; i < HD; i += 32) B0[i] = g_h1[(size_t)r * HD + i];
        __syncwarp();

        // ---- h2 = gelu(LN(h1@w2 + b2)): lane<25 owns 4 contiguous cols ----
        float x[4] = {0.f, 0.f, 0.f, 0.f};
        if (lane < 25) {
            float4 bb4 = *(const float4*)&sb2[lane * 4];
            x[0] = bb4.x; x[1] = bb4.y; x[2] = bb4.z; x[3] = bb4.w;
            for (int k = 0; k < HD; k++) {
                float b = B0[k];
                float4 w = *(const float4*)&sw2[k * HD + lane * 4];
                x[0] = fmaf(b, w.x, x[0]);
                x[1] = fmaf(b, w.y, x[1]);
                x[2] = fmaf(b, w.z, x[2]);
                x[3] = fmaf(b, w.w, x[3]);
            }
        }
        float smv = x[0] + x[1] + x[2] + x[3];
        float sqv = x[0]*x[0] + x[1]*x[1] + x[2]*x[2] + x[3]*x[3];
        smv = wsum(smv); sqv = wsum(sqv);
        float mean = smv * (1.f / HD);
        float rs = rsqrtf(sqv * (1.f / HD) - mean * mean + LN_EPS);
        if (lane < 25) {
            float4 o;
            o.x = geluf((x[0] - mean) * rs);
            o.y = geluf((x[1] - mean) * rs);
            o.z = geluf((x[2] - mean) * rs);
            o.w = geluf((x[3] - mean) * rs);
            *(float4*)&B1[lane * 4] = o;
        }
        __syncwarp();

        // ---- z heads ----
        if (lane < ZD) {
            float mu = sbmu[lane], lv = sblv[lane];
            for (int k = 0; k < HD; k++) {
                float h = B1[k];
                mu += h * swmu[k * ZD + lane];
                lv += h * swlv[k * ZD + lane];
            }
            float sc = softplusf(lv);
            float z = mu + sc * eps_z[(size_t)r * ZD + lane];
            o_z  [(size_t)r * ZD + lane] = z;
            o_muz[(size_t)r * ZD + lane] = mu;
            o_scz[(size_t)r * ZD + lane] = sc;
            B0[lane] = z;
        }
        __syncwarp();

        // ---- hd = gelu(LN(z@ed_w1 + b)) : lane<25 owns 4 cols ----
        x[0] = x[1] = x[2] = x[3] = 0.f;
        if (lane < 25) {
            float4 bb4 = *(const float4*)&sedb1[lane * 4];
            x[0] = bb4.x; x[1] = bb4.y; x[2] = bb4.z; x[3] = bb4.w;
            for (int k = 0; k < ZD; k++) {
                float b = B0[k];
                float4 w = *(const float4*)&sedw1[k * HD + lane * 4];
                x[0] = fmaf(b, w.x, x[0]);
                x[1] = fmaf(b, w.y, x[1]);
                x[2] = fmaf(b, w.z, x[2]);
                x[3] = fmaf(b, w.w, x[3]);
            }
        }
        smv = x[0] + x[1] + x[2] + x[3];
        sqv = x[0]*x[0] + x[1]*x[1] + x[2]*x[2] + x[3]*x[3];
        smv = wsum(smv); sqv = wsum(sqv);
        mean = smv * (1.f / HD);
        rs = rsqrtf(sqv * (1.f / HD) - mean * mean + LN_EPS);
        if (lane < 25) {
            float4 o;
            o.x = geluf((x[0] - mean) * rs);
            o.y = geluf((x[1] - mean) * rs);
            o.z = geluf((x[2] - mean) * rs);
            o.w = geluf((x[3] - mean) * rs);
            *(float4*)&B1[lane * 4] = o;
        }
        __syncwarp();

        // ---- d heads ----
        if (lane < ZD) {
            float mu = sedbmu[lane], lv = sedblv[lane];
            for (int k = 0; k < HD; k++) {
                float h = B1[k];
                mu += h * sedwmu[k * ZD + lane];
                lv += h * sedwlv[k * ZD + lane];
            }
            float sc = softplusf(lv);
            float dz = mu + sc * eps_d[(size_t)r * ZD + lane];
            o_dz [(size_t)r * ZD + lane] = dz;
            o_mud[(size_t)r * ZD + lane] = mu;
            o_scd[(size_t)r * ZD + lane] = sc;
            B0[32 + lane] = dz;
        }
        __syncwarp();

        // ---- decoder layer 1 with JVP: lane<25 owns 4 cols ----
        float a[4] = {0.f,0.f,0.f,0.f}, t[4] = {0.f,0.f,0.f,0.f};
        if (lane < 25) {
            float4 bb4 = *(const float4*)&sdzb1[lane * 4];
            a[0] = bb4.x; a[1] = bb4.y; a[2] = bb4.z; a[3] = bb4.w;
            for (int k = 0; k < ZD; k++) {
                float zz = B0[k];
                float dd = B0[32 + k];
                float4 w = *(const float4*)&sdzw1[k * HD + lane * 4];
                a[0] = fmaf(zz, w.x, a[0]); t[0] = fmaf(dd, w.x, t[0]);
                a[1] = fmaf(zz, w.y, a[1]); t[1] = fmaf(dd, w.y, t[1]);
                a[2] = fmaf(zz, w.z, a[2]); t[2] = fmaf(dd, w.z, t[2]);
                a[3] = fmaf(zz, w.w, a[3]); t[3] = fmaf(dd, w.w, t[3]);
            }
        }
        float sa = a[0]+a[1]+a[2]+a[3];
        float saa = a[0]*a[0]+a[1]*a[1]+a[2]*a[2]+a[3]*a[3];
        float st = t[0]+t[1]+t[2]+t[3];
        float sat = a[0]*t[0]+a[1]*t[1]+a[2]*t[2]+a[3]*t[3];
        sa = wsum(sa); saa = wsum(saa); st = wsum(st); sat = wsum(sat);
        float m  = sa * (1.f / HD);
        float v  = saa * (1.f / HD) - m * m;
        float r2 = rsqrtf(v + LN_EPS);
        float dm = st * (1.f / HD);
        float dv = 2.f * (sat * (1.f / HD) - m * dm);
        if (lane < 25) {
            float4 oh, ot;
            float y, dy, Phi, phi;
#pragma unroll
            for (int j = 0; j < 4; j++) {
                y  = (a[j] - m) * r2;
                dy = r2 * (t[j] - dm) - 0.5f * y * r2 * r2 * dv;
                Phi = 0.5f * (1.f + erff(y * 0.70710678118654752f));
                phi = 0.3989422804014327f * expf(-0.5f * y * y);
                ((float*)&oh)[j] = y * Phi;
                ((float*)&ot)[j] = (Phi + y * phi) * dy;
            }
            *(float4*)&g_h1g[(size_t)r * HD + lane * 4] = oh;
            *(float4*)&g_th [(size_t)r * HD + lane * 4] = ot;
        }
        __syncwarp();
    }
}

// ---------------- k3: big decoder GEMM (primal + tangent), scalar FFMA --------
// Tile M=64, N=64. Ws plain [k][n] (contiguous reads), Hs/Ts transposed [k][m]
// (broadcast LDS.128: 4 rows per load). Per k: 32 FFMA + 3 LDS = 35 slots.
#define K3_SMEM_FLOATS (3 * 100 * 68)
__global__ void __launch_bounds__(256, 2) k3_dec(
    const float* __restrict__ w2, const float* __restrict__ b2)
{
    extern __shared__ float sm3[];
    float (*Ws)[68] = (float (*)[68])sm3;                   // [k][n]
    float (*Hs)[68] = (float (*)[68])(sm3 + 100 * 68);      // [k][m]
    float (*Ts)[68] = (float (*)[68])(sm3 + 2 * 100 * 68);  // [k][m]

    int tid = threadIdx.x;
    int tn = tid & 15, tm = tid >> 4;
    int n0 = blockIdx.x * 64;
    int m0 = blockIdx.y * 64;

    // stage W: 100 k x 64 cols (zero-pad cols beyond XD)
    for (int lin = tid; lin < 1600; lin += 256) {
        int k = lin >> 4, c4 = (lin & 15) * 4;
        float4 v = make_float4(0.f, 0.f, 0.f, 0.f);
        if (n0 + c4 < XD) v = *(const float4*)&w2[(size_t)k * XD + n0 + c4];
        *(float4*)&Ws[k][c4] = v;
    }
    // stage H, T transposed: read float4 along k, scatter to [k][m]
    for (int lin = tid; lin < 1600; lin += 256) {
        int m = lin / 25, k4 = (lin - m * 25) * 4;
        float4 h = *(const float4*)&g_h1g[(size_t)(m0 + m) * HD + k4];
        float4 t = *(const float4*)&g_th [(size_t)(m0 + m) * HD + k4];
        Hs[k4 + 0][m] = h.x; Hs[k4 + 1][m] = h.y; Hs[k4 + 2][m] = h.z; Hs[k4 + 3][m] = h.w;
        Ts[k4 + 0][m] = t.x; Ts[k4 + 1][m] = t.y; Ts[k4 + 2][m] = t.z; Ts[k4 + 3][m] = t.w;
    }
    __syncthreads();

    float accl[4][4], acct[4][4];
#pragma unroll
    for (int i = 0; i < 4; i++)
#pragma unroll
        for (int j = 0; j < 4; j++) { accl[i][j] = 0.f; acct[i][j] = 0.f; }

#pragma unroll 10
    for (int k = 0; k < HD; k++) {
        float4 w = *(const float4*)&Ws[k][tn * 4];
        float4 h = *(const float4*)&Hs[k][tm * 4];
        float4 t = *(const float4*)&Ts[k][tm * 4];
        float hv[4] = {h.x, h.y, h.z, h.w};
        float tv[4] = {t.x, t.y, t.z, t.w};
#pragma unroll
        for (int i = 0; i < 4; i++) {
            accl[i][0] = fmaf(hv[i], w.x, accl[i][0]);
            accl[i][1] = fmaf(hv[i], w.y, accl[i][1]);
            accl[i][2] = fmaf(hv[i], w.z, accl[i][2]);
            accl[i][3] = fmaf(hv[i], w.w, accl[i][3]);
            acct[i][0] = fmaf(tv[i], w.x, acct[i][0]);
            acct[i][1] = fmaf(tv[i], w.y, acct[i][1]);
            acct[i][2] = fmaf(tv[i], w.z, acct[i][2]);
            acct[i][3] = fmaf(tv[i], w.w, acct[i][3]);
        }
    }

    int nc = n0 + tn * 4;
    if (nc >= XD) return;
    float4 bb = *(const float4*)&b2[nc];
    float bj[4] = {bb.x, bb.y, bb.z, bb.w};

#pragma unroll
    for (int i = 0; i < 4; i++) {
        int row = m0 + tm * 4 + i;
        float4 lo, to; float av;
        av = accl[i][0] + bj[0]; lo.x = softplusf(av); to.x = sigmoidf(av) * acct[i][0];
        av = accl[i][1] + bj[1]; lo.y = softplusf(av); to.y = sigmoidf(av) * acct[i][1];
        av = accl[i][2] + bj[2]; lo.z = softplusf(av); to.z = sigmoidf(av) * acct[i][2];
        av = accl[i][3] + bj[3]; lo.w = softplusf(av); to.w = sigmoidf(av) * acct[i][3];
        *(float4*)&g_ld [(size_t)row * XD + nc] = lo;
        *(float4*)&g_tld[(size_t)row * XD + nc] = to;
    }
}

// ---------------- k4: per-row sums + finalize ---------------------------------
__global__ void __launch_bounds__(256) k4_fin(
    float* __restrict__ o_shat, float* __restrict__ o_diff, float* __restrict__ o_pu)
{
    __shared__ float red[16];
    int r = blockIdx.x;
    int tid = threadIdx.x;

    float4 l[2], tl[2];
    float sl = 0.f, st = 0.f;
#pragma unroll
    for (int j = 0; j < 2; j++) {
        int c = (tid + j * 256) * 4;
        if (c < XD) {
            l [j] = *(const float4*)&g_ld [(size_t)r * XD + c];
            tl[j] = *(const float4*)&g_tld[(size_t)r * XD + c];
            sl += l [j].x + l [j].y + l [j].z + l [j].w;
            st += tl[j].x + tl[j].y + tl[j].z + tl[j].w;
        }
    }
    sl = wsum(sl); st = wsum(st);
    int wid = tid >> 5, lane = tid & 31;
    if (lane == 0) { red[wid] = sl; red[8 + wid] = st; }
    __syncthreads();
    sl = red[0]+red[1]+red[2]+red[3]+red[4]+red[5]+red[6]+red[7];
    st = red[8]+red[9]+red[10]+red[11]+red[12]+red[13]+red[14]+red[15];

    float m  = sl * (1.f / XD);
    float mt = st * (1.f / XD);
    float rm = 1.f / m;
    float cm = mt * rm * rm;

#pragma unroll
    for (int j = 0; j < 2; j++) {
        int c = (tid + j * 256) * 4;
        if (c < XD) {
            float4 be = *(const float4*)&g_beta[c];
            float4 ga = *(const float4*)&g_gamma[c];
            float4 sh, df, pu;
            sh.x = l[j].x * rm; df.x = 0.01f * (tl[j].x * rm - l[j].x * cm);
            sh.y = l[j].y * rm; df.y = 0.01f * (tl[j].y * rm - l[j].y * cm);
            sh.z = l[j].z * rm; df.z = 0.01f * (tl[j].z * rm - l[j].z * cm);
            sh.w = l[j].w * rm; df.w = 0.01f * (tl[j].w * rm - l[j].w * cm);
            pu.x = fmaxf((df.x + sh.x * ga.x) / be.x, 0.f);
            pu.y = fmaxf((df.y + sh.y * ga.y) / be.y, 0.f);
            pu.z = fmaxf((df.z + sh.z * ga.z) / be.z, 0.f);
            pu.w = fmaxf((df.w + sh.w * ga.w) / be.w, 0.f);
            *(float4*)&o_shat[(size_t)r * XD + c] = sh;
            *(float4*)&o_diff[(size_t)r * XD + c] = df;
            *(float4*)&o_pu  [(size_t)r * XD + c] = pu;
        }
    }
}

// ---------------- launcher ----------------------------------------------------
extern "C" void kernel_launch(void* const* d_in, const int* in_sizes, int n_in,
                              void* d_out, int out_size)
{
    const float* s      = (const float*)d_in[0];
    const float* u      = (const float*)d_in[1];
    const float* eps_z  = (const float*)d_in[2];
    const float* eps_d  = (const float*)d_in[3];
    const float* ez_w1  = (const float*)d_in[4];
    const float* ez_b1  = (const float*)d_in[5];
    const float* ez_w2  = (const float*)d_in[6];
    const float* ez_b2  = (const float*)d_in[7];
    const float* ez_wmu = (const float*)d_in[8];
    const float* ez_bmu = (const float*)d_in[9];
    const float* ez_wlv = (const float*)d_in[10];
    const float* ez_blv = (const float*)d_in[11];
    const float* ed_w1  = (const float*)d_in[12];
    const float* ed_b1  = (const float*)d_in[13];
    const float* ed_wmu = (const float*)d_in[14];
    const float* ed_bmu = (const float*)d_in[15];
    const float* ed_wlv = (const float*)d_in[16];
    const float* ed_blv = (const float*)d_in[17];
    const float* dz_w1  = (const float*)d_in[18];
    const float* dz_b1  = (const float*)d_in[19];
    const float* dz_w2  = (const float*)d_in[20];
    const float* dz_b2  = (const float*)d_in[21];
    const float* logb   = (const float*)d_in[22];
    const float* logg   = (const float*)d_in[23];

    float* out = (float*)d_out;
    float* o_z    = out;
    float* o_dz   = o_z    + (size_t)BB * ZD;
    float* o_muz  = o_dz   + (size_t)BB * ZD;
    float* o_scz  = o_muz  + (size_t)BB * ZD;
    float* o_mud  = o_scz  + (size_t)BB * ZD;
    float* o_scd  = o_mud  + (size_t)BB * ZD;
    float* o_shat = o_scd  + (size_t)BB * ZD;
    float* o_diff = o_shat + (size_t)BB * XD;
    float* o_pu   = o_diff + (size_t)BB * XD;

    const int smem1 = K1_SMEM_FLOATS * 4;
    const int smem2 = K2_SMEM_FLOATS * 4;
    const int smem3 = K3_SMEM_FLOATS * 4;
    cudaFuncSetAttribute(k1_enc1, cudaFuncAttributeMaxDynamicSharedMemorySize, smem1);
    cudaFuncSetAttribute(k2_mid, cudaFuncAttributeMaxDynamicSharedMemorySize, smem2);
    cudaFuncSetAttribute(k3_dec, cudaFuncAttributeMaxDynamicSharedMemorySize, smem3);

    k0_rates<<<8, 256>>>(logb, logg);
    k1_enc1<<<BB / 64, 256, smem1>>>(s, u, ez_w1, ez_b1);
    k2_mid<<<512, 256, smem2>>>(eps_z, eps_d,
                                ez_w2, ez_b2, ez_wmu, ez_bmu, ez_wlv, ez_blv,
                                ed_w1, ed_b1, ed_wmu, ed_bmu, ed_wlv, ed_blv,
                                dz_w1, dz_b1,
                                o_z, o_dz, o_muz, o_scz, o_mud, o_scd);
    dim3 g3(32, 256);
    k3_dec<<<g3, 256, smem3>>>(dz_w2, dz_b2);
    k4_fin<<<BB, 256>>>(o_shat, o_diff, o_pu);
}

// round 7
// speedup vs baseline: 2.9337x; 1.2563x over previous
#include <cuda_runtime.h>
#include <cuda_bf16.h>
#include <math.h>
#include <stdint.h>

#define BB 16384
#define XD 2000
#define HD 100
#define ZD 20
#define KTOT (2*XD)      // 4000
#define LN_EPS 1e-5f

// ---------------- scratch (static device globals; no allocations) -------------
__device__ float g_h1 [(size_t)BB*HD];
__device__ float g_h1g[(size_t)BB*HD];
__device__ float g_th [(size_t)BB*HD];
__device__ float g_ld [(size_t)BB*XD];
__device__ float g_tld[(size_t)BB*XD];
__device__ float g_beta [XD];
__device__ float g_gamma[XD];

// ---------------- helpers -----------------------------------------------------
__device__ __forceinline__ float softplusf(float x) {
    return fmaxf(x, 0.f) + log1pf(expf(-fabsf(x)));
}
__device__ __forceinline__ float sigmoidf(float x) {
    return 1.f / (1.f + expf(-x));
}
__device__ __forceinline__ float geluf(float x) {
    return 0.5f * x * (1.f + erff(x * 0.70710678118654752f));
}
__device__ __forceinline__ float wsum(float v) {
#pragma unroll
    for (int o = 16; o; o >>= 1) v += __shfl_xor_sync(0xffffffffu, v, o);
    return v;
}

// split fp32 pair -> bf16x2 hi + bf16x2 lo (lo = rounded residual); low half = .x
__device__ __forceinline__ void bfsplit2(float2 v, uint32_t& hi, uint32_t& lo) {
    asm("cvt.rn.bf16x2.f32 %0, %1, %2;" : "=r"(hi) : "f"(v.y), "f"(v.x));
    float hx = __uint_as_float(hi << 16);
    float hy = __uint_as_float(hi & 0xFFFF0000u);
    float rx = v.x - hx;
    float ry = v.y - hy;
    asm("cvt.rn.bf16x2.f32 %0, %1, %2;" : "=r"(lo) : "f"(ry), "f"(rx));
}

// m16n8k16 bf16 MMA, fp32 accumulate (legacy HMMA path, valid at compute_103)
#define MMA_BF16(d, a0, a1, a2, a3, b0, b1) \
    asm volatile("mma.sync.aligned.m16n8k16.row.col.f32.bf16.bf16.f32 " \
        "{%0,%1,%2,%3}, {%4,%5,%6,%7}, {%8,%9}, {%0,%1,%2,%3};" \
        : "+f"((d)[0]), "+f"((d)[1]), "+f"((d)[2]), "+f"((d)[3]) \
        : "r"(a0), "r"(a1), "r"(a2), "r"(a3), "r"(b0), "r"(b1))

// ---------------- k0: beta/gamma precompute ----------------------------------
__global__ void k0_rates(const float* __restrict__ lb, const float* __restrict__ lg) {
    int i = blockIdx.x * blockDim.x + threadIdx.x;
    if (i < XD) {
        g_beta[i]  = softplusf(lb[i]);   // * DT (=1)
        g_gamma[i] = softplusf(lg[i]);
    }
}

// ---------------- k1: h1 = gelu(LN([s,u]@W1 + b1)) (scalar, R5 version) -------
#define KC 32
#define K1_SMEM_FLOATS (2*KC*68 + 2*KC*132)
__global__ void __launch_bounds__(256, 2) k1_enc1(
    const float* __restrict__ s, const float* __restrict__ u,
    const float* __restrict__ w1, const float* __restrict__ b1)
{
    extern __shared__ float sm1[];
    float (*Ast)[KC][68]  = (float (*)[KC][68])sm1;               // [buf][k][m]
    float (*Ws )[KC][132] = (float (*)[KC][132])(sm1 + 2*KC*68);  // [buf][k][n]

    int tid = threadIdx.x;
    int tn = tid & 31, tm = tid >> 5;
    int m0 = blockIdx.x * 64;

    for (int i = tid; i < 2 * KC * 28; i += 256) {
        int b = i / (KC * 28);
        int r = (i / 28) % KC;
        int c = 100 + (i % 28);
        Ws[b][r][c] = 0.f;
    }

    int aM[2], aK4[2];
#pragma unroll
    for (int t = 0; t < 2; t++) {
        int idx = tid + t * 256;
        aM [t] = idx >> 3;
        aK4[t] = (idx & 7) * 4;
    }
    int wRow[4], wC4[4];
#pragma unroll
    for (int t = 0; t < 4; t++) {
        int lin = tid + t * 256;
        wRow[t] = lin / 25;
        wC4 [t] = (lin - wRow[t] * 25) * 4;
    }

    float4 aReg[2];
    float4 wReg[4];

#pragma unroll
    for (int t = 0; t < 2; t++) {
        int gk = aK4[t];
        const float* base = (gk < XD) ? &s[(size_t)(m0 + aM[t]) * XD + gk]
                                      : &u[(size_t)(m0 + aM[t]) * XD + gk - XD];
        aReg[t] = *(const float4*)base;
    }
#pragma unroll
    for (int t = 0; t < 3; t++)
        wReg[t] = *(const float4*)&w1[(size_t)wRow[t] * HD + wC4[t]];
    if (tid < 32)
        wReg[3] = *(const float4*)&w1[(size_t)wRow[3] * HD + wC4[3]];

    float acc[8][4];
#pragma unroll
    for (int i = 0; i < 8; i++)
#pragma unroll
        for (int j = 0; j < 4; j++) acc[i][j] = 0.f;

    float bv[4] = {0.f, 0.f, 0.f, 0.f};
    if (tn < 25) {
        float4 b = *(const float4*)&b1[tn * 4];
        bv[0] = b.x; bv[1] = b.y; bv[2] = b.z; bv[3] = b.w;
    }

    int buf = 0;
    for (int kb = 0; kb < KTOT; kb += KC) {
#pragma unroll
        for (int t = 0; t < 2; t++) {
            Ast[buf][aK4[t] + 0][aM[t]] = aReg[t].x;
            Ast[buf][aK4[t] + 1][aM[t]] = aReg[t].y;
            Ast[buf][aK4[t] + 2][aM[t]] = aReg[t].z;
            Ast[buf][aK4[t] + 3][aM[t]] = aReg[t].w;
        }
#pragma unroll
        for (int t = 0; t < 3; t++)
            *(float4*)&Ws[buf][wRow[t]][wC4[t]] = wReg[t];
        if (tid < 32)
            *(float4*)&Ws[buf][wRow[3]][wC4[3]] = wReg[3];
        __syncthreads();

        int kn = kb + KC;
        if (kn < KTOT) {
#pragma unroll
            for (int t = 0; t < 2; t++) {
                int gk = kn + aK4[t];
                const float* base = (gk < XD) ? &s[(size_t)(m0 + aM[t]) * XD + gk]
                                              : &u[(size_t)(m0 + aM[t]) * XD + gk - XD];
                aReg[t] = *(const float4*)base;
            }
#pragma unroll
            for (int t = 0; t < 3; t++)
                wReg[t] = *(const float4*)&w1[(size_t)(kn + wRow[t]) * HD + wC4[t]];
            if (tid < 32)
                wReg[3] = *(const float4*)&w1[(size_t)(kn + wRow[3]) * HD + wC4[3]];
        }

#pragma unroll 8
        for (int k = 0; k < KC; k++) {
            float4 w  = *(const float4*)&Ws [buf][k][tn * 4];
            float4 a0 = *(const float4*)&Ast[buf][k][tm * 8];
            float4 a1 = *(const float4*)&Ast[buf][k][tm * 8 + 4];
            float av[8] = {a0.x, a0.y, a0.z, a0.w, a1.x, a1.y, a1.z, a1.w};
#pragma unroll
            for (int i = 0; i < 8; i++) {
                acc[i][0] = fmaf(av[i], w.x, acc[i][0]);
                acc[i][1] = fmaf(av[i], w.y, acc[i][1]);
                acc[i][2] = fmaf(av[i], w.z, acc[i][2]);
                acc[i][3] = fmaf(av[i], w.w, acc[i][3]);
            }
        }
        buf ^= 1;
    }

#pragma unroll
    for (int i = 0; i < 8; i++) {
        int m = m0 + tm * 8 + i;
        float x[4], sm = 0.f, sq = 0.f;
#pragma unroll
        for (int j = 0; j < 4; j++) {
            x[j] = acc[i][j] + bv[j];
            sm += x[j];
            sq += x[j] * x[j];
        }
        sm = wsum(sm); sq = wsum(sq);
        float mean = sm * (1.f / HD);
        float var  = sq * (1.f / HD) - mean * mean;
        float rs = rsqrtf(var + LN_EPS);
        if (tn < 25) {
            float4 o;
            o.x = geluf((x[0] - mean) * rs);
            o.y = geluf((x[1] - mean) * rs);
            o.z = geluf((x[2] - mean) * rs);
            o.w = geluf((x[3] - mean) * rs);
            *(float4*)&g_h1[(size_t)m * HD + tn * 4] = o;
        }
    }
}

// ---------------- k2: everything small, one warp per row (R5 version) ---------
#define K2_SMEM_FLOATS (22380 + 8*264)
__global__ void __launch_bounds__(256) k2_mid(
    const float* __restrict__ eps_z, const float* __restrict__ eps_d,
    const float* __restrict__ w2, const float* __restrict__ b2,
    const float* __restrict__ wmu, const float* __restrict__ bmu,
    const float* __restrict__ wlv, const float* __restrict__ blv,
    const float* __restrict__ edw1, const float* __restrict__ edb1,
    const float* __restrict__ edwmu, const float* __restrict__ edbmu,
    const float* __restrict__ edwlv, const float* __restrict__ edblv,
    const float* __restrict__ dzw1, const float* __restrict__ dzb1,
    float* __restrict__ o_z, float* __restrict__ o_dz,
    float* __restrict__ o_muz, float* __restrict__ o_scz,
    float* __restrict__ o_mud, float* __restrict__ o_scd)
{
    extern __shared__ float sm2[];
    float* sw2    = sm2;              // 10000
    float* swmu   = sw2 + 10000;      // 2000
    float* swlv   = swmu + 2000;      // 2000
    float* sb2    = swlv + 2000;      // 100
    float* sbmu   = sb2 + 100;        // 20
    float* sblv   = sbmu + 20;        // 20
    float* sedw1  = sblv + 20;        // 2000
    float* sedb1  = sedw1 + 2000;     // 100
    float* sedwmu = sedb1 + 100;      // 2000
    float* sedbmu = sedwmu + 2000;    // 20
    float* sedwlv = sedbmu + 20;      // 2000
    float* sedblv = sedwlv + 2000;    // 20
    float* sdzw1  = sedblv + 20;      // 2000
    float* sdzb1  = sdzw1 + 2000;     // 100
    float* wbuf   = sdzb1 + 100;      // 8 warps * 264

    {
        int t = threadIdx.x, nt = blockDim.x;
        for (int i = t; i < 10000; i += nt) sw2[i] = w2[i];
        for (int i = t; i < 2000; i += nt) { swmu[i] = wmu[i]; swlv[i] = wlv[i]; }
        for (int i = t; i < 2000; i += nt) { sedw1[i] = edw1[i]; sdzw1[i] = dzw1[i]; }
        for (int i = t; i < 2000; i += nt) { sedwmu[i] = edwmu[i]; sedwlv[i] = edwlv[i]; }
        for (int i = t; i < 100; i += nt) { sb2[i] = b2[i]; sedb1[i] = edb1[i]; sdzb1[i] = dzb1[i]; }
        if (t < 20) { sbmu[t] = bmu[t]; sblv[t] = blv[t]; sedbmu[t] = edbmu[t]; sedblv[t] = edblv[t]; }
    }
    __syncthreads();

    int wid = threadIdx.x >> 5, lane = threadIdx.x & 31;
    float* B0 = wbuf + wid * 264;
    float* B1 = B0 + 132;
    int nwarps = gridDim.x * 8;

    for (int r = blockIdx.x * 8 + wid; r < BB; r += nwarps) {
        for (int i = lane; i < HD; i += 32) B0[i] = g_h1[(size_t)r * HD + i];
        __syncwarp();

        float x[4] = {0.f, 0.f, 0.f, 0.f};
        if (lane < 25) {
            float4 bb4 = *(const float4*)&sb2[lane * 4];
            x[0] = bb4.x; x[1] = bb4.y; x[2] = bb4.z; x[3] = bb4.w;
            for (int k = 0; k < HD; k++) {
                float b = B0[k];
                float4 w = *(const float4*)&sw2[k * HD + lane * 4];
                x[0] = fmaf(b, w.x, x[0]);
                x[1] = fmaf(b, w.y, x[1]);
                x[2] = fmaf(b, w.z, x[2]);
                x[3] = fmaf(b, w.w, x[3]);
            }
        }
        float smv = x[0] + x[1] + x[2] + x[3];
        float sqv = x[0]*x[0] + x[1]*x[1] + x[2]*x[2] + x[3]*x[3];
        smv = wsum(smv); sqv = wsum(sqv);
        float mean = smv * (1.f / HD);
        float rs = rsqrtf(sqv * (1.f / HD) - mean * mean + LN_EPS);
        if (lane < 25) {
            float4 o;
            o.x = geluf((x[0] - mean) * rs);
            o.y = geluf((x[1] - mean) * rs);
            o.z = geluf((x[2] - mean) * rs);
            o.w = geluf((x[3] - mean) * rs);
            *(float4*)&B1[lane * 4] = o;
        }
        __syncwarp();

        if (lane < ZD) {
            float mu = sbmu[lane], lv = sblv[lane];
            for (int k = 0; k < HD; k++) {
                float h = B1[k];
                mu += h * swmu[k * ZD + lane];
                lv += h * swlv[k * ZD + lane];
            }
            float sc = softplusf(lv);
            float z = mu + sc * eps_z[(size_t)r * ZD + lane];
            o_z  [(size_t)r * ZD + lane] = z;
            o_muz[(size_t)r * ZD + lane] = mu;
            o_scz[(size_t)r * ZD + lane] = sc;
            B0[lane] = z;
        }
        __syncwarp();

        x[0] = x[1] = x[2] = x[3] = 0.f;
        if (lane < 25) {
            float4 bb4 = *(const float4*)&sedb1[lane * 4];
            x[0] = bb4.x; x[1] = bb4.y; x[2] = bb4.z; x[3] = bb4.w;
            for (int k = 0; k < ZD; k++) {
                float b = B0[k];
                float4 w = *(const float4*)&sedw1[k * HD + lane * 4];
                x[0] = fmaf(b, w.x, x[0]);
                x[1] = fmaf(b, w.y, x[1]);
                x[2] = fmaf(b, w.z, x[2]);
                x[3] = fmaf(b, w.w, x[3]);
            }
        }
        smv = x[0] + x[1] + x[2] + x[3];
        sqv = x[0]*x[0] + x[1]*x[1] + x[2]*x[2] + x[3]*x[3];
        smv = wsum(smv); sqv = wsum(sqv);
        mean = smv * (1.f / HD);
        rs = rsqrtf(sqv * (1.f / HD) - mean * mean + LN_EPS);
        if (lane < 25) {
            float4 o;
            o.x = geluf((x[0] - mean) * rs);
            o.y = geluf((x[1] - mean) * rs);
            o.z = geluf((x[2] - mean) * rs);
            o.w = geluf((x[3] - mean) * rs);
            *(float4*)&B1[lane * 4] = o;
        }
        __syncwarp();

        if (lane < ZD) {
            float mu = sedbmu[lane], lv = sedblv[lane];
            for (int k = 0; k < HD; k++) {
                float h = B1[k];
                mu += h * sedwmu[k * ZD + lane];
                lv += h * sedwlv[k * ZD + lane];
            }
            float sc = softplusf(lv);
            float dz = mu + sc * eps_d[(size_t)r * ZD + lane];
            o_dz [(size_t)r * ZD + lane] = dz;
            o_mud[(size_t)r * ZD + lane] = mu;
            o_scd[(size_t)r * ZD + lane] = sc;
            B0[32 + lane] = dz;
        }
        __syncwarp();

        float a[4] = {0.f,0.f,0.f,0.f}, t[4] = {0.f,0.f,0.f,0.f};
        if (lane < 25) {
            float4 bb4 = *(const float4*)&sdzb1[lane * 4];
            a[0] = bb4.x; a[1] = bb4.y; a[2] = bb4.z; a[3] = bb4.w;
            for (int k = 0; k < ZD; k++) {
                float zz = B0[k];
                float dd = B0[32 + k];
                float4 w = *(const float4*)&sdzw1[k * HD + lane * 4];
                a[0] = fmaf(zz, w.x, a[0]); t[0] = fmaf(dd, w.x, t[0]);
                a[1] = fmaf(zz, w.y, a[1]); t[1] = fmaf(dd, w.y, t[1]);
                a[2] = fmaf(zz, w.z, a[2]); t[2] = fmaf(dd, w.z, t[2]);
                a[3] = fmaf(zz, w.w, a[3]); t[3] = fmaf(dd, w.w, t[3]);
            }
        }
        float sa = a[0]+a[1]+a[2]+a[3];
        float saa = a[0]*a[0]+a[1]*a[1]+a[2]*a[2]+a[3]*a[3];
        float st = t[0]+t[1]+t[2]+t[3];
        float sat = a[0]*t[0]+a[1]*t[1]+a[2]*t[2]+a[3]*t[3];
        sa = wsum(sa); saa = wsum(saa); st = wsum(st); sat = wsum(sat);
        float m  = sa * (1.f / HD);
        float v  = saa * (1.f / HD) - m * m;
        float r2 = rsqrtf(v + LN_EPS);
        float dm = st * (1.f / HD);
        float dv = 2.f * (sat * (1.f / HD) - m * dm);
        if (lane < 25) {
            float4 oh, ot;
            float y, dy, Phi, phi;
#pragma unroll
            for (int j = 0; j < 4; j++) {
                y  = (a[j] - m) * r2;
                dy = r2 * (t[j] - dm) - 0.5f * y * r2 * r2 * dv;
                Phi = 0.5f * (1.f + erff(y * 0.70710678118654752f));
                phi = 0.3989422804014327f * expf(-0.5f * y * y);
                ((float*)&oh)[j] = y * Phi;
                ((float*)&ot)[j] = (Phi + y * phi) * dy;
            }
            *(float4*)&g_h1g[(size_t)r * HD + lane * 4] = oh;
            *(float4*)&g_th [(size_t)r * HD + lane * 4] = ot;
        }
        __syncwarp();
    }
}

// ---------------- k3: mma.sync bf16-split GEMM (H@W and T@W fused) ------------
// M-tile=64/block (grid 256). 4 A tiles (Hhi,Hlo,Thi,Tlo) staged once as
// [row][k-word] bf16x2 (K=100 -> 112 pad, 56 words, row stride 60 words).
// Loop over 32 N-chunks of 64: stage W hi/lo transposed [n][k-word], then each
// warp computes an m16 x n32 region: 7 k-steps x (A/B fragment LDS + 6 MMAs
// per n-tile pair set). 3-split: hi*hi + hi*lo + lo*hi.
#define RS3 60
#define TW3 (64*RS3)           // words per tile = 3840
#define OAHI 0
#define OALO (1*TW3)
#define OTHI (2*TW3)
#define OTLO (3*TW3)
#define OBHI (4*TW3)
#define OBLO (5*TW3)
#define K3_SMEM_BYTES (6*TW3*4)   // 92160

__global__ void __launch_bounds__(256, 2) k3_mma(
    const float* __restrict__ w2, const float* __restrict__ b2)
{
    extern __shared__ uint32_t smu[];
    int tid = threadIdx.x, wid = tid >> 5, lane = tid & 31;
    int m0 = blockIdx.x * 64;

    // ---- stage A tiles once (zero-pad k-words 50..55) ----
    for (int lin = tid; lin < 64 * 56; lin += 256) {
        int row = lin / 56, w = lin - row * 56;
        float2 h2 = make_float2(0.f, 0.f), t2 = h2;
        if (w < 50) {
            h2 = *(const float2*)&g_h1g[(size_t)(m0 + row) * HD + 2 * w];
            t2 = *(const float2*)&g_th [(size_t)(m0 + row) * HD + 2 * w];
        }
        uint32_t hh, hl, th, tl;
        bfsplit2(h2, hh, hl);
        bfsplit2(t2, th, tl);
        int o = row * RS3 + w;
        smu[OAHI + o] = hh;
        smu[OALO + o] = hl;
        smu[OTHI + o] = th;
        smu[OTLO + o] = tl;
    }

    int g = lane >> 2, tg = lane & 3;
    int mrow = (wid & 3) * 16;
    int nb = (wid >> 2) * 32;
    int arow0 = (mrow + g) * RS3;
    int arow1 = (mrow + 8 + g) * RS3;

    for (int ch = 0; ch < 32; ch++) {
        int n0 = ch * 64;
        // ---- stage W chunk: [n][k-word] hi/lo, zero pad ----
        for (int lin = tid; lin < 64 * 56; lin += 256) {
            int w = lin >> 6, n = lin & 63;
            int col = n0 + n;
            float2 wv = make_float2(0.f, 0.f);
            if (w < 50 && col < XD) {
                wv.x = w2[(size_t)(2 * w) * XD + col];
                wv.y = w2[(size_t)(2 * w + 1) * XD + col];
            }
            uint32_t whi, wlo;
            bfsplit2(wv, whi, wlo);
            smu[OBHI + n * RS3 + w] = whi;
            smu[OBLO + n * RS3 + w] = wlo;
        }
        __syncthreads();

        float dH[4][4], dT[4][4];
#pragma unroll
        for (int j = 0; j < 4; j++)
#pragma unroll
            for (int e = 0; e < 4; e++) { dH[j][e] = 0.f; dT[j][e] = 0.f; }

#pragma unroll
        for (int ks = 0; ks < 7; ks++) {
            int kw = ks * 8;
            uint32_t ah0 = smu[OAHI + arow0 + kw + tg];
            uint32_t ah1 = smu[OAHI + arow1 + kw + tg];
            uint32_t ah2 = smu[OAHI + arow0 + kw + 4 + tg];
            uint32_t ah3 = smu[OAHI + arow1 + kw + 4 + tg];
            uint32_t al0 = smu[OALO + arow0 + kw + tg];
            uint32_t al1 = smu[OALO + arow1 + kw + tg];
            uint32_t al2 = smu[OALO + arow0 + kw + 4 + tg];
            uint32_t al3 = smu[OALO + arow1 + kw + 4 + tg];
            uint32_t th0 = smu[OTHI + arow0 + kw + tg];
            uint32_t th1 = smu[OTHI + arow1 + kw + tg];
            uint32_t th2 = smu[OTHI + arow0 + kw + 4 + tg];
            uint32_t th3 = smu[OTHI + arow1 + kw + 4 + tg];
            uint32_t tl0 = smu[OTLO + arow0 + kw + tg];
            uint32_t tl1 = smu[OTLO + arow1 + kw + tg];
            uint32_t tl2 = smu[OTLO + arow0 + kw + 4 + tg];
            uint32_t tl3 = smu[OTLO + arow1 + kw + 4 + tg];
#pragma unroll
            for (int j = 0; j < 4; j++) {
                int brow = (nb + j * 8 + g) * RS3;
                uint32_t bh0 = smu[OBHI + brow + kw + tg];
                uint32_t bh1 = smu[OBHI + brow + kw + 4 + tg];
                uint32_t bl0 = smu[OBLO + brow + kw + tg];
                uint32_t bl1 = smu[OBLO + brow + kw + 4 + tg];
                MMA_BF16(dH[j], ah0, ah1, ah2, ah3, bh0, bh1);
                MMA_BF16(dH[j], ah0, ah1, ah2, ah3, bl0, bl1);
                MMA_BF16(dH[j], al0, al1, al2, al3, bh0, bh1);
                MMA_BF16(dT[j], th0, th1, th2, th3, bh0, bh1);
                MMA_BF16(dT[j], th0, th1, th2, th3, bl0, bl1);
                MMA_BF16(dT[j], tl0, tl1, tl2, tl3, bh0, bh1);
            }
        }
        __syncthreads();   // all B reads done before next chunk's staging

        // ---- epilogue: bias + softplus / sigmoid*tangent, store pairs ----
        int r0 = m0 + mrow + g;
        int r1 = r0 + 8;
#pragma unroll
        for (int j = 0; j < 4; j++) {
            int c0 = n0 + nb + j * 8 + 2 * tg;
            if (c0 < XD) {
                float bx = b2[c0], by = b2[c0 + 1];
                float a0 = dH[j][0] + bx, a1 = dH[j][1] + by;
                float a2 = dH[j][2] + bx, a3 = dH[j][3] + by;
                float2 l0, t0, l1, t1;
                l0.x = softplusf(a0); t0.x = sigmoidf(a0) * dT[j][0];
                l0.y = softplusf(a1); t0.y = sigmoidf(a1) * dT[j][1];
                l1.x = softplusf(a2); t1.x = sigmoidf(a2) * dT[j][2];
                l1.y = softplusf(a3); t1.y = sigmoidf(a3) * dT[j][3];
                *(float2*)&g_ld [(size_t)r0 * XD + c0] = l0;
                *(float2*)&g_tld[(size_t)r0 * XD + c0] = t0;
                *(float2*)&g_ld [(size_t)r1 * XD + c0] = l1;
                *(float2*)&g_tld[(size_t)r1 * XD + c0] = t1;
            }
        }
    }
}

// ---------------- k4: per-row sums + finalize ---------------------------------
__global__ void __launch_bounds__(256) k4_fin(
    float* __restrict__ o_shat, float* __restrict__ o_diff, float* __restrict__ o_pu)
{
    __shared__ float red[16];
    int r = blockIdx.x;
    int tid = threadIdx.x;

    float4 l[2], tl[2];
    float sl = 0.f, st = 0.f;
#pragma unroll
    for (int j = 0; j < 2; j++) {
        int c = (tid + j * 256) * 4;
        if (c < XD) {
            l [j] = *(const float4*)&g_ld [(size_t)r * XD + c];
            tl[j] = *(const float4*)&g_tld[(size_t)r * XD + c];
            sl += l [j].x + l [j].y + l [j].z + l [j].w;
            st += tl[j].x + tl[j].y + tl[j].z + tl[j].w;
        }
    }
    sl = wsum(sl); st = wsum(st);
    int wid = tid >> 5, lane = tid & 31;
    if (lane == 0) { red[wid] = sl; red[8 + wid] = st; }
    __syncthreads();
    sl = red[0]+red[1]+red[2]+red[3]+red[4]+red[5]+red[6]+red[7];
    st = red[8]+red[9]+red[10]+red[11]+red[12]+red[13]+red[14]+red[15];

    float m  = sl * (1.f / XD);
    float mt = st * (1.f / XD);
    float rm = 1.f / m;
    float cm = mt * rm * rm;

#pragma unroll
    for (int j = 0; j < 2; j++) {
        int c = (tid + j * 256) * 4;
        if (c < XD) {
            float4 be = *(const float4*)&g_beta[c];
            float4 ga = *(const float4*)&g_gamma[c];
            float4 sh, df, pu;
            sh.x = l[j].x * rm; df.x = 0.01f * (tl[j].x * rm - l[j].x * cm);
            sh.y = l[j].y * rm; df.y = 0.01f * (tl[j].y * rm - l[j].y * cm);
            sh.z = l[j].z * rm; df.z = 0.01f * (tl[j].z * rm - l[j].z * cm);
            sh.w = l[j].w * rm; df.w = 0.01f * (tl[j].w * rm - l[j].w * cm);
            pu.x = fmaxf((df.x + sh.x * ga.x) / be.x, 0.f);
            pu.y = fmaxf((df.y + sh.y * ga.y) / be.y, 0.f);
            pu.z = fmaxf((df.z + sh.z * ga.z) / be.z, 0.f);
            pu.w = fmaxf((df.w + sh.w * ga.w) / be.w, 0.f);
            *(float4*)&o_shat[(size_t)r * XD + c] = sh;
            *(float4*)&o_diff[(size_t)r * XD + c] = df;
            *(float4*)&o_pu  [(size_t)r * XD + c] = pu;
        }
    }
}

// ---------------- launcher ----------------------------------------------------
extern "C" void kernel_launch(void* const* d_in, const int* in_sizes, int n_in,
                              void* d_out, int out_size)
{
    const float* s      = (const float*)d_in[0];
    const float* u      = (const float*)d_in[1];
    const float* eps_z  = (const float*)d_in[2];
    const float* eps_d  = (const float*)d_in[3];
    const float* ez_w1  = (const float*)d_in[4];
    const float* ez_b1  = (const float*)d_in[5];
    const float* ez_w2  = (const float*)d_in[6];
    const float* ez_b2  = (const float*)d_in[7];
    const float* ez_wmu = (const float*)d_in[8];
    const float* ez_bmu = (const float*)d_in[9];
    const float* ez_wlv = (const float*)d_in[10];
    const float* ez_blv = (const float*)d_in[11];
    const float* ed_w1  = (const float*)d_in[12];
    const float* ed_b1  = (const float*)d_in[13];
    const float* ed_wmu = (const float*)d_in[14];
    const float* ed_bmu = (const float*)d_in[15];
    const float* ed_wlv = (const float*)d_in[16];
    const float* ed_blv = (const float*)d_in[17];
    const float* dz_w1  = (const float*)d_in[18];
    const float* dz_b1  = (const float*)d_in[19];
    const float* dz_w2  = (const float*)d_in[20];
    const float* dz_b2  = (const float*)d_in[21];
    const float* logb   = (const float*)d_in[22];
    const float* logg   = (const float*)d_in[23];

    float* out = (float*)d_out;
    float* o_z    = out;
    float* o_dz   = o_z    + (size_t)BB * ZD;
    float* o_muz  = o_dz   + (size_t)BB * ZD;
    float* o_scz  = o_muz  + (size_t)BB * ZD;
    float* o_mud  = o_scz  + (size_t)BB * ZD;
    float* o_scd  = o_mud  + (size_t)BB * ZD;
    float* o_shat = o_scd  + (size_t)BB * ZD;
    float* o_diff = o_shat + (size_t)BB * XD;
    float* o_pu   = o_diff + (size_t)BB * XD;

    const int smem1 = K1_SMEM_FLOATS * 4;
    const int smem2 = K2_SMEM_FLOATS * 4;
    cudaFuncSetAttribute(k1_enc1, cudaFuncAttributeMaxDynamicSharedMemorySize, smem1);
    cudaFuncSetAttribute(k2_mid, cudaFuncAttributeMaxDynamicSharedMemorySize, smem2);
    cudaFuncSetAttribute(k3_mma, cudaFuncAttributeMaxDynamicSharedMemorySize, K3_SMEM_BYTES);

    k0_rates<<<8, 256>>>(logb, logg);
    k1_enc1<<<BB / 64, 256, smem1>>>(s, u, ez_w1, ez_b1);
    k2_mid<<<512, 256, smem2>>>(eps_z, eps_d,
                                ez_w2, ez_b2, ez_wmu, ez_bmu, ez_wlv, ez_blv,
                                ed_w1, ed_b1, ed_wmu, ed_bmu, ed_wlv, ed_blv,
                                dz_w1, dz_b1,
                                o_z, o_dz, o_muz, o_scz, o_mud, o_scd);
    k3_mma<<<BB / 64, 256, K3_SMEM_BYTES>>>(dz_w2, dz_b2);
    k4_fin<<<BB, 256>>>(o_shat, o_diff, o_pu);
}

// round 8
// speedup vs baseline: 2.9513x; 1.0060x over previous
#include <cuda_runtime.h>
#include <cuda_bf16.h>
#include <math.h>
#include <stdint.h>

#define BB 16384
#define XD 2000
#define HD 100
#define ZD 20
#define KTOT (2*XD)      // 4000
#define LN_EPS 1e-5f

// ---------------- scratch (static device globals; no allocations) -------------
__device__ float g_h1 [(size_t)BB*HD];
__device__ float g_h1g[(size_t)BB*HD];
__device__ float g_th [(size_t)BB*HD];
__device__ float g_ld [(size_t)BB*XD];
__device__ float g_tld[(size_t)BB*XD];
__device__ float g_beta [XD];
__device__ float g_gamma[XD];
// W1 pre-transposed bf16 split: [n(112)][kword(2000)]
__device__ uint32_t g_w1hi[112 * 2000];
__device__ uint32_t g_w1lo[112 * 2000];

// ---------------- helpers -----------------------------------------------------
__device__ __forceinline__ float softplusf(float x) {
    return fmaxf(x, 0.f) + log1pf(expf(-fabsf(x)));
}
__device__ __forceinline__ float sigmoidf(float x) {
    return 1.f / (1.f + expf(-x));
}
__device__ __forceinline__ float geluf(float x) {
    return 0.5f * x * (1.f + erff(x * 0.70710678118654752f));
}
__device__ __forceinline__ float wsum(float v) {
#pragma unroll
    for (int o = 16; o; o >>= 1) v += __shfl_xor_sync(0xffffffffu, v, o);
    return v;
}

// split fp32 pair -> bf16x2 hi + bf16x2 lo (lo = rounded residual); low half = .x
__device__ __forceinline__ void bfsplit2(float2 v, uint32_t& hi, uint32_t& lo) {
    asm("cvt.rn.bf16x2.f32 %0, %1, %2;" : "=r"(hi) : "f"(v.y), "f"(v.x));
    float hx = __uint_as_float(hi << 16);
    float hy = __uint_as_float(hi & 0xFFFF0000u);
    float rx = v.x - hx;
    float ry = v.y - hy;
    asm("cvt.rn.bf16x2.f32 %0, %1, %2;" : "=r"(lo) : "f"(ry), "f"(rx));
}

// m16n8k16 bf16 MMA, fp32 accumulate (legacy HMMA path, valid at compute_103)
#define MMA_BF16(d, a0, a1, a2, a3, b0, b1) \
    asm volatile("mma.sync.aligned.m16n8k16.row.col.f32.bf16.bf16.f32 " \
        "{%0,%1,%2,%3}, {%4,%5,%6,%7}, {%8,%9}, {%0,%1,%2,%3};" \
        : "+f"((d)[0]), "+f"((d)[1]), "+f"((d)[2]), "+f"((d)[3]) \
        : "r"(a0), "r"(a1), "r"(a2), "r"(a3), "r"(b0), "r"(b1))

// ---------------- k0: beta/gamma precompute ----------------------------------
__global__ void k0_rates(const float* __restrict__ lb, const float* __restrict__ lg) {
    int i = blockIdx.x * blockDim.x + threadIdx.x;
    if (i < XD) {
        g_beta[i]  = softplusf(lb[i]);   // * DT (=1)
        g_gamma[i] = softplusf(lg[i]);
    }
}

// ---------------- k0b: W1 -> transposed bf16 split ----------------------------
__global__ void k0b_w1split(const float* __restrict__ w1) {
    int idx = blockIdx.x * 256 + threadIdx.x;
    if (idx >= 112 * 2000) return;
    int n = idx / 2000, kw = idx - n * 2000;
    float2 v = make_float2(0.f, 0.f);
    if (n < HD) {
        v.x = w1[(size_t)(2 * kw) * HD + n];
        v.y = w1[(size_t)(2 * kw + 1) * HD + n];
    }
    uint32_t hi, lo;
    bfsplit2(v, hi, lo);
    g_w1hi[idx] = hi;
    g_w1lo[idx] = lo;
}

// ---------------- k1: mma.sync bf16-split: h1 = gelu(LN([s,u]@W1 + b1)) -------
// M-tile=64 (grid 256). 8 warps = 4 M x 2 N-halves (each warp m16 x n56).
// K chunks of 64 (32 kwords), 63 chunks (zero-padded tail).
// smem word layout, row stride 36 (bank = (4g+tg)%32, conflict-free frags).
#define K1RS 36
#define OAH1 0
#define OAL1 (64*K1RS)             // 2304
#define OBH1 (2*64*K1RS)           // 4608
#define OBL1 (OBH1 + 112*K1RS)     // 8640
#define K1_SMEM_BYTES ((2*64*K1RS + 2*112*K1RS) * 4)   // 50688

__global__ void __launch_bounds__(256, 2) k1_mma(
    const float* __restrict__ s, const float* __restrict__ u,
    const float* __restrict__ b1)
{
    extern __shared__ uint32_t smu[];
    int tid = threadIdx.x, wid = tid >> 5, lane = tid & 31;
    int m0 = blockIdx.x * 64;
    int g = lane >> 2, tg = lane & 3;
    int mwarp = wid & 3, nh = wid >> 2;

    float dA[7][4];
#pragma unroll
    for (int j = 0; j < 7; j++)
#pragma unroll
        for (int e = 0; e < 4; e++) dA[j][e] = 0.f;

    int abase0 = OAH1 + (mwarp * 16 + g) * K1RS;
    int abase1 = abase0 + 8 * K1RS;

    for (int c = 0; c < 63; c++) {
        int kw0 = c * 32;
        // ---- stage A: 64 rows x 32 kwords, convert fp32 -> bf16 hi/lo ----
#pragma unroll
        for (int i = 0; i < 8; i++) {
            int lin = tid + i * 256;
            int row = lin >> 5, w = lin & 31;
            int kw = kw0 + w;
            float2 v = make_float2(0.f, 0.f);
            if (kw < 1000)      v = *(const float2*)&s[(size_t)(m0 + row) * XD + 2 * kw];
            else if (kw < 2000) v = *(const float2*)&u[(size_t)(m0 + row) * XD + 2 * kw - XD];
            uint32_t hi, lo;
            bfsplit2(v, hi, lo);
            smu[OAH1 + row * K1RS + w] = hi;
            smu[OAL1 + row * K1RS + w] = lo;
        }
        // ---- stage B: 112 n x 32 kwords from precomputed split ----
#pragma unroll
        for (int i = 0; i < 14; i++) {
            int lin = tid + i * 256;
            int n = lin >> 5, w = lin & 31;
            int kw = kw0 + w;
            uint32_t hi = 0u, lo = 0u;
            if (kw < 2000) {
                hi = g_w1hi[n * 2000 + kw];
                lo = g_w1lo[n * 2000 + kw];
            }
            smu[OBH1 + n * K1RS + w] = hi;
            smu[OBL1 + n * K1RS + w] = lo;
        }
        __syncthreads();

#pragma unroll
        for (int ks = 0; ks < 4; ks++) {
            int kw = ks * 8 + tg;
            uint32_t ah0 = smu[abase0 + kw];
            uint32_t ah1 = smu[abase1 + kw];
            uint32_t ah2 = smu[abase0 + kw + 4];
            uint32_t ah3 = smu[abase1 + kw + 4];
            uint32_t al0 = smu[OAL1 - OAH1 + abase0 + kw];
            uint32_t al1 = smu[OAL1 - OAH1 + abase1 + kw];
            uint32_t al2 = smu[OAL1 - OAH1 + abase0 + kw + 4];
            uint32_t al3 = smu[OAL1 - OAH1 + abase1 + kw + 4];
#pragma unroll
            for (int j = 0; j < 7; j++) {
                int bb = OBH1 + (nh * 56 + 8 * j + g) * K1RS + kw;
                uint32_t bh0 = smu[bb];
                uint32_t bh1 = smu[bb + 4];
                uint32_t bl0 = smu[bb + (OBL1 - OBH1)];
                uint32_t bl1 = smu[bb + (OBL1 - OBH1) + 4];
                MMA_BF16(dA[j], ah0, ah1, ah2, ah3, bh0, bh1);
                MMA_BF16(dA[j], ah0, ah1, ah2, ah3, bl0, bl1);
                MMA_BF16(dA[j], al0, al1, al2, al3, bh0, bh1);
            }
        }
        __syncthreads();
    }

    // ---- epilogue: LN over N per row (halves joined via smem) + GELU ----
    float* red = (float*)smu;    // [64][2 halves][2 {sum,sq}]
    int lr0 = mwarp * 16 + g;
    int lr1 = lr0 + 8;

    float s0 = 0.f, q0 = 0.f, s1 = 0.f, q1 = 0.f;
#pragma unroll
    for (int j = 0; j < 7; j++) {
        int col = nh * 56 + 8 * j + 2 * tg;
        if (col < HD) {
            float bx = b1[col], by = b1[col + 1];
            float x0 = dA[j][0] + bx, x1 = dA[j][1] + by;
            float x2 = dA[j][2] + bx, x3 = dA[j][3] + by;
            s0 += x0 + x1; q0 += x0 * x0 + x1 * x1;
            s1 += x2 + x3; q1 += x2 * x2 + x3 * x3;
        }
    }
#pragma unroll
    for (int o = 1; o <= 2; o <<= 1) {
        s0 += __shfl_xor_sync(0xffffffffu, s0, o);
        q0 += __shfl_xor_sync(0xffffffffu, q0, o);
        s1 += __shfl_xor_sync(0xffffffffu, s1, o);
        q1 += __shfl_xor_sync(0xffffffffu, q1, o);
    }
    if (tg == 0) {
        red[(lr0 * 2 + nh) * 2 + 0] = s0;
        red[(lr0 * 2 + nh) * 2 + 1] = q0;
        red[(lr1 * 2 + nh) * 2 + 0] = s1;
        red[(lr1 * 2 + nh) * 2 + 1] = q1;
    }
    __syncthreads();

    float sum0 = red[(lr0 * 2) * 2 + 0] + red[(lr0 * 2 + 1) * 2 + 0];
    float sq0  = red[(lr0 * 2) * 2 + 1] + red[(lr0 * 2 + 1) * 2 + 1];
    float sum1 = red[(lr1 * 2) * 2 + 0] + red[(lr1 * 2 + 1) * 2 + 0];
    float sq1  = red[(lr1 * 2) * 2 + 1] + red[(lr1 * 2 + 1) * 2 + 1];
    float mean0 = sum0 * (1.f / HD);
    float mean1 = sum1 * (1.f / HD);
    float rs0 = rsqrtf(sq0 * (1.f / HD) - mean0 * mean0 + LN_EPS);
    float rs1 = rsqrtf(sq1 * (1.f / HD) - mean1 * mean1 + LN_EPS);

    int r0 = m0 + lr0, r1 = m0 + lr1;
#pragma unroll
    for (int j = 0; j < 7; j++) {
        int col = nh * 56 + 8 * j + 2 * tg;
        if (col < HD) {
            float bx = b1[col], by = b1[col + 1];
            float2 o0, o1;
            o0.x = geluf((dA[j][0] + bx - mean0) * rs0);
            o0.y = geluf((dA[j][1] + by - mean0) * rs0);
            o1.x = geluf((dA[j][2] + bx - mean1) * rs1);
            o1.y = geluf((dA[j][3] + by - mean1) * rs1);
            *(float2*)&g_h1[(size_t)r0 * HD + col] = o0;
            *(float2*)&g_h1[(size_t)r1 * HD + col] = o1;
        }
    }
}

// ---------------- k2: everything small, one warp per row (R5 version) ---------
#define K2_SMEM_FLOATS (22380 + 8*264)
__global__ void __launch_bounds__(256) k2_mid(
    const float* __restrict__ eps_z, const float* __restrict__ eps_d,
    const float* __restrict__ w2, const float* __restrict__ b2,
    const float* __restrict__ wmu, const float* __restrict__ bmu,
    const float* __restrict__ wlv, const float* __restrict__ blv,
    const float* __restrict__ edw1, const float* __restrict__ edb1,
    const float* __restrict__ edwmu, const float* __restrict__ edbmu,
    const float* __restrict__ edwlv, const float* __restrict__ edblv,
    const float* __restrict__ dzw1, const float* __restrict__ dzb1,
    float* __restrict__ o_z, float* __restrict__ o_dz,
    float* __restrict__ o_muz, float* __restrict__ o_scz,
    float* __restrict__ o_mud, float* __restrict__ o_scd)
{
    extern __shared__ float sm2[];
    float* sw2    = sm2;              // 10000
    float* swmu   = sw2 + 10000;      // 2000
    float* swlv   = swmu + 2000;      // 2000
    float* sb2    = swlv + 2000;      // 100
    float* sbmu   = sb2 + 100;        // 20
    float* sblv   = sbmu + 20;        // 20
    float* sedw1  = sblv + 20;        // 2000
    float* sedb1  = sedw1 + 2000;     // 100
    float* sedwmu = sedb1 + 100;      // 2000
    float* sedbmu = sedwmu + 2000;    // 20
    float* sedwlv = sedbmu + 20;      // 2000
    float* sedblv = sedwlv + 2000;    // 20
    float* sdzw1  = sedblv + 20;      // 2000
    float* sdzb1  = sdzw1 + 2000;     // 100
    float* wbuf   = sdzb1 + 100;      // 8 warps * 264

    {
        int t = threadIdx.x, nt = blockDim.x;
        for (int i = t; i < 10000; i += nt) sw2[i] = w2[i];
        for (int i = t; i < 2000; i += nt) { swmu[i] = wmu[i]; swlv[i] = wlv[i]; }
        for (int i = t; i < 2000; i += nt) { sedw1[i] = edw1[i]; sdzw1[i] = dzw1[i]; }
        for (int i = t; i < 2000; i += nt) { sedwmu[i] = edwmu[i]; sedwlv[i] = edwlv[i]; }
        for (int i = t; i < 100; i += nt) { sb2[i] = b2[i]; sedb1[i] = edb1[i]; sdzb1[i] = dzb1[i]; }
        if (t < 20) { sbmu[t] = bmu[t]; sblv[t] = blv[t]; sedbmu[t] = edbmu[t]; sedblv[t] = edblv[t]; }
    }
    __syncthreads();

    int wid = threadIdx.x >> 5, lane = threadIdx.x & 31;
    float* B0 = wbuf + wid * 264;
    float* B1 = B0 + 132;
    int nwarps = gridDim.x * 8;

    for (int r = blockIdx.x * 8 + wid; r < BB; r += nwarps) {
        for (int i = lane; i < HD; i += 32) B0[i] = g_h1[(size_t)r * HD + i];
        __syncwarp();

        float x[4] = {0.f, 0.f, 0.f, 0.f};
        if (lane < 25) {
            float4 bb4 = *(const float4*)&sb2[lane * 4];
            x[0] = bb4.x; x[1] = bb4.y; x[2] = bb4.z; x[3] = bb4.w;
            for (int k = 0; k < HD; k++) {
                float b = B0[k];
                float4 w = *(const float4*)&sw2[k * HD + lane * 4];
                x[0] = fmaf(b, w.x, x[0]);
                x[1] = fmaf(b, w.y, x[1]);
                x[2] = fmaf(b, w.z, x[2]);
                x[3] = fmaf(b, w.w, x[3]);
            }
        }
        float smv = x[0] + x[1] + x[2] + x[3];
        float sqv = x[0]*x[0] + x[1]*x[1] + x[2]*x[2] + x[3]*x[3];
        smv = wsum(smv); sqv = wsum(sqv);
        float mean = smv * (1.f / HD);
        float rs = rsqrtf(sqv * (1.f / HD) - mean * mean + LN_EPS);
        if (lane < 25) {
            float4 o;
            o.x = geluf((x[0] - mean) * rs);
            o.y = geluf((x[1] - mean) * rs);
            o.z = geluf((x[2] - mean) * rs);
            o.w = geluf((x[3] - mean) * rs);
            *(float4*)&B1[lane * 4] = o;
        }
        __syncwarp();

        if (lane < ZD) {
            float mu = sbmu[lane], lv = sblv[lane];
            for (int k = 0; k < HD; k++) {
                float h = B1[k];
                mu += h * swmu[k * ZD + lane];
                lv += h * swlv[k * ZD + lane];
            }
            float sc = softplusf(lv);
            float z = mu + sc * eps_z[(size_t)r * ZD + lane];
            o_z  [(size_t)r * ZD + lane] = z;
            o_muz[(size_t)r * ZD + lane] = mu;
            o_scz[(size_t)r * ZD + lane] = sc;
            B0[lane] = z;
        }
        __syncwarp();

        x[0] = x[1] = x[2] = x[3] = 0.f;
        if (lane < 25) {
            float4 bb4 = *(const float4*)&sedb1[lane * 4];
            x[0] = bb4.x; x[1] = bb4.y; x[2] = bb4.z; x[3] = bb4.w;
            for (int k = 0; k < ZD; k++) {
                float b = B0[k];
                float4 w = *(const float4*)&sedw1[k * HD + lane * 4];
                x[0] = fmaf(b, w.x, x[0]);
                x[1] = fmaf(b, w.y, x[1]);
                x[2] = fmaf(b, w.z, x[2]);
                x[3] = fmaf(b, w.w, x[3]);
            }
        }
        smv = x[0] + x[1] + x[2] + x[3];
        sqv = x[0]*x[0] + x[1]*x[1] + x[2]*x[2] + x[3]*x[3];
        smv = wsum(smv); sqv = wsum(sqv);
        mean = smv * (1.f / HD);
        rs = rsqrtf(sqv * (1.f / HD) - mean * mean + LN_EPS);
        if (lane < 25) {
            float4 o;
            o.x = geluf((x[0] - mean) * rs);
            o.y = geluf((x[1] - mean) * rs);
            o.z = geluf((x[2] - mean) * rs);
            o.w = geluf((x[3] - mean) * rs);
            *(float4*)&B1[lane * 4] = o;
        }
        __syncwarp();

        if (lane < ZD) {
            float mu = sedbmu[lane], lv = sedblv[lane];
            for (int k = 0; k < HD; k++) {
                float h = B1[k];
                mu += h * sedwmu[k * ZD + lane];
                lv += h * sedwlv[k * ZD + lane];
            }
            float sc = softplusf(lv);
            float dz = mu + sc * eps_d[(size_t)r * ZD + lane];
            o_dz [(size_t)r * ZD + lane] = dz;
            o_mud[(size_t)r * ZD + lane] = mu;
            o_scd[(size_t)r * ZD + lane] = sc;
            B0[32 + lane] = dz;
        }
        __syncwarp();

        float a[4] = {0.f,0.f,0.f,0.f}, t[4] = {0.f,0.f,0.f,0.f};
        if (lane < 25) {
            float4 bb4 = *(const float4*)&sdzb1[lane * 4];
            a[0] = bb4.x; a[1] = bb4.y; a[2] = bb4.z; a[3] = bb4.w;
            for (int k = 0; k < ZD; k++) {
                float zz = B0[k];
                float dd = B0[32 + k];
                float4 w = *(const float4*)&sdzw1[k * HD + lane * 4];
                a[0] = fmaf(zz, w.x, a[0]); t[0] = fmaf(dd, w.x, t[0]);
                a[1] = fmaf(zz, w.y, a[1]); t[1] = fmaf(dd, w.y, t[1]);
                a[2] = fmaf(zz, w.z, a[2]); t[2] = fmaf(dd, w.z, t[2]);
                a[3] = fmaf(zz, w.w, a[3]); t[3] = fmaf(dd, w.w, t[3]);
            }
        }
        float sa = a[0]+a[1]+a[2]+a[3];
        float saa = a[0]*a[0]+a[1]*a[1]+a[2]*a[2]+a[3]*a[3];
        float st = t[0]+t[1]+t[2]+t[3];
        float sat = a[0]*t[0]+a[1]*t[1]+a[2]*t[2]+a[3]*t[3];
        sa = wsum(sa); saa = wsum(saa); st = wsum(st); sat = wsum(sat);
        float m  = sa * (1.f / HD);
        float v  = saa * (1.f / HD) - m * m;
        float r2 = rsqrtf(v + LN_EPS);
        float dm = st * (1.f / HD);
        float dv = 2.f * (sat * (1.f / HD) - m * dm);
        if (lane < 25) {
            float4 oh, ot;
            float y, dy, Phi, phi;
#pragma unroll
            for (int j = 0; j < 4; j++) {
                y  = (a[j] - m) * r2;
                dy = r2 * (t[j] - dm) - 0.5f * y * r2 * r2 * dv;
                Phi = 0.5f * (1.f + erff(y * 0.70710678118654752f));
                phi = 0.3989422804014327f * expf(-0.5f * y * y);
                ((float*)&oh)[j] = y * Phi;
                ((float*)&ot)[j] = (Phi + y * phi) * dy;
            }
            *(float4*)&g_h1g[(size_t)r * HD + lane * 4] = oh;
            *(float4*)&g_th [(size_t)r * HD + lane * 4] = ot;
        }
        __syncwarp();
    }
}

// ---------------- k3: mma.sync bf16-split GEMM (H@W and T@W fused) ------------
#define RS3 60
#define TW3 (64*RS3)           // words per tile = 3840
#define OAHI 0
#define OALO (1*TW3)
#define OTHI (2*TW3)
#define OTLO (3*TW3)
#define OBHI (4*TW3)
#define OBLO (5*TW3)
#define K3_SMEM_BYTES (6*TW3*4)   // 92160

__global__ void __launch_bounds__(256, 2) k3_mma(
    const float* __restrict__ w2, const float* __restrict__ b2)
{
    extern __shared__ uint32_t smu[];
    int tid = threadIdx.x, wid = tid >> 5, lane = tid & 31;
    int m0 = blockIdx.x * 64;

    // ---- stage A tiles once (zero-pad k-words 50..55) ----
    for (int lin = tid; lin < 64 * 56; lin += 256) {
        int row = lin / 56, w = lin - row * 56;
        float2 h2 = make_float2(0.f, 0.f), t2 = h2;
        if (w < 50) {
            h2 = *(const float2*)&g_h1g[(size_t)(m0 + row) * HD + 2 * w];
            t2 = *(const float2*)&g_th [(size_t)(m0 + row) * HD + 2 * w];
        }
        uint32_t hh, hl, th, tl;
        bfsplit2(h2, hh, hl);
        bfsplit2(t2, th, tl);
        int o = row * RS3 + w;
        smu[OAHI + o] = hh;
        smu[OALO + o] = hl;
        smu[OTHI + o] = th;
        smu[OTLO + o] = tl;
    }

    int g = lane >> 2, tg = lane & 3;
    int mrow = (wid & 3) * 16;
    int nb = (wid >> 2) * 32;
    int arow0 = (mrow + g) * RS3;
    int arow1 = (mrow + 8 + g) * RS3;

    for (int ch = 0; ch < 32; ch++) {
        int n0 = ch * 64;
        // ---- stage W chunk: [n][k-word] hi/lo, zero pad ----
        for (int lin = tid; lin < 64 * 56; lin += 256) {
            int w = lin >> 6, n = lin & 63;
            int col = n0 + n;
            float2 wv = make_float2(0.f, 0.f);
            if (w < 50 && col < XD) {
                wv.x = w2[(size_t)(2 * w) * XD + col];
                wv.y = w2[(size_t)(2 * w + 1) * XD + col];
            }
            uint32_t whi, wlo;
            bfsplit2(wv, whi, wlo);
            smu[OBHI + n * RS3 + w] = whi;
            smu[OBLO + n * RS3 + w] = wlo;
        }
        __syncthreads();

        float dH[4][4], dT[4][4];
#pragma unroll
        for (int j = 0; j < 4; j++)
#pragma unroll
            for (int e = 0; e < 4; e++) { dH[j][e] = 0.f; dT[j][e] = 0.f; }

#pragma unroll
        for (int ks = 0; ks < 7; ks++) {
            int kw = ks * 8;
            uint32_t ah0 = smu[OAHI + arow0 + kw + tg];
            uint32_t ah1 = smu[OAHI + arow1 + kw + tg];
            uint32_t ah2 = smu[OAHI + arow0 + kw + 4 + tg];
            uint32_t ah3 = smu[OAHI + arow1 + kw + 4 + tg];
            uint32_t al0 = smu[OALO + arow0 + kw + tg];
            uint32_t al1 = smu[OALO + arow1 + kw + tg];
            uint32_t al2 = smu[OALO + arow0 + kw + 4 + tg];
            uint32_t al3 = smu[OALO + arow1 + kw + 4 + tg];
            uint32_t th0 = smu[OTHI + arow0 + kw + tg];
            uint32_t th1 = smu[OTHI + arow1 + kw + tg];
            uint32_t th2 = smu[OTHI + arow0 + kw + 4 + tg];
            uint32_t th3 = smu[OTHI + arow1 + kw + 4 + tg];
            uint32_t tl0 = smu[OTLO + arow0 + kw + tg];
            uint32_t tl1 = smu[OTLO + arow1 + kw + tg];
            uint32_t tl2 = smu[OTLO + arow0 + kw + 4 + tg];
            uint32_t tl3 = smu[OTLO + arow1 + kw + 4 + tg];
#pragma unroll
            for (int j = 0; j < 4; j++) {
                int brow = (nb + j * 8 + g) * RS3;
                uint32_t bh0 = smu[OBHI + brow + kw + tg];
                uint32_t bh1 = smu[OBHI + brow + kw + 4 + tg];
                uint32_t bl0 = smu[OBLO + brow + kw + tg];
                uint32_t bl1 = smu[OBLO + brow + kw + 4 + tg];
                MMA_BF16(dH[j], ah0, ah1, ah2, ah3, bh0, bh1);
                MMA_BF16(dH[j], ah0, ah1, ah2, ah3, bl0, bl1);
                MMA_BF16(dH[j], al0, al1, al2, al3, bh0, bh1);
                MMA_BF16(dT[j], th0, th1, th2, th3, bh0, bh1);
                MMA_BF16(dT[j], th0, th1, th2, th3, bl0, bl1);
                MMA_BF16(dT[j], tl0, tl1, tl2, tl3, bh0, bh1);
            }
        }
        __syncthreads();   // all B reads done before next chunk's staging

        // ---- epilogue: bias + softplus / sigmoid*tangent, store pairs ----
        int r0 = m0 + mrow + g;
        int r1 = r0 + 8;
#pragma unroll
        for (int j = 0; j < 4; j++) {
            int c0 = n0 + nb + j * 8 + 2 * tg;
            if (c0 < XD) {
                float bx = b2[c0], by = b2[c0 + 1];
                float a0 = dH[j][0] + bx, a1 = dH[j][1] + by;
                float a2 = dH[j][2] + bx, a3 = dH[j][3] + by;
                float2 l0, t0, l1, t1;
                l0.x = softplusf(a0); t0.x = sigmoidf(a0) * dT[j][0];
                l0.y = softplusf(a1); t0.y = sigmoidf(a1) * dT[j][1];
                l1.x = softplusf(a2); t1.x = sigmoidf(a2) * dT[j][2];
                l1.y = softplusf(a3); t1.y = sigmoidf(a3) * dT[j][3];
                *(float2*)&g_ld [(size_t)r0 * XD + c0] = l0;
                *(float2*)&g_tld[(size_t)r0 * XD + c0] = t0;
                *(float2*)&g_ld [(size_t)r1 * XD + c0] = l1;
                *(float2*)&g_tld[(size_t)r1 * XD + c0] = t1;
            }
        }
    }
}

// ---------------- k4: per-row sums + finalize ---------------------------------
__global__ void __launch_bounds__(256) k4_fin(
    float* __restrict__ o_shat, float* __restrict__ o_diff, float* __restrict__ o_pu)
{
    __shared__ float red[16];
    int r = blockIdx.x;
    int tid = threadIdx.x;

    float4 l[2], tl[2];
    float sl = 0.f, st = 0.f;
#pragma unroll
    for (int j = 0; j < 2; j++) {
        int c = (tid + j * 256) * 4;
        if (c < XD) {
            l [j] = *(const float4*)&g_ld [(size_t)r * XD + c];
            tl[j] = *(const float4*)&g_tld[(size_t)r * XD + c];
            sl += l [j].x + l [j].y + l [j].z + l [j].w;
            st += tl[j].x + tl[j].y + tl[j].z + tl[j].w;
        }
    }
    sl = wsum(sl); st = wsum(st);
    int wid = tid >> 5, lane = tid & 31;
    if (lane == 0) { red[wid] = sl; red[8 + wid] = st; }
    __syncthreads();
    sl = red[0]+red[1]+red[2]+red[3]+red[4]+red[5]+red[6]+red[7];
    st = red[8]+red[9]+red[10]+red[11]+red[12]+red[13]+red[14]+red[15];

    float m  = sl * (1.f / XD);
    float mt = st * (1.f / XD);
    float rm = 1.f / m;
    float cm = mt * rm * rm;

#pragma unroll
    for (int j = 0; j < 2; j++) {
        int c = (tid + j * 256) * 4;
        if (c < XD) {
            float4 be = *(const float4*)&g_beta[c];
            float4 ga = *(const float4*)&g_gamma[c];
            float4 sh, df, pu;
            sh.x = l[j].x * rm; df.x = 0.01f * (tl[j].x * rm - l[j].x * cm);
            sh.y = l[j].y * rm; df.y = 0.01f * (tl[j].y * rm - l[j].y * cm);
            sh.z = l[j].z * rm; df.z = 0.01f * (tl[j].z * rm - l[j].z * cm);
            sh.w = l[j].w * rm; df.w = 0.01f * (tl[j].w * rm - l[j].w * cm);
            pu.x = fmaxf((df.x + sh.x * ga.x) / be.x, 0.f);
            pu.y = fmaxf((df.y + sh.y * ga.y) / be.y, 0.f);
            pu.z = fmaxf((df.z + sh.z * ga.z) / be.z, 0.f);
            pu.w = fmaxf((df.w + sh.w * ga.w) / be.w, 0.f);
            *(float4*)&o_shat[(size_t)r * XD + c] = sh;
            *(float4*)&o_diff[(size_t)r * XD + c] = df;
            *(float4*)&o_pu  [(size_t)r * XD + c] = pu;
        }
    }
}

// ---------------- launcher ----------------------------------------------------
extern "C" void kernel_launch(void* const* d_in, const int* in_sizes, int n_in,
                              void* d_out, int out_size)
{
    const float* s      = (const float*)d_in[0];
    const float* u      = (const float*)d_in[1];
    const float* eps_z  = (const float*)d_in[2];
    const float* eps_d  = (const float*)d_in[3];
    const float* ez_w1  = (const float*)d_in[4];
    const float* ez_b1  = (const float*)d_in[5];
    const float* ez_w2  = (const float*)d_in[6];
    const float* ez_b2  = (const float*)d_in[7];
    const float* ez_wmu = (const float*)d_in[8];
    const float* ez_bmu = (const float*)d_in[9];
    const float* ez_wlv = (const float*)d_in[10];
    const float* ez_blv = (const float*)d_in[11];
    const float* ed_w1  = (const float*)d_in[12];
    const float* ed_b1  = (const float*)d_in[13];
    const float* ed_wmu = (const float*)d_in[14];
    const float* ed_bmu = (const float*)d_in[15];
    const float* ed_wlv = (const float*)d_in[16];
    const float* ed_blv = (const float*)d_in[17];
    const float* dz_w1  = (const float*)d_in[18];
    const float* dz_b1  = (const float*)d_in[19];
    const float* dz_w2  = (const float*)d_in[20];
    const float* dz_b2  = (const float*)d_in[21];
    const float* logb   = (const float*)d_in[22];
    const float* logg   = (const float*)d_in[23];

    float* out = (float*)d_out;
    float* o_z    = out;
    float* o_dz   = o_z    + (size_t)BB * ZD;
    float* o_muz  = o_dz   + (size_t)BB * ZD;
    float* o_scz  = o_muz  + (size_t)BB * ZD;
    float* o_mud  = o_scz  + (size_t)BB * ZD;
    float* o_scd  = o_mud  + (size_t)BB * ZD;
    float* o_shat = o_scd  + (size_t)BB * ZD;
    float* o_diff = o_shat + (size_t)BB * XD;
    float* o_pu   = o_diff + (size_t)BB * XD;

    const int smem2 = K2_SMEM_FLOATS * 4;
    cudaFuncSetAttribute(k1_mma, cudaFuncAttributeMaxDynamicSharedMemorySize, K1_SMEM_BYTES);
    cudaFuncSetAttribute(k2_mid, cudaFuncAttributeMaxDynamicSharedMemorySize, smem2);
    cudaFuncSetAttribute(k3_mma, cudaFuncAttributeMaxDynamicSharedMemorySize, K3_SMEM_BYTES);

    k0_rates<<<8, 256>>>(logb, logg);
    k0b_w1split<<<(112 * 2000 + 255) / 256, 256>>>(ez_w1);
    k1_mma<<<BB / 64, 256, K1_SMEM_BYTES>>>(s, u, ez_b1);
    k2_mid<<<512, 256, smem2>>>(eps_z, eps_d,
                                ez_w2, ez_b2, ez_wmu, ez_bmu, ez_wlv, ez_blv,
                                ed_w1, ed_b1, ed_wmu, ed_bmu, ed_wlv, ed_blv,
                                dz_w1, dz_b1,
                                o_z, o_dz, o_muz, o_scz, o_mud, o_scd);
    k3_mma<<<BB / 64, 256, K3_SMEM_BYTES>>>(dz_w2, dz_b2);
    k4_fin<<<BB, 256>>>(o_shat, o_diff, o_pu);
}

// round 9
// speedup vs baseline: 3.1536x; 1.0685x over previous
#include <cuda_runtime.h>
#include <cuda_bf16.h>
#include <math.h>
#include <stdint.h>

#define BB 16384
#define XD 2000
#define HD 100
#define ZD 20
#define KTOT (2*XD)      // 4000
#define LN_EPS 1e-5f

// ---------------- scratch (static device globals; no allocations) -------------
__device__ float g_h1 [(size_t)BB*HD];
__device__ float g_h1g[(size_t)BB*HD];
__device__ float g_th [(size_t)BB*HD];
__device__ float g_ld [(size_t)BB*XD];
__device__ float g_tld[(size_t)BB*XD];
__device__ float g_beta [XD];
__device__ float g_gamma[XD];
// W1 pre-transposed bf16 split: [n(128, rows >=100 zero)][kword(2000)]
__device__ uint32_t g_w1hi[128 * 2000];
__device__ uint32_t g_w1lo[128 * 2000];

// ---------------- helpers -----------------------------------------------------
__device__ __forceinline__ float softplusf(float x) {
    return fmaxf(x, 0.f) + log1pf(expf(-fabsf(x)));
}
__device__ __forceinline__ float sigmoidf(float x) {
    return 1.f / (1.f + expf(-x));
}
__device__ __forceinline__ float geluf(float x) {
    return 0.5f * x * (1.f + erff(x * 0.70710678118654752f));
}
__device__ __forceinline__ float wsum(float v) {
#pragma unroll
    for (int o = 16; o; o >>= 1) v += __shfl_xor_sync(0xffffffffu, v, o);
    return v;
}

// split fp32 pair -> bf16x2 hi + bf16x2 lo (lo = rounded residual); low half = .x
__device__ __forceinline__ void bfsplit2(float2 v, uint32_t& hi, uint32_t& lo) {
    asm("cvt.rn.bf16x2.f32 %0, %1, %2;" : "=r"(hi) : "f"(v.y), "f"(v.x));
    float hx = __uint_as_float(hi << 16);
    float hy = __uint_as_float(hi & 0xFFFF0000u);
    float rx = v.x - hx;
    float ry = v.y - hy;
    asm("cvt.rn.bf16x2.f32 %0, %1, %2;" : "=r"(lo) : "f"(ry), "f"(rx));
}

// m16n8k16 bf16 MMA, fp32 accumulate (legacy HMMA path, valid at compute_103)
#define MMA_BF16(d, a0, a1, a2, a3, b0, b1) \
    asm volatile("mma.sync.aligned.m16n8k16.row.col.f32.bf16.bf16.f32 " \
        "{%0,%1,%2,%3}, {%4,%5,%6,%7}, {%8,%9}, {%0,%1,%2,%3};" \
        : "+f"((d)[0]), "+f"((d)[1]), "+f"((d)[2]), "+f"((d)[3]) \
        : "r"(a0), "r"(a1), "r"(a2), "r"(a3), "r"(b0), "r"(b1))

// ---------------- k0: beta/gamma precompute ----------------------------------
__global__ void k0_rates(const float* __restrict__ lb, const float* __restrict__ lg) {
    int i = blockIdx.x * blockDim.x + threadIdx.x;
    if (i < XD) {
        g_beta[i]  = softplusf(lb[i]);   // * DT (=1)
        g_gamma[i] = softplusf(lg[i]);
    }
}

// ---------------- k0b: W1 -> transposed bf16 split (128 rows, zero pad) -------
__global__ void k0b_w1split(const float* __restrict__ w1) {
    int idx = blockIdx.x * 256 + threadIdx.x;
    if (idx >= 128 * 2000) return;
    int n = idx / 2000, kw = idx - n * 2000;
    float2 v = make_float2(0.f, 0.f);
    if (n < HD) {
        v.x = w1[(size_t)(2 * kw) * HD + n];
        v.y = w1[(size_t)(2 * kw + 1) * HD + n];
    }
    uint32_t hi, lo;
    bfsplit2(v, hi, lo);
    g_w1hi[idx] = hi;
    g_w1lo[idx] = lo;
}

// ---------------- k1: double-buffered mma.sync bf16-split -----------------------
// M-tile=32 (grid 512), N pad 128. 8 warps = 2 M x 4 N-quarters (m16 x n32).
// K chunks of 64 elem (32 kwords), 63 chunks. Double smem buffer + register
// prefetch: LDG(c+1) -> MMA(c) -> STS(c+1 -> buf^1) -> one sync.
#define K1RS 36
#define K1_AH(b) ((b)*11520)
#define K1_AL(b) ((b)*11520 + 1152)
#define K1_BH(b) ((b)*11520 + 2304)
#define K1_BL(b) ((b)*11520 + 6912)
#define K1_BLO_DELTA 4608
#define K1_SMEM_BYTES (23040 * 4)   // 92160

__global__ void __launch_bounds__(256, 2) k1_mma(
    const float* __restrict__ s, const float* __restrict__ u,
    const float* __restrict__ b1)
{
    extern __shared__ uint32_t smu[];
    int tid = threadIdx.x, wid = tid >> 5, lane = tid & 31;
    int m0 = blockIdx.x * 32;
    int g = lane >> 2, tg = lane & 3;
    int mwarp = wid & 1, nq = wid >> 1;

    // staging maps
    int aRow = tid >> 3, aW4 = (tid & 7) * 4;     // A: 32 rows x 8 quad-slots
    int bN[4], bG4[4];                             // B: 128 n x 8 quad-slots x4
#pragma unroll
    for (int i = 0; i < 4; i++) {
        int lin = tid + i * 256;
        bN[i]  = lin >> 3;
        bG4[i] = (lin & 7) * 4;
    }

    float4 aPre0, aPre1;
    uint4 bPreH[4], bPreL[4];

#define K1_LDG(kw0_) do {                                                     \
        int kw_ = (kw0_) + aW4;                                               \
        aPre0 = make_float4(0.f,0.f,0.f,0.f); aPre1 = aPre0;                  \
        if (kw_ < 1000) {                                                     \
            const float* p_ = &s[(size_t)(m0 + aRow) * XD + 2 * kw_];         \
            aPre0 = *(const float4*)p_; aPre1 = *(const float4*)(p_ + 4);     \
        } else if (kw_ < 2000) {                                              \
            const float* p_ = &u[(size_t)(m0 + aRow) * XD + 2 * kw_ - XD];    \
            aPre0 = *(const float4*)p_; aPre1 = *(const float4*)(p_ + 4);     \
        }                                                                     \
        _Pragma("unroll")                                                     \
        for (int i_ = 0; i_ < 4; i_++) {                                      \
            int kb_ = (kw0_) + bG4[i_];                                       \
            if (kb_ < 2000) {                                                 \
                bPreH[i_] = *(const uint4*)&g_w1hi[bN[i_] * 2000 + kb_];      \
                bPreL[i_] = *(const uint4*)&g_w1lo[bN[i_] * 2000 + kb_];      \
            } else {                                                          \
                bPreH[i_] = make_uint4(0u,0u,0u,0u); bPreL[i_] = bPreH[i_];   \
            }                                                                 \
        }                                                                     \
    } while (0)

#define K1_STS(buf_) do {                                                     \
        uint32_t h_[4], l_[4];                                                \
        bfsplit2(make_float2(aPre0.x, aPre0.y), h_[0], l_[0]);                \
        bfsplit2(make_float2(aPre0.z, aPre0.w), h_[1], l_[1]);                \
        bfsplit2(make_float2(aPre1.x, aPre1.y), h_[2], l_[2]);                \
        bfsplit2(make_float2(aPre1.z, aPre1.w), h_[3], l_[3]);                \
        *(uint4*)&smu[K1_AH(buf_) + aRow * K1RS + aW4] =                      \
            make_uint4(h_[0], h_[1], h_[2], h_[3]);                           \
        *(uint4*)&smu[K1_AL(buf_) + aRow * K1RS + aW4] =                      \
            make_uint4(l_[0], l_[1], l_[2], l_[3]);                           \
        _Pragma("unroll")                                                     \
        for (int i_ = 0; i_ < 4; i_++) {                                      \
            *(uint4*)&smu[K1_BH(buf_) + bN[i_] * K1RS + bG4[i_]] = bPreH[i_]; \
            *(uint4*)&smu[K1_BL(buf_) + bN[i_] * K1RS + bG4[i_]] = bPreL[i_]; \
        }                                                                     \
    } while (0)

    float dM[4][4], dL[4][4];
#pragma unroll
    for (int j = 0; j < 4; j++)
#pragma unroll
        for (int e = 0; e < 4; e++) { dM[j][e] = 0.f; dL[j][e] = 0.f; }

    // prologue
    K1_LDG(0);
    K1_STS(0);
    __syncthreads();

    int b = 0;
    for (int c = 0; c < 63; c++) {
        if (c < 62) K1_LDG((c + 1) * 32);

        int abH = K1_AH(b) + (mwarp * 16 + g) * K1RS;
        int abL = abH + 1152;   // AL - AH
#pragma unroll
        for (int ks = 0; ks < 4; ks++) {
            int kw = ks * 8 + tg;
            uint32_t ah0 = smu[abH + kw];
            uint32_t ah1 = smu[abH + 8 * K1RS + kw];
            uint32_t ah2 = smu[abH + kw + 4];
            uint32_t ah3 = smu[abH + 8 * K1RS + kw + 4];
            uint32_t al0 = smu[abL + kw];
            uint32_t al1 = smu[abL + 8 * K1RS + kw];
            uint32_t al2 = smu[abL + kw + 4];
            uint32_t al3 = smu[abL + 8 * K1RS + kw + 4];
#pragma unroll
            for (int j = 0; j < 4; j++) {
                int bb = K1_BH(b) + (nq * 32 + 8 * j + g) * K1RS + kw;
                uint32_t bh0 = smu[bb];
                uint32_t bh1 = smu[bb + 4];
                uint32_t bl0 = smu[bb + K1_BLO_DELTA];
                uint32_t bl1 = smu[bb + K1_BLO_DELTA + 4];
                MMA_BF16(dM[j], ah0, ah1, ah2, ah3, bh0, bh1);
                MMA_BF16(dM[j], ah0, ah1, ah2, ah3, bl0, bl1);
                MMA_BF16(dL[j], al0, al1, al2, al3, bh0, bh1);
            }
        }

        if (c < 62) K1_STS(b ^ 1);
        __syncthreads();
        b ^= 1;
    }

    // ---- epilogue: LN over N per row (4 quarters joined via smem) + GELU ----
    float* red = (float*)smu;    // [32 rows][4 quarters][2 {sum,sq}]
    int lr0 = mwarp * 16 + g;
    int lr1 = lr0 + 8;

    float s0 = 0.f, q0 = 0.f, s1 = 0.f, q1 = 0.f;
#pragma unroll
    for (int j = 0; j < 4; j++) {
        int col = nq * 32 + 8 * j + 2 * tg;
        if (col < HD) {
            float bx = b1[col], by = b1[col + 1];
            float x0 = dM[j][0] + dL[j][0] + bx;
            float x1 = dM[j][1] + dL[j][1] + by;
            float x2 = dM[j][2] + dL[j][2] + bx;
            float x3 = dM[j][3] + dL[j][3] + by;
            s0 += x0 + x1; q0 += x0 * x0 + x1 * x1;
            s1 += x2 + x3; q1 += x2 * x2 + x3 * x3;
        }
    }
#pragma unroll
    for (int o = 1; o <= 2; o <<= 1) {
        s0 += __shfl_xor_sync(0xffffffffu, s0, o);
        q0 += __shfl_xor_sync(0xffffffffu, q0, o);
        s1 += __shfl_xor_sync(0xffffffffu, s1, o);
        q1 += __shfl_xor_sync(0xffffffffu, q1, o);
    }
    if (tg == 0) {
        red[(lr0 * 4 + nq) * 2 + 0] = s0;
        red[(lr0 * 4 + nq) * 2 + 1] = q0;
        red[(lr1 * 4 + nq) * 2 + 0] = s1;
        red[(lr1 * 4 + nq) * 2 + 1] = q1;
    }
    __syncthreads();

    float sum0 = red[(lr0*4+0)*2] + red[(lr0*4+1)*2] + red[(lr0*4+2)*2] + red[(lr0*4+3)*2];
    float sq0  = red[(lr0*4+0)*2+1] + red[(lr0*4+1)*2+1] + red[(lr0*4+2)*2+1] + red[(lr0*4+3)*2+1];
    float sum1 = red[(lr1*4+0)*2] + red[(lr1*4+1)*2] + red[(lr1*4+2)*2] + red[(lr1*4+3)*2];
    float sq1  = red[(lr1*4+0)*2+1] + red[(lr1*4+1)*2+1] + red[(lr1*4+2)*2+1] + red[(lr1*4+3)*2+1];
    float mean0 = sum0 * (1.f / HD);
    float mean1 = sum1 * (1.f / HD);
    float rs0 = rsqrtf(sq0 * (1.f / HD) - mean0 * mean0 + LN_EPS);
    float rs1 = rsqrtf(sq1 * (1.f / HD) - mean1 * mean1 + LN_EPS);

    int r0 = m0 + lr0, r1 = m0 + lr1;
#pragma unroll
    for (int j = 0; j < 4; j++) {
        int col = nq * 32 + 8 * j + 2 * tg;
        if (col < HD) {
            float bx = b1[col], by = b1[col + 1];
            float2 o0, o1;
            o0.x = geluf((dM[j][0] + dL[j][0] + bx - mean0) * rs0);
            o0.y = geluf((dM[j][1] + dL[j][1] + by - mean0) * rs0);
            o1.x = geluf((dM[j][2] + dL[j][2] + bx - mean1) * rs1);
            o1.y = geluf((dM[j][3] + dL[j][3] + by - mean1) * rs1);
            *(float2*)&g_h1[(size_t)r0 * HD + col] = o0;
            *(float2*)&g_h1[(size_t)r1 * HD + col] = o1;
        }
    }
}

// ---------------- k2: everything small, one warp per row (R5 version) ---------
#define K2_SMEM_FLOATS (22380 + 8*264)
__global__ void __launch_bounds__(256) k2_mid(
    const float* __restrict__ eps_z, const float* __restrict__ eps_d,
    const float* __restrict__ w2, const float* __restrict__ b2,
    const float* __restrict__ wmu, const float* __restrict__ bmu,
    const float* __restrict__ wlv, const float* __restrict__ blv,
    const float* __restrict__ edw1, const float* __restrict__ edb1,
    const float* __restrict__ edwmu, const float* __restrict__ edbmu,
    const float* __restrict__ edwlv, const float* __restrict__ edblv,
    const float* __restrict__ dzw1, const float* __restrict__ dzb1,
    float* __restrict__ o_z, float* __restrict__ o_dz,
    float* __restrict__ o_muz, float* __restrict__ o_scz,
    float* __restrict__ o_mud, float* __restrict__ o_scd)
{
    extern __shared__ float sm2[];
    float* sw2    = sm2;              // 10000
    float* swmu   = sw2 + 10000;      // 2000
    float* swlv   = swmu + 2000;      // 2000
    float* sb2    = swlv + 2000;      // 100
    float* sbmu   = sb2 + 100;        // 20
    float* sblv   = sbmu + 20;        // 20
    float* sedw1  = sblv + 20;        // 2000
    float* sedb1  = sedw1 + 2000;     // 100
    float* sedwmu = sedb1 + 100;      // 2000
    float* sedbmu = sedwmu + 2000;    // 20
    float* sedwlv = sedbmu + 20;      // 2000
    float* sedblv = sedwlv + 2000;    // 20
    float* sdzw1  = sedblv + 20;      // 2000
    float* sdzb1  = sdzw1 + 2000;     // 100
    float* wbuf   = sdzb1 + 100;      // 8 warps * 264

    {
        int t = threadIdx.x, nt = blockDim.x;
        for (int i = t; i < 10000; i += nt) sw2[i] = w2[i];
        for (int i = t; i < 2000; i += nt) { swmu[i] = wmu[i]; swlv[i] = wlv[i]; }
        for (int i = t; i < 2000; i += nt) { sedw1[i] = edw1[i]; sdzw1[i] = dzw1[i]; }
        for (int i = t; i < 2000; i += nt) { sedwmu[i] = edwmu[i]; sedwlv[i] = edwlv[i]; }
        for (int i = t; i < 100; i += nt) { sb2[i] = b2[i]; sedb1[i] = edb1[i]; sdzb1[i] = dzb1[i]; }
        if (t < 20) { sbmu[t] = bmu[t]; sblv[t] = blv[t]; sedbmu[t] = edbmu[t]; sedblv[t] = edblv[t]; }
    }
    __syncthreads();

    int wid = threadIdx.x >> 5, lane = threadIdx.x & 31;
    float* B0 = wbuf + wid * 264;
    float* B1 = B0 + 132;
    int nwarps = gridDim.x * 8;

    for (int r = blockIdx.x * 8 + wid; r < BB; r += nwarps) {
        for (int i = lane; i < HD; i += 32) B0[i] = g_h1[(size_t)r * HD + i];
        __syncwarp();

        float x[4] = {0.f, 0.f, 0.f, 0.f};
        if (lane < 25) {
            float4 bb4 = *(const float4*)&sb2[lane * 4];
            x[0] = bb4.x; x[1] = bb4.y; x[2] = bb4.z; x[3] = bb4.w;
            for (int k = 0; k < HD; k++) {
                float b = B0[k];
                float4 w = *(const float4*)&sw2[k * HD + lane * 4];
                x[0] = fmaf(b, w.x, x[0]);
                x[1] = fmaf(b, w.y, x[1]);
                x[2] = fmaf(b, w.z, x[2]);
                x[3] = fmaf(b, w.w, x[3]);
            }
        }
        float smv = x[0] + x[1] + x[2] + x[3];
        float sqv = x[0]*x[0] + x[1]*x[1] + x[2]*x[2] + x[3]*x[3];
        smv = wsum(smv); sqv = wsum(sqv);
        float mean = smv * (1.f / HD);
        float rs = rsqrtf(sqv * (1.f / HD) - mean * mean + LN_EPS);
        if (lane < 25) {
            float4 o;
            o.x = geluf((x[0] - mean) * rs);
            o.y = geluf((x[1] - mean) * rs);
            o.z = geluf((x[2] - mean) * rs);
            o.w = geluf((x[3] - mean) * rs);
            *(float4*)&B1[lane * 4] = o;
        }
        __syncwarp();

        if (lane < ZD) {
            float mu = sbmu[lane], lv = sblv[lane];
            for (int k = 0; k < HD; k++) {
                float h = B1[k];
                mu += h * swmu[k * ZD + lane];
                lv += h * swlv[k * ZD + lane];
            }
            float sc = softplusf(lv);
            float z = mu + sc * eps_z[(size_t)r * ZD + lane];
            o_z  [(size_t)r * ZD + lane] = z;
            o_muz[(size_t)r * ZD + lane] = mu;
            o_scz[(size_t)r * ZD + lane] = sc;
            B0[lane] = z;
        }
        __syncwarp();

        x[0] = x[1] = x[2] = x[3] = 0.f;
        if (lane < 25) {
            float4 bb4 = *(const float4*)&sedb1[lane * 4];
            x[0] = bb4.x; x[1] = bb4.y; x[2] = bb4.z; x[3] = bb4.w;
            for (int k = 0; k < ZD; k++) {
                float b = B0[k];
                float4 w = *(const float4*)&sedw1[k * HD + lane * 4];
                x[0] = fmaf(b, w.x, x[0]);
                x[1] = fmaf(b, w.y, x[1]);
                x[2] = fmaf(b, w.z, x[2]);
                x[3] = fmaf(b, w.w, x[3]);
            }
        }
        smv = x[0] + x[1] + x[2] + x[3];
        sqv = x[0]*x[0] + x[1]*x[1] + x[2]*x[2] + x[3]*x[3];
        smv = wsum(smv); sqv = wsum(sqv);
        mean = smv * (1.f / HD);
        rs = rsqrtf(sqv * (1.f / HD) - mean * mean + LN_EPS);
        if (lane < 25) {
            float4 o;
            o.x = geluf((x[0] - mean) * rs);
            o.y = geluf((x[1] - mean) * rs);
            o.z = geluf((x[2] - mean) * rs);
            o.w = geluf((x[3] - mean) * rs);
            *(float4*)&B1[lane * 4] = o;
        }
        __syncwarp();

        if (lane < ZD) {
            float mu = sedbmu[lane], lv = sedblv[lane];
            for (int k = 0; k < HD; k++) {
                float h = B1[k];
                mu += h * sedwmu[k * ZD + lane];
                lv += h * sedwlv[k * ZD + lane];
            }
            float sc = softplusf(lv);
            float dz = mu + sc * eps_d[(size_t)r * ZD + lane];
            o_dz [(size_t)r * ZD + lane] = dz;
            o_mud[(size_t)r * ZD + lane] = mu;
            o_scd[(size_t)r * ZD + lane] = sc;
            B0[32 + lane] = dz;
        }
        __syncwarp();

        float a[4] = {0.f,0.f,0.f,0.f}, t[4] = {0.f,0.f,0.f,0.f};
        if (lane < 25) {
            float4 bb4 = *(const float4*)&sdzb1[lane * 4];
            a[0] = bb4.x; a[1] = bb4.y; a[2] = bb4.z; a[3] = bb4.w;
            for (int k = 0; k < ZD; k++) {
                float zz = B0[k];
                float dd = B0[32 + k];
                float4 w = *(const float4*)&sdzw1[k * HD + lane * 4];
                a[0] = fmaf(zz, w.x, a[0]); t[0] = fmaf(dd, w.x, t[0]);
                a[1] = fmaf(zz, w.y, a[1]); t[1] = fmaf(dd, w.y, t[1]);
                a[2] = fmaf(zz, w.z, a[2]); t[2] = fmaf(dd, w.z, t[2]);
                a[3] = fmaf(zz, w.w, a[3]); t[3] = fmaf(dd, w.w, t[3]);
            }
        }
        float sa = a[0]+a[1]+a[2]+a[3];
        float saa = a[0]*a[0]+a[1]*a[1]+a[2]*a[2]+a[3]*a[3];
        float st = t[0]+t[1]+t[2]+t[3];
        float sat = a[0]*t[0]+a[1]*t[1]+a[2]*t[2]+a[3]*t[3];
        sa = wsum(sa); saa = wsum(saa); st = wsum(st); sat = wsum(sat);
        float m  = sa * (1.f / HD);
        float v  = saa * (1.f / HD) - m * m;
        float r2 = rsqrtf(v + LN_EPS);
        float dm = st * (1.f / HD);
        float dv = 2.f * (sat * (1.f / HD) - m * dm);
        if (lane < 25) {
            float4 oh, ot;
            float y, dy, Phi, phi;
#pragma unroll
            for (int j = 0; j < 4; j++) {
                y  = (a[j] - m) * r2;
                dy = r2 * (t[j] - dm) - 0.5f * y * r2 * r2 * dv;
                Phi = 0.5f * (1.f + erff(y * 0.70710678118654752f));
                phi = 0.3989422804014327f * expf(-0.5f * y * y);
                ((float*)&oh)[j] = y * Phi;
                ((float*)&ot)[j] = (Phi + y * phi) * dy;
            }
            *(float4*)&g_h1g[(size_t)r * HD + lane * 4] = oh;
            *(float4*)&g_th [(size_t)r * HD + lane * 4] = ot;
        }
        __syncwarp();
    }
}

// ---------------- k3: mma.sync bf16-split GEMM (H@W and T@W fused) ------------
#define RS3 60
#define TW3 (64*RS3)           // words per tile = 3840
#define OAHI 0
#define OALO (1*TW3)
#define OTHI (2*TW3)
#define OTLO (3*TW3)
#define OBHI (4*TW3)
#define OBLO (5*TW3)
#define K3_SMEM_BYTES (6*TW3*4)   // 92160

__global__ void __launch_bounds__(256, 2) k3_mma(
    const float* __restrict__ w2, const float* __restrict__ b2)
{
    extern __shared__ uint32_t smu[];
    int tid = threadIdx.x, wid = tid >> 5, lane = tid & 31;
    int m0 = blockIdx.x * 64;

    // ---- stage A tiles once (zero-pad k-words 50..55) ----
    for (int lin = tid; lin < 64 * 56; lin += 256) {
        int row = lin / 56, w = lin - row * 56;
        float2 h2 = make_float2(0.f, 0.f), t2 = h2;
        if (w < 50) {
            h2 = *(const float2*)&g_h1g[(size_t)(m0 + row) * HD + 2 * w];
            t2 = *(const float2*)&g_th [(size_t)(m0 + row) * HD + 2 * w];
        }
        uint32_t hh, hl, th, tl;
        bfsplit2(h2, hh, hl);
        bfsplit2(t2, th, tl);
        int o = row * RS3 + w;
        smu[OAHI + o] = hh;
        smu[OALO + o] = hl;
        smu[OTHI + o] = th;
        smu[OTLO + o] = tl;
    }

    int g = lane >> 2, tg = lane & 3;
    int mrow = (wid & 3) * 16;
    int nb = (wid >> 2) * 32;
    int arow0 = (mrow + g) * RS3;
    int arow1 = (mrow + 8 + g) * RS3;

    for (int ch = 0; ch < 32; ch++) {
        int n0 = ch * 64;
        // ---- stage W chunk: [n][k-word] hi/lo, zero pad ----
        for (int lin = tid; lin < 64 * 56; lin += 256) {
            int w = lin >> 6, n = lin & 63;
            int col = n0 + n;
            float2 wv = make_float2(0.f, 0.f);
            if (w < 50 && col < XD) {
                wv.x = w2[(size_t)(2 * w) * XD + col];
                wv.y = w2[(size_t)(2 * w + 1) * XD + col];
            }
            uint32_t whi, wlo;
            bfsplit2(wv, whi, wlo);
            smu[OBHI + n * RS3 + w] = whi;
            smu[OBLO + n * RS3 + w] = wlo;
        }
        __syncthreads();

        float dH[4][4], dT[4][4];
#pragma unroll
        for (int j = 0; j < 4; j++)
#pragma unroll
            for (int e = 0; e < 4; e++) { dH[j][e] = 0.f; dT[j][e] = 0.f; }

#pragma unroll
        for (int ks = 0; ks < 7; ks++) {
            int kw = ks * 8;
            uint32_t ah0 = smu[OAHI + arow0 + kw + tg];
            uint32_t ah1 = smu[OAHI + arow1 + kw + tg];
            uint32_t ah2 = smu[OAHI + arow0 + kw + 4 + tg];
            uint32_t ah3 = smu[OAHI + arow1 + kw + 4 + tg];
            uint32_t al0 = smu[OALO + arow0 + kw + tg];
            uint32_t al1 = smu[OALO + arow1 + kw + tg];
            uint32_t al2 = smu[OALO + arow0 + kw + 4 + tg];
            uint32_t al3 = smu[OALO + arow1 + kw + 4 + tg];
            uint32_t th0 = smu[OTHI + arow0 + kw + tg];
            uint32_t th1 = smu[OTHI + arow1 + kw + tg];
            uint32_t th2 = smu[OTHI + arow0 + kw + 4 + tg];
            uint32_t th3 = smu[OTHI + arow1 + kw + 4 + tg];
            uint32_t tl0 = smu[OTLO + arow0 + kw + tg];
            uint32_t tl1 = smu[OTLO + arow1 + kw + tg];
            uint32_t tl2 = smu[OTLO + arow0 + kw + 4 + tg];
            uint32_t tl3 = smu[OTLO + arow1 + kw + 4 + tg];
#pragma unroll
            for (int j = 0; j < 4; j++) {
                int brow = (nb + j * 8 + g) * RS3;
                uint32_t bh0 = smu[OBHI + brow + kw + tg];
                uint32_t bh1 = smu[OBHI + brow + kw + 4 + tg];
                uint32_t bl0 = smu[OBLO + brow + kw + tg];
                uint32_t bl1 = smu[OBLO + brow + kw + 4 + tg];
                MMA_BF16(dH[j], ah0, ah1, ah2, ah3, bh0, bh1);
                MMA_BF16(dH[j], ah0, ah1, ah2, ah3, bl0, bl1);
                MMA_BF16(dH[j], al0, al1, al2, al3, bh0, bh1);
                MMA_BF16(dT[j], th0, th1, th2, th3, bh0, bh1);
                MMA_BF16(dT[j], th0, th1, th2, th3, bl0, bl1);
                MMA_BF16(dT[j], tl0, tl1, tl2, tl3, bh0, bh1);
            }
        }
        __syncthreads();   // all B reads done before next chunk's staging

        // ---- epilogue: bias + softplus / sigmoid*tangent, store pairs ----
        int r0 = m0 + mrow + g;
        int r1 = r0 + 8;
#pragma unroll
        for (int j = 0; j < 4; j++) {
            int c0 = n0 + nb + j * 8 + 2 * tg;
            if (c0 < XD) {
                float bx = b2[c0], by = b2[c0 + 1];
                float a0 = dH[j][0] + bx, a1 = dH[j][1] + by;
                float a2 = dH[j][2] + bx, a3 = dH[j][3] + by;
                float2 l0, t0, l1, t1;
                l0.x = softplusf(a0); t0.x = sigmoidf(a0) * dT[j][0];
                l0.y = softplusf(a1); t0.y = sigmoidf(a1) * dT[j][1];
                l1.x = softplusf(a2); t1.x = sigmoidf(a2) * dT[j][2];
                l1.y = softplusf(a3); t1.y = sigmoidf(a3) * dT[j][3];
                *(float2*)&g_ld [(size_t)r0 * XD + c0] = l0;
                *(float2*)&g_tld[(size_t)r0 * XD + c0] = t0;
                *(float2*)&g_ld [(size_t)r1 * XD + c0] = l1;
                *(float2*)&g_tld[(size_t)r1 * XD + c0] = t1;
            }
        }
    }
}

// ---------------- k4: per-row sums + finalize ---------------------------------
__global__ void __launch_bounds__(256) k4_fin(
    float* __restrict__ o_shat, float* __restrict__ o_diff, float* __restrict__ o_pu)
{
    __shared__ float red[16];
    int r = blockIdx.x;
    int tid = threadIdx.x;

    float4 l[2], tl[2];
    float sl = 0.f, st = 0.f;
#pragma unroll
    for (int j = 0; j < 2; j++) {
        int c = (tid + j * 256) * 4;
        if (c < XD) {
            l [j] = *(const float4*)&g_ld [(size_t)r * XD + c];
            tl[j] = *(const float4*)&g_tld[(size_t)r * XD + c];
            sl += l [j].x + l [j].y + l [j].z + l [j].w;
            st += tl[j].x + tl[j].y + tl[j].z + tl[j].w;
        }
    }
    sl = wsum(sl); st = wsum(st);
    int wid = tid >> 5, lane = tid & 31;
    if (lane == 0) { red[wid] = sl; red[8 + wid] = st; }
    __syncthreads();
    sl = red[0]+red[1]+red[2]+red[3]+red[4]+red[5]+red[6]+red[7];
    st = red[8]+red[9]+red[10]+red[11]+red[12]+red[13]+red[14]+red[15];

    float m  = sl * (1.f / XD);
    float mt = st * (1.f / XD);
    float rm = 1.f / m;
    float cm = mt * rm * rm;

#pragma unroll
    for (int j = 0; j < 2; j++) {
        int c = (tid + j * 256) * 4;
        if (c < XD) {
            float4 be = *(const float4*)&g_beta[c];
            float4 ga = *(const float4*)&g_gamma[c];
            float4 sh, df, pu;
            sh.x = l[j].x * rm; df.x = 0.01f * (tl[j].x * rm - l[j].x * cm);
            sh.y = l[j].y * rm; df.y = 0.01f * (tl[j].y * rm - l[j].y * cm);
            sh.z = l[j].z * rm; df.z = 0.01f * (tl[j].z * rm - l[j].z * cm);
            sh.w = l[j].w * rm; df.w = 0.01f * (tl[j].w * rm - l[j].w * cm);
            pu.x = fmaxf((df.x + sh.x * ga.x) / be.x, 0.f);
            pu.y = fmaxf((df.y + sh.y * ga.y) / be.y, 0.f);
            pu.z = fmaxf((df.z + sh.z * ga.z) / be.z, 0.f);
            pu.w = fmaxf((df.w + sh.w * ga.w) / be.w, 0.f);
            *(float4*)&o_shat[(size_t)r * XD + c] = sh;
            *(float4*)&o_diff[(size_t)r * XD + c] = df;
            *(float4*)&o_pu  [(size_t)r * XD + c] = pu;
        }
    }
}

// ---------------- launcher ----------------------------------------------------
extern "C" void kernel_launch(void* const* d_in, const int* in_sizes, int n_in,
                              void* d_out, int out_size)
{
    const float* s      = (const float*)d_in[0];
    const float* u      = (const float*)d_in[1];
    const float* eps_z  = (const float*)d_in[2];
    const float* eps_d  = (const float*)d_in[3];
    const float* ez_w1  = (const float*)d_in[4];
    const float* ez_b1  = (const float*)d_in[5];
    const float* ez_w2  = (const float*)d_in[6];
    const float* ez_b2  = (const float*)d_in[7];
    const float* ez_wmu = (const float*)d_in[8];
    const float* ez_bmu = (const float*)d_in[9];
    const float* ez_wlv = (const float*)d_in[10];
    const float* ez_blv = (const float*)d_in[11];
    const float* ed_w1  = (const float*)d_in[12];
    const float* ed_b1  = (const float*)d_in[13];
    const float* ed_wmu = (const float*)d_in[14];
    const float* ed_bmu = (const float*)d_in[15];
    const float* ed_wlv = (const float*)d_in[16];
    const float* ed_blv = (const float*)d_in[17];
    const float* dz_w1  = (const float*)d_in[18];
    const float* dz_b1  = (const float*)d_in[19];
    const float* dz_w2  = (const float*)d_in[20];
    const float* dz_b2  = (const float*)d_in[21];
    const float* logb   = (const float*)d_in[22];
    const float* logg   = (const float*)d_in[23];

    float* out = (float*)d_out;
    float* o_z    = out;
    float* o_dz   = o_z    + (size_t)BB * ZD;
    float* o_muz  = o_dz   + (size_t)BB * ZD;
    float* o_scz  = o_muz  + (size_t)BB * ZD;
    float* o_mud  = o_scz  + (size_t)BB * ZD;
    float* o_scd  = o_mud  + (size_t)BB * ZD;
    float* o_shat = o_scd  + (size_t)BB * ZD;
    float* o_diff = o_shat + (size_t)BB * XD;
    float* o_pu   = o_diff + (size_t)BB * XD;

    const int smem2 = K2_SMEM_FLOATS * 4;
    cudaFuncSetAttribute(k1_mma, cudaFuncAttributeMaxDynamicSharedMemorySize, K1_SMEM_BYTES);
    cudaFuncSetAttribute(k2_mid, cudaFuncAttributeMaxDynamicSharedMemorySize, smem2);
    cudaFuncSetAttribute(k3_mma, cudaFuncAttributeMaxDynamicSharedMemorySize, K3_SMEM_BYTES);

    k0_rates<<<8, 256>>>(logb, logg);
    k0b_w1split<<<(128 * 2000 + 255) / 256, 256>>>(ez_w1);
    k1_mma<<<BB / 32, 256, K1_SMEM_BYTES>>>(s, u, ez_b1);
    k2_mid<<<512, 256, smem2>>>(eps_z, eps_d,
                                ez_w2, ez_b2, ez_wmu, ez_bmu, ez_wlv, ez_blv,
                                ed_w1, ed_b1, ed_wmu, ed_bmu, ed_wlv, ed_blv,
                                dz_w1, dz_b1,
                                o_z, o_dz, o_muz, o_scz, o_mud, o_scd);
    k3_mma<<<BB / 64, 256, K3_SMEM_BYTES>>>(dz_w2, dz_b2);
    k4_fin<<<BB, 256>>>(o_shat, o_diff, o_pu);
}

// round 10
// speedup vs baseline: 3.4852x; 1.1051x over previous
#include <cuda_runtime.h>
#include <cuda_bf16.h>
#include <math.h>
#include <stdint.h>

#define BB 16384
#define XD 2000
#define HD 100
#define ZD 20
#define KTOT (2*XD)      // 4000
#define LN_EPS 1e-5f

// ---------------- scratch (static device globals; no allocations) -------------
__device__ float g_h1 [(size_t)BB*HD];
__device__ float g_h1g[(size_t)BB*HD];
__device__ float g_th [(size_t)BB*HD];
__device__ float g_ld [(size_t)BB*XD];
__device__ float g_tld[(size_t)BB*XD];
__device__ float g_beta [XD];
__device__ float g_gamma[XD];
// W1 pre-transposed bf16 split: [n(128, rows >=100 zero)][kword(2000)]
__device__ uint32_t g_w1hi[128 * 2000];
__device__ uint32_t g_w1lo[128 * 2000];
// W2 pre-transposed bf16 split: [n(2048, cols >=2000 zero)][kword(56, >=50 zero)]
__device__ uint32_t g_w2hi[2048 * 56];
__device__ uint32_t g_w2lo[2048 * 56];

// ---------------- helpers -----------------------------------------------------
__device__ __forceinline__ float softplusf(float x) {
    return fmaxf(x, 0.f) + log1pf(expf(-fabsf(x)));
}
__device__ __forceinline__ float sigmoidf(float x) {
    return 1.f / (1.f + expf(-x));
}
__device__ __forceinline__ float geluf(float x) {
    return 0.5f * x * (1.f + erff(x * 0.70710678118654752f));
}
__device__ __forceinline__ float wsum(float v) {
#pragma unroll
    for (int o = 16; o; o >>= 1) v += __shfl_xor_sync(0xffffffffu, v, o);
    return v;
}

// split fp32 pair -> bf16x2 hi + bf16x2 lo (lo = rounded residual); low half = .x
__device__ __forceinline__ void bfsplit2(float2 v, uint32_t& hi, uint32_t& lo) {
    asm("cvt.rn.bf16x2.f32 %0, %1, %2;" : "=r"(hi) : "f"(v.y), "f"(v.x));
    float hx = __uint_as_float(hi << 16);
    float hy = __uint_as_float(hi & 0xFFFF0000u);
    float rx = v.x - hx;
    float ry = v.y - hy;
    asm("cvt.rn.bf16x2.f32 %0, %1, %2;" : "=r"(lo) : "f"(ry), "f"(rx));
}

// m16n8k16 bf16 MMA, fp32 accumulate (legacy HMMA path, valid at compute_103)
#define MMA_BF16(d, a0, a1, a2, a3, b0, b1) \
    asm volatile("mma.sync.aligned.m16n8k16.row.col.f32.bf16.bf16.f32 " \
        "{%0,%1,%2,%3}, {%4,%5,%6,%7}, {%8,%9}, {%0,%1,%2,%3};" \
        : "+f"((d)[0]), "+f"((d)[1]), "+f"((d)[2]), "+f"((d)[3]) \
        : "r"(a0), "r"(a1), "r"(a2), "r"(a3), "r"(b0), "r"(b1))

// ---------------- k0: beta/gamma precompute ----------------------------------
__global__ void k0_rates(const float* __restrict__ lb, const float* __restrict__ lg) {
    int i = blockIdx.x * blockDim.x + threadIdx.x;
    if (i < XD) {
        g_beta[i]  = softplusf(lb[i]);   // * DT (=1)
        g_gamma[i] = softplusf(lg[i]);
    }
}

// ---------------- k0b: W1 -> transposed bf16 split (128 rows, zero pad) -------
__global__ void k0b_w1split(const float* __restrict__ w1) {
    int idx = blockIdx.x * 256 + threadIdx.x;
    if (idx >= 128 * 2000) return;
    int n = idx / 2000, kw = idx - n * 2000;
    float2 v = make_float2(0.f, 0.f);
    if (n < HD) {
        v.x = w1[(size_t)(2 * kw) * HD + n];
        v.y = w1[(size_t)(2 * kw + 1) * HD + n];
    }
    uint32_t hi, lo;
    bfsplit2(v, hi, lo);
    g_w1hi[idx] = hi;
    g_w1lo[idx] = lo;
}

// ---------------- k0c: W2 -> transposed bf16 split (2048 x 56, zero pad) ------
__global__ void k0c_w2split(const float* __restrict__ w2) {
    int idx = blockIdx.x * 256 + threadIdx.x;
    if (idx >= 2048 * 56) return;
    int n = idx / 56, w = idx - n * 56;
    float2 v = make_float2(0.f, 0.f);
    if (n < XD && w < 50) {
        v.x = w2[(size_t)(2 * w) * XD + n];
        v.y = w2[(size_t)(2 * w + 1) * XD + n];
    }
    uint32_t hi, lo;
    bfsplit2(v, hi, lo);
    g_w2hi[idx] = hi;
    g_w2lo[idx] = lo;
}

// ---------------- k1: double-buffered mma.sync bf16-split, M-tile 64 ----------
// grid 256, N pad 128. 8 warps = 4 M-groups x 2 N-halves (m16 x n64 each).
// K chunks of 64 elem (32 kwords), 63 chunks. Double buffer + register prefetch.
#define K1RS 36
#define K1BUF 13824                 // words per buffer
#define K1_AHo 0
#define K1_ALo 2304
#define K1_BHo 4608
#define K1_BLo 9216
#define K1_SMEM_BYTES (2 * K1BUF * 4)   // 110592

__global__ void __launch_bounds__(256, 1) k1_mma(
    const float* __restrict__ s, const float* __restrict__ u,
    const float* __restrict__ b1)
{
    extern __shared__ uint32_t smu[];
    int tid = threadIdx.x, wid = tid >> 5, lane = tid & 31;
    int m0 = blockIdx.x * 64;
    int g = lane >> 2, tg = lane & 3;
    int mwarp = wid & 3, nh = wid >> 2;

    // staging maps: A 64 rows x 8 quad-slots -> 2/thread; B 128 n x 8 -> 4/thread
    int aRow[2], aW4[2];
#pragma unroll
    for (int t = 0; t < 2; t++) {
        int lin = tid + t * 256;
        aRow[t] = lin >> 3;
        aW4 [t] = (lin & 7) * 4;
    }
    int bN[4], bG4[4];
#pragma unroll
    for (int i = 0; i < 4; i++) {
        int lin = tid + i * 256;
        bN[i]  = lin >> 3;
        bG4[i] = (lin & 7) * 4;
    }

    float4 aP0[2], aP1[2];
    uint4 bPH[4], bPL[4];

#define K1_LDG(kw0_) do {                                                       \
        _Pragma("unroll")                                                       \
        for (int t_ = 0; t_ < 2; t_++) {                                        \
            int kw_ = (kw0_) + aW4[t_];                                         \
            aP0[t_] = make_float4(0.f,0.f,0.f,0.f); aP1[t_] = aP0[t_];          \
            if (kw_ < 1000) {                                                   \
                const float* p_ = &s[(size_t)(m0 + aRow[t_]) * XD + 2 * kw_];   \
                aP0[t_] = *(const float4*)p_; aP1[t_] = *(const float4*)(p_+4); \
            } else if (kw_ < 2000) {                                            \
                const float* p_ = &u[(size_t)(m0 + aRow[t_]) * XD + 2*kw_ - XD];\
                aP0[t_] = *(const float4*)p_; aP1[t_] = *(const float4*)(p_+4); \
            }                                                                   \
        }                                                                       \
        _Pragma("unroll")                                                       \
        for (int i_ = 0; i_ < 4; i_++) {                                        \
            int kb_ = (kw0_) + bG4[i_];                                         \
            if (kb_ < 2000) {                                                   \
                bPH[i_] = *(const uint4*)&g_w1hi[bN[i_] * 2000 + kb_];          \
                bPL[i_] = *(const uint4*)&g_w1lo[bN[i_] * 2000 + kb_];          \
            } else {                                                            \
                bPH[i_] = make_uint4(0u,0u,0u,0u); bPL[i_] = bPH[i_];           \
            }                                                                   \
        }                                                                       \
    } while (0)

#define K1_STS(b_) do {                                                         \
        _Pragma("unroll")                                                       \
        for (int t_ = 0; t_ < 2; t_++) {                                        \
            uint32_t h_[4], l_[4];                                              \
            bfsplit2(make_float2(aP0[t_].x, aP0[t_].y), h_[0], l_[0]);          \
            bfsplit2(make_float2(aP0[t_].z, aP0[t_].w), h_[1], l_[1]);          \
            bfsplit2(make_float2(aP1[t_].x, aP1[t_].y), h_[2], l_[2]);          \
            bfsplit2(make_float2(aP1[t_].z, aP1[t_].w), h_[3], l_[3]);          \
            *(uint4*)&smu[(b_)*K1BUF + K1_AHo + aRow[t_]*K1RS + aW4[t_]] =      \
                make_uint4(h_[0], h_[1], h_[2], h_[3]);                         \
            *(uint4*)&smu[(b_)*K1BUF + K1_ALo + aRow[t_]*K1RS + aW4[t_]] =      \
                make_uint4(l_[0], l_[1], l_[2], l_[3]);                         \
        }                                                                       \
        _Pragma("unroll")                                                       \
        for (int i_ = 0; i_ < 4; i_++) {                                        \
            *(uint4*)&smu[(b_)*K1BUF + K1_BHo + bN[i_]*K1RS + bG4[i_]] = bPH[i_];\
            *(uint4*)&smu[(b_)*K1BUF + K1_BLo + bN[i_]*K1RS + bG4[i_]] = bPL[i_];\
        }                                                                       \
    } while (0)

    float dM[8][4], dL[8][4];
#pragma unroll
    for (int j = 0; j < 8; j++)
#pragma unroll
        for (int e = 0; e < 4; e++) { dM[j][e] = 0.f; dL[j][e] = 0.f; }

    K1_LDG(0);
    K1_STS(0);
    __syncthreads();

    int b = 0;
    for (int c = 0; c < 63; c++) {
        if (c < 62) K1_LDG((c + 1) * 32);

        int abH = b * K1BUF + K1_AHo + (mwarp * 16 + g) * K1RS;
        int abL = abH + (K1_ALo - K1_AHo);
#pragma unroll
        for (int ks = 0; ks < 4; ks++) {
            int kw = ks * 8 + tg;
            uint32_t ah0 = smu[abH + kw];
            uint32_t ah1 = smu[abH + 8 * K1RS + kw];
            uint32_t ah2 = smu[abH + kw + 4];
            uint32_t ah3 = smu[abH + 8 * K1RS + kw + 4];
            uint32_t al0 = smu[abL + kw];
            uint32_t al1 = smu[abL + 8 * K1RS + kw];
            uint32_t al2 = smu[abL + kw + 4];
            uint32_t al3 = smu[abL + 8 * K1RS + kw + 4];
#pragma unroll
            for (int j = 0; j < 8; j++) {
                int bb = b * K1BUF + K1_BHo + (nh * 64 + 8 * j + g) * K1RS + kw;
                uint32_t bh0 = smu[bb];
                uint32_t bh1 = smu[bb + 4];
                uint32_t bl0 = smu[bb + (K1_BLo - K1_BHo)];
                uint32_t bl1 = smu[bb + (K1_BLo - K1_BHo) + 4];
                MMA_BF16(dM[j], ah0, ah1, ah2, ah3, bh0, bh1);
                MMA_BF16(dM[j], ah0, ah1, ah2, ah3, bl0, bl1);
                MMA_BF16(dL[j], al0, al1, al2, al3, bh0, bh1);
            }
        }

        if (c < 62) K1_STS(b ^ 1);
        __syncthreads();
        b ^= 1;
    }

    // ---- epilogue: LN over N per row (2 halves joined via smem) + GELU ----
    float* red = (float*)smu;    // [64 rows][2 halves][2 {sum,sq}]
    int lr0 = mwarp * 16 + g;
    int lr1 = lr0 + 8;

    float s0 = 0.f, q0 = 0.f, s1 = 0.f, q1 = 0.f;
#pragma unroll
    for (int j = 0; j < 8; j++) {
        int col = nh * 64 + 8 * j + 2 * tg;
        if (col < HD) {
            float bx = b1[col], by = b1[col + 1];
            float x0 = dM[j][0] + dL[j][0] + bx;
            float x1 = dM[j][1] + dL[j][1] + by;
            float x2 = dM[j][2] + dL[j][2] + bx;
            float x3 = dM[j][3] + dL[j][3] + by;
            s0 += x0 + x1; q0 += x0 * x0 + x1 * x1;
            s1 += x2 + x3; q1 += x2 * x2 + x3 * x3;
        }
    }
#pragma unroll
    for (int o = 1; o <= 2; o <<= 1) {
        s0 += __shfl_xor_sync(0xffffffffu, s0, o);
        q0 += __shfl_xor_sync(0xffffffffu, q0, o);
        s1 += __shfl_xor_sync(0xffffffffu, s1, o);
        q1 += __shfl_xor_sync(0xffffffffu, q1, o);
    }
    if (tg == 0) {
        red[(lr0 * 2 + nh) * 2 + 0] = s0;
        red[(lr0 * 2 + nh) * 2 + 1] = q0;
        red[(lr1 * 2 + nh) * 2 + 0] = s1;
        red[(lr1 * 2 + nh) * 2 + 1] = q1;
    }
    __syncthreads();

    float sum0 = red[(lr0*2+0)*2] + red[(lr0*2+1)*2];
    float sq0  = red[(lr0*2+0)*2+1] + red[(lr0*2+1)*2+1];
    float sum1 = red[(lr1*2+0)*2] + red[(lr1*2+1)*2];
    float sq1  = red[(lr1*2+0)*2+1] + red[(lr1*2+1)*2+1];
    float mean0 = sum0 * (1.f / HD);
    float mean1 = sum1 * (1.f / HD);
    float rs0 = rsqrtf(sq0 * (1.f / HD) - mean0 * mean0 + LN_EPS);
    float rs1 = rsqrtf(sq1 * (1.f / HD) - mean1 * mean1 + LN_EPS);

    int r0 = m0 + lr0, r1 = m0 + lr1;
#pragma unroll
    for (int j = 0; j < 8; j++) {
        int col = nh * 64 + 8 * j + 2 * tg;
        if (col < HD) {
            float bx = b1[col], by = b1[col + 1];
            float2 o0, o1;
            o0.x = geluf((dM[j][0] + dL[j][0] + bx - mean0) * rs0);
            o0.y = geluf((dM[j][1] + dL[j][1] + by - mean0) * rs0);
            o1.x = geluf((dM[j][2] + dL[j][2] + bx - mean1) * rs1);
            o1.y = geluf((dM[j][3] + dL[j][3] + by - mean1) * rs1);
            *(float2*)&g_h1[(size_t)r0 * HD + col] = o0;
            *(float2*)&g_h1[(size_t)r1 * HD + col] = o1;
        }
    }
}

// ---------------- k2: everything small, one warp per row ----------------------
#define K2_SMEM_FLOATS (22380 + 8*264)
__global__ void __launch_bounds__(256) k2_mid(
    const float* __restrict__ eps_z, const float* __restrict__ eps_d,
    const float* __restrict__ w2, const float* __restrict__ b2,
    const float* __restrict__ wmu, const float* __restrict__ bmu,
    const float* __restrict__ wlv, const float* __restrict__ blv,
    const float* __restrict__ edw1, const float* __restrict__ edb1,
    const float* __restrict__ edwmu, const float* __restrict__ edbmu,
    const float* __restrict__ edwlv, const float* __restrict__ edblv,
    const float* __restrict__ dzw1, const float* __restrict__ dzb1,
    float* __restrict__ o_z, float* __restrict__ o_dz,
    float* __restrict__ o_muz, float* __restrict__ o_scz,
    float* __restrict__ o_mud, float* __restrict__ o_scd)
{
    extern __shared__ float sm2[];
    float* sw2    = sm2;              // 10000
    float* swmu   = sw2 + 10000;      // 2000
    float* swlv   = swmu + 2000;      // 2000
    float* sb2    = swlv + 2000;      // 100
    float* sbmu   = sb2 + 100;        // 20
    float* sblv   = sbmu + 20;        // 20
    float* sedw1  = sblv + 20;        // 2000
    float* sedb1  = sedw1 + 2000;     // 100
    float* sedwmu = sedb1 + 100;      // 2000
    float* sedbmu = sedwmu + 2000;    // 20
    float* sedwlv = sedbmu + 20;      // 2000
    float* sedblv = sedwlv + 2000;    // 20
    float* sdzw1  = sedblv + 20;      // 2000
    float* sdzb1  = sdzw1 + 2000;     // 100
    float* wbuf   = sdzb1 + 100;      // 8 warps * 264

    {
        int t = threadIdx.x, nt = blockDim.x;
        for (int i = t; i < 10000; i += nt) sw2[i] = w2[i];
        for (int i = t; i < 2000; i += nt) { swmu[i] = wmu[i]; swlv[i] = wlv[i]; }
        for (int i = t; i < 2000; i += nt) { sedw1[i] = edw1[i]; sdzw1[i] = dzw1[i]; }
        for (int i = t; i < 2000; i += nt) { sedwmu[i] = edwmu[i]; sedwlv[i] = edwlv[i]; }
        for (int i = t; i < 100; i += nt) { sb2[i] = b2[i]; sedb1[i] = edb1[i]; sdzb1[i] = dzb1[i]; }
        if (t < 20) { sbmu[t] = bmu[t]; sblv[t] = blv[t]; sedbmu[t] = edbmu[t]; sedblv[t] = edblv[t]; }
    }
    __syncthreads();

    int wid = threadIdx.x >> 5, lane = threadIdx.x & 31;
    float* B0 = wbuf + wid * 264;
    float* B1 = B0 + 132;
    int nwarps = gridDim.x * 8;

    for (int r = blockIdx.x * 8 + wid; r < BB; r += nwarps) {
        for (int i = lane; i < HD; i += 32) B0[i] = g_h1[(size_t)r * HD + i];
        __syncwarp();

        float x[4] = {0.f, 0.f, 0.f, 0.f};
        if (lane < 25) {
            float4 bb4 = *(const float4*)&sb2[lane * 4];
            x[0] = bb4.x; x[1] = bb4.y; x[2] = bb4.z; x[3] = bb4.w;
            for (int k = 0; k < HD; k++) {
                float b = B0[k];
                float4 w = *(const float4*)&sw2[k * HD + lane * 4];
                x[0] = fmaf(b, w.x, x[0]);
                x[1] = fmaf(b, w.y, x[1]);
                x[2] = fmaf(b, w.z, x[2]);
                x[3] = fmaf(b, w.w, x[3]);
            }
        }
        float smv = x[0] + x[1] + x[2] + x[3];
        float sqv = x[0]*x[0] + x[1]*x[1] + x[2]*x[2] + x[3]*x[3];
        smv = wsum(smv); sqv = wsum(sqv);
        float mean = smv * (1.f / HD);
        float rs = rsqrtf(sqv * (1.f / HD) - mean * mean + LN_EPS);
        if (lane < 25) {
            float4 o;
            o.x = geluf((x[0] - mean) * rs);
            o.y = geluf((x[1] - mean) * rs);
            o.z = geluf((x[2] - mean) * rs);
            o.w = geluf((x[3] - mean) * rs);
            *(float4*)&B1[lane * 4] = o;
        }
        __syncwarp();

        if (lane < ZD) {
            float mu = sbmu[lane], lv = sblv[lane];
            for (int k = 0; k < HD; k++) {
                float h = B1[k];
                mu += h * swmu[k * ZD + lane];
                lv += h * swlv[k * ZD + lane];
            }
            float sc = softplusf(lv);
            float z = mu + sc * eps_z[(size_t)r * ZD + lane];
            o_z  [(size_t)r * ZD + lane] = z;
            o_muz[(size_t)r * ZD + lane] = mu;
            o_scz[(size_t)r * ZD + lane] = sc;
            B0[lane] = z;
        }
        __syncwarp();

        x[0] = x[1] = x[2] = x[3] = 0.f;
        if (lane < 25) {
            float4 bb4 = *(const float4*)&sedb1[lane * 4];
            x[0] = bb4.x; x[1] = bb4.y; x[2] = bb4.z; x[3] = bb4.w;
            for (int k = 0; k < ZD; k++) {
                float b = B0[k];
                float4 w = *(const float4*)&sedw1[k * HD + lane * 4];
                x[0] = fmaf(b, w.x, x[0]);
                x[1] = fmaf(b, w.y, x[1]);
                x[2] = fmaf(b, w.z, x[2]);
                x[3] = fmaf(b, w.w, x[3]);
            }
        }
        smv = x[0] + x[1] + x[2] + x[3];
        sqv = x[0]*x[0] + x[1]*x[1] + x[2]*x[2] + x[3]*x[3];
        smv = wsum(smv); sqv = wsum(sqv);
        mean = smv * (1.f / HD);
        rs = rsqrtf(sqv * (1.f / HD) - mean * mean + LN_EPS);
        if (lane < 25) {
            float4 o;
            o.x = geluf((x[0] - mean) * rs);
            o.y = geluf((x[1] - mean) * rs);
            o.z = geluf((x[2] - mean) * rs);
            o.w = geluf((x[3] - mean) * rs);
            *(float4*)&B1[lane * 4] = o;
        }
        __syncwarp();

        if (lane < ZD) {
            float mu = sedbmu[lane], lv = sedblv[lane];
            for (int k = 0; k < HD; k++) {
                float h = B1[k];
                mu += h * sedwmu[k * ZD + lane];
                lv += h * sedwlv[k * ZD + lane];
            }
            float sc = softplusf(lv);
            float dz = mu + sc * eps_d[(size_t)r * ZD + lane];
            o_dz [(size_t)r * ZD + lane] = dz;
            o_mud[(size_t)r * ZD + lane] = mu;
            o_scd[(size_t)r * ZD + lane] = sc;
            B0[32 + lane] = dz;
        }
        __syncwarp();

        float a[4] = {0.f,0.f,0.f,0.f}, t[4] = {0.f,0.f,0.f,0.f};
        if (lane < 25) {
            float4 bb4 = *(const float4*)&sdzb1[lane * 4];
            a[0] = bb4.x; a[1] = bb4.y; a[2] = bb4.z; a[3] = bb4.w;
            for (int k = 0; k < ZD; k++) {
                float zz = B0[k];
                float dd = B0[32 + k];
                float4 w = *(const float4*)&sdzw1[k * HD + lane * 4];
                a[0] = fmaf(zz, w.x, a[0]); t[0] = fmaf(dd, w.x, t[0]);
                a[1] = fmaf(zz, w.y, a[1]); t[1] = fmaf(dd, w.y, t[1]);
                a[2] = fmaf(zz, w.z, a[2]); t[2] = fmaf(dd, w.z, t[2]);
                a[3] = fmaf(zz, w.w, a[3]); t[3] = fmaf(dd, w.w, t[3]);
            }
        }
        float sa = a[0]+a[1]+a[2]+a[3];
        float saa = a[0]*a[0]+a[1]*a[1]+a[2]*a[2]+a[3]*a[3];
        float st = t[0]+t[1]+t[2]+t[3];
        float sat = a[0]*t[0]+a[1]*t[1]+a[2]*t[2]+a[3]*t[3];
        sa = wsum(sa); saa = wsum(saa); st = wsum(st); sat = wsum(sat);
        float m  = sa * (1.f / HD);
        float v  = saa * (1.f / HD) - m * m;
        float r2 = rsqrtf(v + LN_EPS);
        float dm = st * (1.f / HD);
        float dv = 2.f * (sat * (1.f / HD) - m * dm);
        if (lane < 25) {
            float4 oh, ot;
            float y, dy, Phi, phi;
#pragma unroll
            for (int j = 0; j < 4; j++) {
                y  = (a[j] - m) * r2;
                dy = r2 * (t[j] - dm) - 0.5f * y * r2 * r2 * dv;
                Phi = 0.5f * (1.f + erff(y * 0.70710678118654752f));
                phi = 0.3989422804014327f * expf(-0.5f * y * y);
                ((float*)&oh)[j] = y * Phi;
                ((float*)&ot)[j] = (Phi + y * phi) * dy;
            }
            *(float4*)&g_h1g[(size_t)r * HD + lane * 4] = oh;
            *(float4*)&g_th [(size_t)r * HD + lane * 4] = ot;
        }
        __syncwarp();
    }
}

// ---------------- k3: mma.sync bf16-split GEMM + fused finalize ---------------
#define RS3 60
#define TW3 (64*RS3)           // words per tile = 3840
#define OAHI 0
#define OALO (1*TW3)
#define OTHI (2*TW3)
#define OTLO (3*TW3)
#define OBHI (4*TW3)
#define OBLO (5*TW3)
#define K3_SMEM_BYTES (6*TW3*4)   // 92160

__global__ void __launch_bounds__(256, 2) k3_mma(
    const float* __restrict__ b2,
    float* __restrict__ o_shat, float* __restrict__ o_diff, float* __restrict__ o_pu)
{
    extern __shared__ uint32_t smu[];
    int tid = threadIdx.x, wid = tid >> 5, lane = tid & 31;
    int m0 = blockIdx.x * 64;

    // ---- stage A tiles once (zero-pad k-words 50..55) ----
    for (int lin = tid; lin < 64 * 56; lin += 256) {
        int row = lin / 56, w = lin - row * 56;
        float2 h2 = make_float2(0.f, 0.f), t2 = h2;
        if (w < 50) {
            h2 = *(const float2*)&g_h1g[(size_t)(m0 + row) * HD + 2 * w];
            t2 = *(const float2*)&g_th [(size_t)(m0 + row) * HD + 2 * w];
        }
        uint32_t hh, hl, th, tl;
        bfsplit2(h2, hh, hl);
        bfsplit2(t2, th, tl);
        int o = row * RS3 + w;
        smu[OAHI + o] = hh;
        smu[OALO + o] = hl;
        smu[OTHI + o] = th;
        smu[OTLO + o] = tl;
    }

    int g = lane >> 2, tg = lane & 3;
    int mrow = (wid & 3) * 16;
    int nbh = wid >> 2;             // 0/1
    int nb = nbh * 32;
    int arow0 = (mrow + g) * RS3;
    int arow1 = (mrow + 8 + g) * RS3;

    float sl0 = 0.f, st0 = 0.f, sl1 = 0.f, st1 = 0.f;   // fused row sums

    for (int ch = 0; ch < 32; ch++) {
        int n0 = ch * 64;
        // ---- stage W chunk: pure uint4 copy from precomputed split ----
        for (int lin = tid; lin < 64 * 14; lin += 256) {
            int n = lin / 14, w4 = (lin - n * 14) * 4;
            size_t src = (size_t)(n0 + n) * 56 + w4;
            *(uint4*)&smu[OBHI + n * RS3 + w4] = *(const uint4*)&g_w2hi[src];
            *(uint4*)&smu[OBLO + n * RS3 + w4] = *(const uint4*)&g_w2lo[src];
        }
        __syncthreads();

        float dH[4][4], dT[4][4];
#pragma unroll
        for (int j = 0; j < 4; j++)
#pragma unroll
            for (int e = 0; e < 4; e++) { dH[j][e] = 0.f; dT[j][e] = 0.f; }

#pragma unroll
        for (int ks = 0; ks < 7; ks++) {
            int kw = ks * 8;
            uint32_t ah0 = smu[OAHI + arow0 + kw + tg];
            uint32_t ah1 = smu[OAHI + arow1 + kw + tg];
            uint32_t ah2 = smu[OAHI + arow0 + kw + 4 + tg];
            uint32_t ah3 = smu[OAHI + arow1 + kw + 4 + tg];
            uint32_t al0 = smu[OALO + arow0 + kw + tg];
            uint32_t al1 = smu[OALO + arow1 + kw + tg];
            uint32_t al2 = smu[OALO + arow0 + kw + 4 + tg];
            uint32_t al3 = smu[OALO + arow1 + kw + 4 + tg];
            uint32_t th0 = smu[OTHI + arow0 + kw + tg];
            uint32_t th1 = smu[OTHI + arow1 + kw + tg];
            uint32_t th2 = smu[OTHI + arow0 + kw + 4 + tg];
            uint32_t th3 = smu[OTHI + arow1 + kw + 4 + tg];
            uint32_t tl0 = smu[OTLO + arow0 + kw + tg];
            uint32_t tl1 = smu[OTLO + arow1 + kw + tg];
            uint32_t tl2 = smu[OTLO + arow0 + kw + 4 + tg];
            uint32_t tl3 = smu[OTLO + arow1 + kw + 4 + tg];
#pragma unroll
            for (int j = 0; j < 4; j++) {
                int brow = (nb + j * 8 + g) * RS3;
                uint32_t bh0 = smu[OBHI + brow + kw + tg];
                uint32_t bh1 = smu[OBHI + brow + kw + 4 + tg];
                uint32_t bl0 = smu[OBLO + brow + kw + tg];
                uint32_t bl1 = smu[OBLO + brow + kw + 4 + tg];
                MMA_BF16(dH[j], ah0, ah1, ah2, ah3, bh0, bh1);
                MMA_BF16(dH[j], ah0, ah1, ah2, ah3, bl0, bl1);
                MMA_BF16(dH[j], al0, al1, al2, al3, bh0, bh1);
                MMA_BF16(dT[j], th0, th1, th2, th3, bh0, bh1);
                MMA_BF16(dT[j], th0, th1, th2, th3, bl0, bl1);
                MMA_BF16(dT[j], tl0, tl1, tl2, tl3, bh0, bh1);
            }
        }
        __syncthreads();   // all smem reads done before next chunk's staging

        // ---- epilogue: bias + softplus / sigmoid*tangent, store + accumulate --
        int r0 = m0 + mrow + g;
        int r1 = r0 + 8;
#pragma unroll
        for (int j = 0; j < 4; j++) {
            int c0 = n0 + nb + j * 8 + 2 * tg;
            if (c0 < XD) {
                float bx = b2[c0], by = b2[c0 + 1];
                float a0 = dH[j][0] + bx, a1 = dH[j][1] + by;
                float a2 = dH[j][2] + bx, a3 = dH[j][3] + by;
                float2 l0, t0, l1, t1;
                l0.x = softplusf(a0); t0.x = sigmoidf(a0) * dT[j][0];
                l0.y = softplusf(a1); t0.y = sigmoidf(a1) * dT[j][1];
                l1.x = softplusf(a2); t1.x = sigmoidf(a2) * dT[j][2];
                l1.y = softplusf(a3); t1.y = sigmoidf(a3) * dT[j][3];
                *(float2*)&g_ld [(size_t)r0 * XD + c0] = l0;
                *(float2*)&g_tld[(size_t)r0 * XD + c0] = t0;
                *(float2*)&g_ld [(size_t)r1 * XD + c0] = l1;
                *(float2*)&g_tld[(size_t)r1 * XD + c0] = t1;
                sl0 += l0.x + l0.y; st0 += t0.x + t0.y;
                sl1 += l1.x + l1.y; st1 += t1.x + t1.y;
            }
        }
    }

    // ---- fused k4: per-row mean normalize + outputs ----
#pragma unroll
    for (int o = 1; o <= 2; o <<= 1) {
        sl0 += __shfl_xor_sync(0xffffffffu, sl0, o);
        st0 += __shfl_xor_sync(0xffffffffu, st0, o);
        sl1 += __shfl_xor_sync(0xffffffffu, sl1, o);
        st1 += __shfl_xor_sync(0xffffffffu, st1, o);
    }
    float* redf = (float*)smu;          // [64 rows][2 nbh][2]
    float* rowst = redf + 256;          // [64 rows][2 {rm, cm}]
    if (tg == 0) {
        int rr0 = mrow + g, rr1 = rr0 + 8;
        redf[(rr0 * 2 + nbh) * 2 + 0] = sl0;
        redf[(rr0 * 2 + nbh) * 2 + 1] = st0;
        redf[(rr1 * 2 + nbh) * 2 + 0] = sl1;
        redf[(rr1 * 2 + nbh) * 2 + 1] = st1;
    }
    __syncthreads();
    for (int r = tid; r < 64; r += 256) {
        float sl = redf[(r * 2 + 0) * 2 + 0] + redf[(r * 2 + 1) * 2 + 0];
        float st = redf[(r * 2 + 0) * 2 + 1] + redf[(r * 2 + 1) * 2 + 1];
        float m  = sl * (1.f / XD);
        float mt = st * (1.f / XD);
        rowst[r * 2 + 0] = 1.f / m;
        rowst[r * 2 + 1] = mt / (m * m);
    }
    __syncthreads();

    for (int lin = tid; lin < 64 * 500; lin += 256) {
        int row = lin / 500;
        int c = (lin - row * 500) * 4;
        float rm = rowst[row * 2 + 0];
        float cm = rowst[row * 2 + 1];
        size_t off = (size_t)(m0 + row) * XD + c;
        float4 l  = *(const float4*)&g_ld [off];
        float4 tl = *(const float4*)&g_tld[off];
        float4 be = *(const float4*)&g_beta[c];
        float4 ga = *(const float4*)&g_gamma[c];
        float4 sh, df, pu;
        sh.x = l.x * rm; df.x = 0.01f * (tl.x * rm - l.x * cm);
        sh.y = l.y * rm; df.y = 0.01f * (tl.y * rm - l.y * cm);
        sh.z = l.z * rm; df.z = 0.01f * (tl.z * rm - l.z * cm);
        sh.w = l.w * rm; df.w = 0.01f * (tl.w * rm - l.w * cm);
        pu.x = fmaxf((df.x + sh.x * ga.x) / be.x, 0.f);
        pu.y = fmaxf((df.y + sh.y * ga.y) / be.y, 0.f);
        pu.z = fmaxf((df.z + sh.z * ga.z) / be.z, 0.f);
        pu.w = fmaxf((df.w + sh.w * ga.w) / be.w, 0.f);
        *(float4*)&o_shat[off] = sh;
        *(float4*)&o_diff[off] = df;
        *(float4*)&o_pu  [off] = pu;
    }
}

// ---------------- launcher ----------------------------------------------------
extern "C" void kernel_launch(void* const* d_in, const int* in_sizes, int n_in,
                              void* d_out, int out_size)
{
    const float* s      = (const float*)d_in[0];
    const float* u      = (const float*)d_in[1];
    const float* eps_z  = (const float*)d_in[2];
    const float* eps_d  = (const float*)d_in[3];
    const float* ez_w1  = (const float*)d_in[4];
    const float* ez_b1  = (const float*)d_in[5];
    const float* ez_w2  = (const float*)d_in[6];
    const float* ez_b2  = (const float*)d_in[7];
    const float* ez_wmu = (const float*)d_in[8];
    const float* ez_bmu = (const float*)d_in[9];
    const float* ez_wlv = (const float*)d_in[10];
    const float* ez_blv = (const float*)d_in[11];
    const float* ed_w1  = (const float*)d_in[12];
    const float* ed_b1  = (const float*)d_in[13];
    const float* ed_wmu = (const float*)d_in[14];
    const float* ed_bmu = (const float*)d_in[15];
    const float* ed_wlv = (const float*)d_in[16];
    const float* ed_blv = (const float*)d_in[17];
    const float* dz_w1  = (const float*)d_in[18];
    const float* dz_b1  = (const float*)d_in[19];
    const float* dz_w2  = (const float*)d_in[20];
    const float* dz_b2  = (const float*)d_in[21];
    const float* logb   = (const float*)d_in[22];
    const float* logg   = (const float*)d_in[23];

    float* out = (float*)d_out;
    float* o_z    = out;
    float* o_dz   = o_z    + (size_t)BB * ZD;
    float* o_muz  = o_dz   + (size_t)BB * ZD;
    float* o_scz  = o_muz  + (size_t)BB * ZD;
    float* o_mud  = o_scz  + (size_t)BB * ZD;
    float* o_scd  = o_mud  + (size_t)BB * ZD;
    float* o_shat = o_scd  + (size_t)BB * ZD;
    float* o_diff = o_shat + (size_t)BB * XD;
    float* o_pu   = o_diff + (size_t)BB * XD;

    const int smem2 = K2_SMEM_FLOATS * 4;
    cudaFuncSetAttribute(k1_mma, cudaFuncAttributeMaxDynamicSharedMemorySize, K1_SMEM_BYTES);
    cudaFuncSetAttribute(k2_mid, cudaFuncAttributeMaxDynamicSharedMemorySize, smem2);
    cudaFuncSetAttribute(k3_mma, cudaFuncAttributeMaxDynamicSharedMemorySize, K3_SMEM_BYTES);

    k0_rates<<<8, 256>>>(logb, logg);
    k0b_w1split<<<(128 * 2000 + 255) / 256, 256>>>(ez_w1);
    k0c_w2split<<<(2048 * 56 + 255) / 256, 256>>>(dz_w2);
    k1_mma<<<BB / 64, 256, K1_SMEM_BYTES>>>(s, u, ez_b1);
    k2_mid<<<512, 256, smem2>>>(eps_z, eps_d,
                                ez_w2, ez_b2, ez_wmu, ez_bmu, ez_wlv, ez_blv,
                                ed_w1, ed_b1, ed_wmu, ed_bmu, ed_wlv, ed_blv,
                                dz_w1, dz_b1,
                                o_z, o_dz, o_muz, o_scz, o_mud, o_scd);
    k3_mma<<<BB / 64, 256, K3_SMEM_BYTES>>>(dz_b2, o_shat, o_diff, o_pu);
}

// round 11
// speedup vs baseline: 3.4895x; 1.0012x over previous
#include <cuda_runtime.h>
#include <cuda_bf16.h>
#include <math.h>
#include <stdint.h>

#define BB 16384
#define XD 2000
#define HD 100
#define ZD 20
#define KTOT (2*XD)      // 4000
#define LN_EPS 1e-5f

// ---------------- scratch (static device globals; no allocations) -------------
__device__ float g_h1 [(size_t)BB*HD];
__device__ float g_h1g[(size_t)BB*HD];
__device__ float g_th [(size_t)BB*HD];
__device__ float g_ld [(size_t)BB*XD];
__device__ float g_tld[(size_t)BB*XD];
__device__ float g_beta [XD];
__device__ float g_gamma[XD];
// W1 pre-transposed bf16 split: [n(128, rows >=100 zero)][kword(2000)]
__device__ uint32_t g_w1hi[128 * 2000];
__device__ uint32_t g_w1lo[128 * 2000];
// W2 pre-transposed bf16 split: [n(2048, cols >=2000 zero)][kword(56, >=50 zero)]
__device__ uint32_t g_w2hi[2048 * 56];
__device__ uint32_t g_w2lo[2048 * 56];

// ---------------- helpers -----------------------------------------------------
__device__ __forceinline__ float softplusf(float x) {
    return fmaxf(x, 0.f) + log1pf(expf(-fabsf(x)));
}
__device__ __forceinline__ float sigmoidf(float x) {
    return 1.f / (1.f + expf(-x));
}
__device__ __forceinline__ float geluf(float x) {
    return 0.5f * x * (1.f + erff(x * 0.70710678118654752f));
}
__device__ __forceinline__ float wsum(float v) {
#pragma unroll
    for (int o = 16; o; o >>= 1) v += __shfl_xor_sync(0xffffffffu, v, o);
    return v;
}

// split fp32 pair -> bf16x2 hi + bf16x2 lo (lo = rounded residual); low half = .x
__device__ __forceinline__ void bfsplit2(float2 v, uint32_t& hi, uint32_t& lo) {
    asm("cvt.rn.bf16x2.f32 %0, %1, %2;" : "=r"(hi) : "f"(v.y), "f"(v.x));
    float hx = __uint_as_float(hi << 16);
    float hy = __uint_as_float(hi & 0xFFFF0000u);
    float rx = v.x - hx;
    float ry = v.y - hy;
    asm("cvt.rn.bf16x2.f32 %0, %1, %2;" : "=r"(lo) : "f"(ry), "f"(rx));
}

// m16n8k16 bf16 MMA, fp32 accumulate (legacy HMMA path, valid at compute_103)
#define MMA_BF16(d, a0, a1, a2, a3, b0, b1) \
    asm volatile("mma.sync.aligned.m16n8k16.row.col.f32.bf16.bf16.f32 " \
        "{%0,%1,%2,%3}, {%4,%5,%6,%7}, {%8,%9}, {%0,%1,%2,%3};" \
        : "+f"((d)[0]), "+f"((d)[1]), "+f"((d)[2]), "+f"((d)[3]) \
        : "r"(a0), "r"(a1), "r"(a2), "r"(a3), "r"(b0), "r"(b1))

// ---------------- k0: beta/gamma precompute ----------------------------------
__global__ void k0_rates(const float* __restrict__ lb, const float* __restrict__ lg) {
    int i = blockIdx.x * blockDim.x + threadIdx.x;
    if (i < XD) {
        g_beta[i]  = softplusf(lb[i]);   // * DT (=1)
        g_gamma[i] = softplusf(lg[i]);
    }
}

// ---------------- k0b: W1 -> transposed bf16 split (128 rows, zero pad) -------
__global__ void k0b_w1split(const float* __restrict__ w1) {
    int idx = blockIdx.x * 256 + threadIdx.x;
    if (idx >= 128 * 2000) return;
    int n = idx / 2000, kw = idx - n * 2000;
    float2 v = make_float2(0.f, 0.f);
    if (n < HD) {
        v.x = w1[(size_t)(2 * kw) * HD + n];
        v.y = w1[(size_t)(2 * kw + 1) * HD + n];
    }
    uint32_t hi, lo;
    bfsplit2(v, hi, lo);
    g_w1hi[idx] = hi;
    g_w1lo[idx] = lo;
}

// ---------------- k0c: W2 -> transposed bf16 split (2048 x 56, zero pad) ------
__global__ void k0c_w2split(const float* __restrict__ w2) {
    int idx = blockIdx.x * 256 + threadIdx.x;
    if (idx >= 2048 * 56) return;
    int n = idx / 56, w = idx - n * 56;
    float2 v = make_float2(0.f, 0.f);
    if (n < XD && w < 50) {
        v.x = w2[(size_t)(2 * w) * XD + n];
        v.y = w2[(size_t)(2 * w + 1) * XD + n];
    }
    uint32_t hi, lo;
    bfsplit2(v, hi, lo);
    g_w2hi[idx] = hi;
    g_w2lo[idx] = lo;
}

// ---------------- k1: double-buffered mma.sync bf16-split, M-tile 64 ----------
// grid 256, N pad 128. 8 warps = 4 M-groups x 2 N-halves (m16 x n64 each).
// K chunks of 64 elem (32 kwords), 63 chunks. Double buffer + register prefetch.
#define K1RS 36
#define K1BUF 13824                 // words per buffer
#define K1_AHo 0
#define K1_ALo 2304
#define K1_BHo 4608
#define K1_BLo 9216
#define K1_SMEM_BYTES (2 * K1BUF * 4)   // 110592

__global__ void __launch_bounds__(256, 1) k1_mma(
    const float* __restrict__ s, const float* __restrict__ u,
    const float* __restrict__ b1)
{
    extern __shared__ uint32_t smu[];
    int tid = threadIdx.x, wid = tid >> 5, lane = tid & 31;
    int m0 = blockIdx.x * 64;
    int g = lane >> 2, tg = lane & 3;
    int mwarp = wid & 3, nh = wid >> 2;

    // staging maps: A 64 rows x 8 quad-slots -> 2/thread; B 128 n x 8 -> 4/thread
    int aRow[2], aW4[2];
#pragma unroll
    for (int t = 0; t < 2; t++) {
        int lin = tid + t * 256;
        aRow[t] = lin >> 3;
        aW4 [t] = (lin & 7) * 4;
    }
    int bN[4], bG4[4];
#pragma unroll
    for (int i = 0; i < 4; i++) {
        int lin = tid + i * 256;
        bN[i]  = lin >> 3;
        bG4[i] = (lin & 7) * 4;
    }

    float4 aP0[2], aP1[2];
    uint4 bPH[4], bPL[4];

#define K1_LDG(kw0_) do {                                                       \
        _Pragma("unroll")                                                       \
        for (int t_ = 0; t_ < 2; t_++) {                                        \
            int kw_ = (kw0_) + aW4[t_];                                         \
            aP0[t_] = make_float4(0.f,0.f,0.f,0.f); aP1[t_] = aP0[t_];          \
            if (kw_ < 1000) {                                                   \
                const float* p_ = &s[(size_t)(m0 + aRow[t_]) * XD + 2 * kw_];   \
                aP0[t_] = *(const float4*)p_; aP1[t_] = *(const float4*)(p_+4); \
            } else if (kw_ < 2000) {                                            \
                const float* p_ = &u[(size_t)(m0 + aRow[t_]) * XD + 2*kw_ - XD];\
                aP0[t_] = *(const float4*)p_; aP1[t_] = *(const float4*)(p_+4); \
            }                                                                   \
        }                                                                       \
        _Pragma("unroll")                                                       \
        for (int i_ = 0; i_ < 4; i_++) {                                        \
            int kb_ = (kw0_) + bG4[i_];                                         \
            if (kb_ < 2000) {                                                   \
                bPH[i_] = *(const uint4*)&g_w1hi[bN[i_] * 2000 + kb_];          \
                bPL[i_] = *(const uint4*)&g_w1lo[bN[i_] * 2000 + kb_];          \
            } else {                                                            \
                bPH[i_] = make_uint4(0u,0u,0u,0u); bPL[i_] = bPH[i_];           \
            }                                                                   \
        }                                                                       \
    } while (0)

#define K1_STS(b_) do {                                                         \
        _Pragma("unroll")                                                       \
        for (int t_ = 0; t_ < 2; t_++) {                                        \
            uint32_t h_[4], l_[4];                                              \
            bfsplit2(make_float2(aP0[t_].x, aP0[t_].y), h_[0], l_[0]);          \
            bfsplit2(make_float2(aP0[t_].z, aP0[t_].w), h_[1], l_[1]);          \
            bfsplit2(make_float2(aP1[t_].x, aP1[t_].y), h_[2], l_[2]);          \
            bfsplit2(make_float2(aP1[t_].z, aP1[t_].w), h_[3], l_[3]);          \
            *(uint4*)&smu[(b_)*K1BUF + K1_AHo + aRow[t_]*K1RS + aW4[t_]] =      \
                make_uint4(h_[0], h_[1], h_[2], h_[3]);                         \
            *(uint4*)&smu[(b_)*K1BUF + K1_ALo + aRow[t_]*K1RS + aW4[t_]] =      \
                make_uint4(l_[0], l_[1], l_[2], l_[3]);                         \
        }                                                                       \
        _Pragma("unroll")                                                       \
        for (int i_ = 0; i_ < 4; i_++) {                                        \
            *(uint4*)&smu[(b_)*K1BUF + K1_BHo + bN[i_]*K1RS + bG4[i_]] = bPH[i_];\
            *(uint4*)&smu[(b_)*K1BUF + K1_BLo + bN[i_]*K1RS + bG4[i_]] = bPL[i_];\
        }                                                                       \
    } while (0)

    float dM[8][4], dL[8][4];
#pragma unroll
    for (int j = 0; j < 8; j++)
#pragma unroll
        for (int e = 0; e < 4; e++) { dM[j][e] = 0.f; dL[j][e] = 0.f; }

    K1_LDG(0);
    K1_STS(0);
    __syncthreads();

    int b = 0;
    for (int c = 0; c < 63; c++) {
        if (c < 62) K1_LDG((c + 1) * 32);

        int abH = b * K1BUF + K1_AHo + (mwarp * 16 + g) * K1RS;
        int abL = abH + (K1_ALo - K1_AHo);
#pragma unroll
        for (int ks = 0; ks < 4; ks++) {
            int kw = ks * 8 + tg;
            uint32_t ah0 = smu[abH + kw];
            uint32_t ah1 = smu[abH + 8 * K1RS + kw];
            uint32_t ah2 = smu[abH + kw + 4];
            uint32_t ah3 = smu[abH + 8 * K1RS + kw + 4];
            uint32_t al0 = smu[abL + kw];
            uint32_t al1 = smu[abL + 8 * K1RS + kw];
            uint32_t al2 = smu[abL + kw + 4];
            uint32_t al3 = smu[abL + 8 * K1RS + kw + 4];
#pragma unroll
            for (int j = 0; j < 8; j++) {
                int bb = b * K1BUF + K1_BHo + (nh * 64 + 8 * j + g) * K1RS + kw;
                uint32_t bh0 = smu[bb];
                uint32_t bh1 = smu[bb + 4];
                uint32_t bl0 = smu[bb + (K1_BLo - K1_BHo)];
                uint32_t bl1 = smu[bb + (K1_BLo - K1_BHo) + 4];
                MMA_BF16(dM[j], ah0, ah1, ah2, ah3, bh0, bh1);
                MMA_BF16(dM[j], ah0, ah1, ah2, ah3, bl0, bl1);
                MMA_BF16(dL[j], al0, al1, al2, al3, bh0, bh1);
            }
        }

        if (c < 62) K1_STS(b ^ 1);
        __syncthreads();
        b ^= 1;
    }

    // ---- epilogue: LN over N per row (2 halves joined via smem) + GELU ----
    float* red = (float*)smu;    // [64 rows][2 halves][2 {sum,sq}]
    int lr0 = mwarp * 16 + g;
    int lr1 = lr0 + 8;

    float s0 = 0.f, q0 = 0.f, s1 = 0.f, q1 = 0.f;
#pragma unroll
    for (int j = 0; j < 8; j++) {
        int col = nh * 64 + 8 * j + 2 * tg;
        if (col < HD) {
            float bx = b1[col], by = b1[col + 1];
            float x0 = dM[j][0] + dL[j][0] + bx;
            float x1 = dM[j][1] + dL[j][1] + by;
            float x2 = dM[j][2] + dL[j][2] + bx;
            float x3 = dM[j][3] + dL[j][3] + by;
            s0 += x0 + x1; q0 += x0 * x0 + x1 * x1;
            s1 += x2 + x3; q1 += x2 * x2 + x3 * x3;
        }
    }
#pragma unroll
    for (int o = 1; o <= 2; o <<= 1) {
        s0 += __shfl_xor_sync(0xffffffffu, s0, o);
        q0 += __shfl_xor_sync(0xffffffffu, q0, o);
        s1 += __shfl_xor_sync(0xffffffffu, s1, o);
        q1 += __shfl_xor_sync(0xffffffffu, q1, o);
    }
    if (tg == 0) {
        red[(lr0 * 2 + nh) * 2 + 0] = s0;
        red[(lr0 * 2 + nh) * 2 + 1] = q0;
        red[(lr1 * 2 + nh) * 2 + 0] = s1;
        red[(lr1 * 2 + nh) * 2 + 1] = q1;
    }
    __syncthreads();

    float sum0 = red[(lr0*2+0)*2] + red[(lr0*2+1)*2];
    float sq0  = red[(lr0*2+0)*2+1] + red[(lr0*2+1)*2+1];
    float sum1 = red[(lr1*2+0)*2] + red[(lr1*2+1)*2];
    float sq1  = red[(lr1*2+0)*2+1] + red[(lr1*2+1)*2+1];
    float mean0 = sum0 * (1.f / HD);
    float mean1 = sum1 * (1.f / HD);
    float rs0 = rsqrtf(sq0 * (1.f / HD) - mean0 * mean0 + LN_EPS);
    float rs1 = rsqrtf(sq1 * (1.f / HD) - mean1 * mean1 + LN_EPS);

    int r0 = m0 + lr0, r1 = m0 + lr1;
#pragma unroll
    for (int j = 0; j < 8; j++) {
        int col = nh * 64 + 8 * j + 2 * tg;
        if (col < HD) {
            float bx = b1[col], by = b1[col + 1];
            float2 o0, o1;
            o0.x = geluf((dM[j][0] + dL[j][0] + bx - mean0) * rs0);
            o0.y = geluf((dM[j][1] + dL[j][1] + by - mean0) * rs0);
            o1.x = geluf((dM[j][2] + dL[j][2] + bx - mean1) * rs1);
            o1.y = geluf((dM[j][3] + dL[j][3] + by - mean1) * rs1);
            *(float2*)&g_h1[(size_t)r0 * HD + col] = o0;
            *(float2*)&g_h1[(size_t)r1 * HD + col] = o1;
        }
    }
}

// ---------------- k2: everything small, one warp per row ----------------------
#define K2_SMEM_FLOATS (22380 + 8*264)
__global__ void __launch_bounds__(256) k2_mid(
    const float* __restrict__ eps_z, const float* __restrict__ eps_d,
    const float* __restrict__ w2, const float* __restrict__ b2,
    const float* __restrict__ wmu, const float* __restrict__ bmu,
    const float* __restrict__ wlv, const float* __restrict__ blv,
    const float* __restrict__ edw1, const float* __restrict__ edb1,
    const float* __restrict__ edwmu, const float* __restrict__ edbmu,
    const float* __restrict__ edwlv, const float* __restrict__ edblv,
    const float* __restrict__ dzw1, const float* __restrict__ dzb1,
    float* __restrict__ o_z, float* __restrict__ o_dz,
    float* __restrict__ o_muz, float* __restrict__ o_scz,
    float* __restrict__ o_mud, float* __restrict__ o_scd)
{
    extern __shared__ float sm2[];
    float* sw2    = sm2;              // 10000
    float* swmu   = sw2 + 10000;      // 2000
    float* swlv   = swmu + 2000;      // 2000
    float* sb2    = swlv + 2000;      // 100
    float* sbmu   = sb2 + 100;        // 20
    float* sblv   = sbmu + 20;        // 20
    float* sedw1  = sblv + 20;        // 2000
    float* sedb1  = sedw1 + 2000;     // 100
    float* sedwmu = sedb1 + 100;      // 2000
    float* sedbmu = sedwmu + 2000;    // 20
    float* sedwlv = sedbmu + 20;      // 2000
    float* sedblv = sedwlv + 2000;    // 20
    float* sdzw1  = sedblv + 20;      // 2000
    float* sdzb1  = sdzw1 + 2000;     // 100
    float* wbuf   = sdzb1 + 100;      // 8 warps * 264

    {
        int t = threadIdx.x, nt = blockDim.x;
        for (int i = t; i < 10000; i += nt) sw2[i] = w2[i];
        for (int i = t; i < 2000; i += nt) { swmu[i] = wmu[i]; swlv[i] = wlv[i]; }
        for (int i = t; i < 2000; i += nt) { sedw1[i] = edw1[i]; sdzw1[i] = dzw1[i]; }
        for (int i = t; i < 2000; i += nt) { sedwmu[i] = edwmu[i]; sedwlv[i] = edwlv[i]; }
        for (int i = t; i < 100; i += nt) { sb2[i] = b2[i]; sedb1[i] = edb1[i]; sdzb1[i] = dzb1[i]; }
        if (t < 20) { sbmu[t] = bmu[t]; sblv[t] = blv[t]; sedbmu[t] = edbmu[t]; sedblv[t] = edblv[t]; }
    }
    __syncthreads();

    int wid = threadIdx.x >> 5, lane = threadIdx.x & 31;
    float* B0 = wbuf + wid * 264;
    float* B1 = B0 + 132;
    int nwarps = gridDim.x * 8;

    for (int r = blockIdx.x * 8 + wid; r < BB; r += nwarps) {
        for (int i = lane; i < HD; i += 32) B0[i] = g_h1[(size_t)r * HD + i];
        __syncwarp();

        float x[4] = {0.f, 0.f, 0.f, 0.f};
        if (lane < 25) {
            float4 bb4 = *(const float4*)&sb2[lane * 4];
            x[0] = bb4.x; x[1] = bb4.y; x[2] = bb4.z; x[3] = bb4.w;
            for (int k = 0; k < HD; k++) {
                float b = B0[k];
                float4 w = *(const float4*)&sw2[k * HD + lane * 4];
                x[0] = fmaf(b, w.x, x[0]);
                x[1] = fmaf(b, w.y, x[1]);
                x[2] = fmaf(b, w.z, x[2]);
                x[3] = fmaf(b, w.w, x[3]);
            }
        }
        float smv = x[0] + x[1] + x[2] + x[3];
        float sqv = x[0]*x[0] + x[1]*x[1] + x[2]*x[2] + x[3]*x[3];
        smv = wsum(smv); sqv = wsum(sqv);
        float mean = smv * (1.f / HD);
        float rs = rsqrtf(sqv * (1.f / HD) - mean * mean + LN_EPS);
        if (lane < 25) {
            float4 o;
            o.x = geluf((x[0] - mean) * rs);
            o.y = geluf((x[1] - mean) * rs);
            o.z = geluf((x[2] - mean) * rs);
            o.w = geluf((x[3] - mean) * rs);
            *(float4*)&B1[lane * 4] = o;
        }
        __syncwarp();

        if (lane < ZD) {
            float mu = sbmu[lane], lv = sblv[lane];
            for (int k = 0; k < HD; k++) {
                float h = B1[k];
                mu += h * swmu[k * ZD + lane];
                lv += h * swlv[k * ZD + lane];
            }
            float sc = softplusf(lv);
            float z = mu + sc * eps_z[(size_t)r * ZD + lane];
            o_z  [(size_t)r * ZD + lane] = z;
            o_muz[(size_t)r * ZD + lane] = mu;
            o_scz[(size_t)r * ZD + lane] = sc;
            B0[lane] = z;
        }
        __syncwarp();

        x[0] = x[1] = x[2] = x[3] = 0.f;
        if (lane < 25) {
            float4 bb4 = *(const float4*)&sedb1[lane * 4];
            x[0] = bb4.x; x[1] = bb4.y; x[2] = bb4.z; x[3] = bb4.w;
            for (int k = 0; k < ZD; k++) {
                float b = B0[k];
                float4 w = *(const float4*)&sedw1[k * HD + lane * 4];
                x[0] = fmaf(b, w.x, x[0]);
                x[1] = fmaf(b, w.y, x[1]);
                x[2] = fmaf(b, w.z, x[2]);
                x[3] = fmaf(b, w.w, x[3]);
            }
        }
        smv = x[0] + x[1] + x[2] + x[3];
        sqv = x[0]*x[0] + x[1]*x[1] + x[2]*x[2] + x[3]*x[3];
        smv = wsum(smv); sqv = wsum(sqv);
        mean = smv * (1.f / HD);
        rs = rsqrtf(sqv * (1.f / HD) - mean * mean + LN_EPS);
        if (lane < 25) {
            float4 o;
            o.x = geluf((x[0] - mean) * rs);
            o.y = geluf((x[1] - mean) * rs);
            o.z = geluf((x[2] - mean) * rs);
            o.w = geluf((x[3] - mean) * rs);
            *(float4*)&B1[lane * 4] = o;
        }
        __syncwarp();

        if (lane < ZD) {
            float mu = sedbmu[lane], lv = sedblv[lane];
            for (int k = 0; k < HD; k++) {
                float h = B1[k];
                mu += h * sedwmu[k * ZD + lane];
                lv += h * sedwlv[k * ZD + lane];
            }
            float sc = softplusf(lv);
            float dz = mu + sc * eps_d[(size_t)r * ZD + lane];
            o_dz [(size_t)r * ZD + lane] = dz;
            o_mud[(size_t)r * ZD + lane] = mu;
            o_scd[(size_t)r * ZD + lane] = sc;
            B0[32 + lane] = dz;
        }
        __syncwarp();

        float a[4] = {0.f,0.f,0.f,0.f}, t[4] = {0.f,0.f,0.f,0.f};
        if (lane < 25) {
            float4 bb4 = *(const float4*)&sdzb1[lane * 4];
            a[0] = bb4.x; a[1] = bb4.y; a[2] = bb4.z; a[3] = bb4.w;
            for (int k = 0; k < ZD; k++) {
                float zz = B0[k];
                float dd = B0[32 + k];
                float4 w = *(const float4*)&sdzw1[k * HD + lane * 4];
                a[0] = fmaf(zz, w.x, a[0]); t[0] = fmaf(dd, w.x, t[0]);
                a[1] = fmaf(zz, w.y, a[1]); t[1] = fmaf(dd, w.y, t[1]);
                a[2] = fmaf(zz, w.z, a[2]); t[2] = fmaf(dd, w.z, t[2]);
                a[3] = fmaf(zz, w.w, a[3]); t[3] = fmaf(dd, w.w, t[3]);
            }
        }
        float sa = a[0]+a[1]+a[2]+a[3];
        float saa = a[0]*a[0]+a[1]*a[1]+a[2]*a[2]+a[3]*a[3];
        float st = t[0]+t[1]+t[2]+t[3];
        float sat = a[0]*t[0]+a[1]*t[1]+a[2]*t[2]+a[3]*t[3];
        sa = wsum(sa); saa = wsum(saa); st = wsum(st); sat = wsum(sat);
        float m  = sa * (1.f / HD);
        float v  = saa * (1.f / HD) - m * m;
        float r2 = rsqrtf(v + LN_EPS);
        float dm = st * (1.f / HD);
        float dv = 2.f * (sat * (1.f / HD) - m * dm);
        if (lane < 25) {
            float4 oh, ot;
            float y, dy, Phi, phi;
#pragma unroll
            for (int j = 0; j < 4; j++) {
                y  = (a[j] - m) * r2;
                dy = r2 * (t[j] - dm) - 0.5f * y * r2 * r2 * dv;
                Phi = 0.5f * (1.f + erff(y * 0.70710678118654752f));
                phi = 0.3989422804014327f * expf(-0.5f * y * y);
                ((float*)&oh)[j] = y * Phi;
                ((float*)&ot)[j] = (Phi + y * phi) * dy;
            }
            *(float4*)&g_h1g[(size_t)r * HD + lane * 4] = oh;
            *(float4*)&g_th [(size_t)r * HD + lane * 4] = ot;
        }
        __syncwarp();
    }
}

// ---------------- k3: mma.sync bf16-split GEMM + fused finalize ---------------
#define RS3 60
#define TW3 (64*RS3)           // words per tile = 3840
#define OAHI 0
#define OALO (1*TW3)
#define OTHI (2*TW3)
#define OTLO (3*TW3)
#define OBHI (4*TW3)
#define OBLO (5*TW3)
#define K3_SMEM_BYTES (6*TW3*4)   // 92160

__global__ void __launch_bounds__(256, 2) k3_mma(
    const float* __restrict__ b2,
    float* __restrict__ o_shat, float* __restrict__ o_diff, float* __restrict__ o_pu)
{
    extern __shared__ uint32_t smu[];
    int tid = threadIdx.x, wid = tid >> 5, lane = tid & 31;
    int m0 = blockIdx.x * 64;

    // ---- stage A tiles once (zero-pad k-words 50..55) ----
    for (int lin = tid; lin < 64 * 56; lin += 256) {
        int row = lin / 56, w = lin - row * 56;
        float2 h2 = make_float2(0.f, 0.f), t2 = h2;
        if (w < 50) {
            h2 = *(const float2*)&g_h1g[(size_t)(m0 + row) * HD + 2 * w];
            t2 = *(const float2*)&g_th [(size_t)(m0 + row) * HD + 2 * w];
        }
        uint32_t hh, hl, th, tl;
        bfsplit2(h2, hh, hl);
        bfsplit2(t2, th, tl);
        int o = row * RS3 + w;
        smu[OAHI + o] = hh;
        smu[OALO + o] = hl;
        smu[OTHI + o] = th;
        smu[OTLO + o] = tl;
    }

    int g = lane >> 2, tg = lane & 3;
    int mrow = (wid & 3) * 16;
    int nbh = wid >> 2;             // 0/1
    int nb = nbh * 32;
    int arow0 = (mrow + g) * RS3;
    int arow1 = (mrow + 8 + g) * RS3;

    float sl0 = 0.f, st0 = 0.f, sl1 = 0.f, st1 = 0.f;   // fused row sums

    for (int ch = 0; ch < 32; ch++) {
        int n0 = ch * 64;
        // ---- stage W chunk: pure uint4 copy from precomputed split ----
        for (int lin = tid; lin < 64 * 14; lin += 256) {
            int n = lin / 14, w4 = (lin - n * 14) * 4;
            size_t src = (size_t)(n0 + n) * 56 + w4;
            *(uint4*)&smu[OBHI + n * RS3 + w4] = *(const uint4*)&g_w2hi[src];
            *(uint4*)&smu[OBLO + n * RS3 + w4] = *(const uint4*)&g_w2lo[src];
        }
        __syncthreads();

        float dH[4][4], dT[4][4];
#pragma unroll
        for (int j = 0; j < 4; j++)
#pragma unroll
            for (int e = 0; e < 4; e++) { dH[j][e] = 0.f; dT[j][e] = 0.f; }

#pragma unroll
        for (int ks = 0; ks < 7; ks++) {
            int kw = ks * 8;
            uint32_t ah0 = smu[OAHI + arow0 + kw + tg];
            uint32_t ah1 = smu[OAHI + arow1 + kw + tg];
            uint32_t ah2 = smu[OAHI + arow0 + kw + 4 + tg];
            uint32_t ah3 = smu[OAHI + arow1 + kw + 4 + tg];
            uint32_t al0 = smu[OALO + arow0 + kw + tg];
            uint32_t al1 = smu[OALO + arow1 + kw + tg];
            uint32_t al2 = smu[OALO + arow0 + kw + 4 + tg];
            uint32_t al3 = smu[OALO + arow1 + kw + 4 + tg];
            uint32_t th0 = smu[OTHI + arow0 + kw + tg];
            uint32_t th1 = smu[OTHI + arow1 + kw + tg];
            uint32_t th2 = smu[OTHI + arow0 + kw + 4 + tg];
            uint32_t th3 = smu[OTHI + arow1 + kw + 4 + tg];
            uint32_t tl0 = smu[OTLO + arow0 + kw + tg];
            uint32_t tl1 = smu[OTLO + arow1 + kw + tg];
            uint32_t tl2 = smu[OTLO + arow0 + kw + 4 + tg];
            uint32_t tl3 = smu[OTLO + arow1 + kw + 4 + tg];
#pragma unroll
            for (int j = 0; j < 4; j++) {
                int brow = (nb + j * 8 + g) * RS3;
                uint32_t bh0 = smu[OBHI + brow + kw + tg];
                uint32_t bh1 = smu[OBHI + brow + kw + 4 + tg];
                uint32_t bl0 = smu[OBLO + brow + kw + tg];
                uint32_t bl1 = smu[OBLO + brow + kw + 4 + tg];
                MMA_BF16(dH[j], ah0, ah1, ah2, ah3, bh0, bh1);
                MMA_BF16(dH[j], ah0, ah1, ah2, ah3, bl0, bl1);
                MMA_BF16(dH[j], al0, al1, al2, al3, bh0, bh1);
                MMA_BF16(dT[j], th0, th1, th2, th3, bh0, bh1);
                MMA_BF16(dT[j], th0, th1, th2, th3, bl0, bl1);
                MMA_BF16(dT[j], tl0, tl1, tl2, tl3, bh0, bh1);
            }
        }
        __syncthreads();   // all smem reads done before next chunk's staging

        // ---- epilogue: bias + softplus / sigmoid*tangent, store + accumulate --
        int r0 = m0 + mrow + g;
        int r1 = r0 + 8;
#pragma unroll
        for (int j = 0; j < 4; j++) {
            int c0 = n0 + nb + j * 8 + 2 * tg;
            if (c0 < XD) {
                float bx = b2[c0], by = b2[c0 + 1];
                float a0 = dH[j][0] + bx, a1 = dH[j][1] + by;
                float a2 = dH[j][2] + bx, a3 = dH[j][3] + by;
                float2 l0, t0, l1, t1;
                l0.x = softplusf(a0); t0.x = sigmoidf(a0) * dT[j][0];
                l0.y = softplusf(a1); t0.y = sigmoidf(a1) * dT[j][1];
                l1.x = softplusf(a2); t1.x = sigmoidf(a2) * dT[j][2];
                l1.y = softplusf(a3); t1.y = sigmoidf(a3) * dT[j][3];
                *(float2*)&g_ld [(size_t)r0 * XD + c0] = l0;
                *(float2*)&g_tld[(size_t)r0 * XD + c0] = t0;
                *(float2*)&g_ld [(size_t)r1 * XD + c0] = l1;
                *(float2*)&g_tld[(size_t)r1 * XD + c0] = t1;
                sl0 += l0.x + l0.y; st0 += t0.x + t0.y;
                sl1 += l1.x + l1.y; st1 += t1.x + t1.y;
            }
        }
    }

    // ---- fused k4: per-row mean normalize + outputs ----
#pragma unroll
    for (int o = 1; o <= 2; o <<= 1) {
        sl0 += __shfl_xor_sync(0xffffffffu, sl0, o);
        st0 += __shfl_xor_sync(0xffffffffu, st0, o);
        sl1 += __shfl_xor_sync(0xffffffffu, sl1, o);
        st1 += __shfl_xor_sync(0xffffffffu, st1, o);
    }
    float* redf = (float*)smu;          // [64 rows][2 nbh][2]
    float* rowst = redf + 256;          // [64 rows][2 {rm, cm}]
    if (tg == 0) {
        int rr0 = mrow + g, rr1 = rr0 + 8;
        redf[(rr0 * 2 + nbh) * 2 + 0] = sl0;
        redf[(rr0 * 2 + nbh) * 2 + 1] = st0;
        redf[(rr1 * 2 + nbh) * 2 + 0] = sl1;
        redf[(rr1 * 2 + nbh) * 2 + 1] = st1;
    }
    __syncthreads();
    for (int r = tid; r < 64; r += 256) {
        float sl = redf[(r * 2 + 0) * 2 + 0] + redf[(r * 2 + 1) * 2 + 0];
        float st = redf[(r * 2 + 0) * 2 + 1] + redf[(r * 2 + 1) * 2 + 1];
        float m  = sl * (1.f / XD);
        float mt = st * (1.f / XD);
        rowst[r * 2 + 0] = 1.f / m;
        rowst[r * 2 + 1] = mt / (m * m);
    }
    __syncthreads();

    for (int lin = tid; lin < 64 * 500; lin += 256) {
        int row = lin / 500;
        int c = (lin - row * 500) * 4;
        float rm = rowst[row * 2 + 0];
        float cm = rowst[row * 2 + 1];
        size_t off = (size_t)(m0 + row) * XD + c;
        float4 l  = *(const float4*)&g_ld [off];
        float4 tl = *(const float4*)&g_tld[off];
        float4 be = *(const float4*)&g_beta[c];
        float4 ga = *(const float4*)&g_gamma[c];
        float4 sh, df, pu;
        sh.x = l.x * rm; df.x = 0.01f * (tl.x * rm - l.x * cm);
        sh.y = l.y * rm; df.y = 0.01f * (tl.y * rm - l.y * cm);
        sh.z = l.z * rm; df.z = 0.01f * (tl.z * rm - l.z * cm);
        sh.w = l.w * rm; df.w = 0.01f * (tl.w * rm - l.w * cm);
        pu.x = fmaxf((df.x + sh.x * ga.x) / be.x, 0.f);
        pu.y = fmaxf((df.y + sh.y * ga.y) / be.y, 0.f);
        pu.z = fmaxf((df.z + sh.z * ga.z) / be.z, 0.f);
        pu.w = fmaxf((df.w + sh.w * ga.w) / be.w, 0.f);
        *(float4*)&o_shat[off] = sh;
        *(float4*)&o_diff[off] = df;
        *(float4*)&o_pu  [off] = pu;
    }
}

// ---------------- launcher ----------------------------------------------------
extern "C" void kernel_launch(void* const* d_in, const int* in_sizes, int n_in,
                              void* d_out, int out_size)
{
    const float* s      = (const float*)d_in[0];
    const float* u      = (const float*)d_in[1];
    const float* eps_z  = (const float*)d_in[2];
    const float* eps_d  = (const float*)d_in[3];
    const float* ez_w1  = (const float*)d_in[4];
    const float* ez_b1  = (const float*)d_in[5];
    const float* ez_w2  = (const float*)d_in[6];
    const float* ez_b2  = (const float*)d_in[7];
    const float* ez_wmu = (const float*)d_in[8];
    const float* ez_bmu = (const float*)d_in[9];
    const float* ez_wlv = (const float*)d_in[10];
    const float* ez_blv = (const float*)d_in[11];
    const float* ed_w1  = (const float*)d_in[12];
    const float* ed_b1  = (const float*)d_in[13];
    const float* ed_wmu = (const float*)d_in[14];
    const float* ed_bmu = (const float*)d_in[15];
    const float* ed_wlv = (const float*)d_in[16];
    const float* ed_blv = (const float*)d_in[17];
    const float* dz_w1  = (const float*)d_in[18];
    const float* dz_b1  = (const float*)d_in[19];
    const float* dz_w2  = (const float*)d_in[20];
    const float* dz_b2  = (const float*)d_in[21];
    const float* logb   = (const float*)d_in[22];
    const float* logg   = (const float*)d_in[23];

    float* out = (float*)d_out;
    float* o_z    = out;
    float* o_dz   = o_z    + (size_t)BB * ZD;
    float* o_muz  = o_dz   + (size_t)BB * ZD;
    float* o_scz  = o_muz  + (size_t)BB * ZD;
    float* o_mud  = o_scz  + (size_t)BB * ZD;
    float* o_scd  = o_mud  + (size_t)BB * ZD;
    float* o_shat = o_scd  + (size_t)BB * ZD;
    float* o_diff = o_shat + (size_t)BB * XD;
    float* o_pu   = o_diff + (size_t)BB * XD;

    const int smem2 = K2_SMEM_FLOATS * 4;
    cudaFuncSetAttribute(k1_mma, cudaFuncAttributeMaxDynamicSharedMemorySize, K1_SMEM_BYTES);
    cudaFuncSetAttribute(k2_mid, cudaFuncAttributeMaxDynamicSharedMemorySize, smem2);
    cudaFuncSetAttribute(k3_mma, cudaFuncAttributeMaxDynamicSharedMemorySize, K3_SMEM_BYTES);

    k0_rates<<<8, 256>>>(logb, logg);
    k0b_w1split<<<(128 * 2000 + 255) / 256, 256>>>(ez_w1);
    k0c_w2split<<<(2048 * 56 + 255) / 256, 256>>>(dz_w2);
    k1_mma<<<BB / 64, 256, K1_SMEM_BYTES>>>(s, u, ez_b1);
    k2_mid<<<512, 256, smem2>>>(eps_z, eps_d,
                                ez_w2, ez_b2, ez_wmu, ez_bmu, ez_wlv, ez_blv,
                                ed_w1, ed_b1, ed_wmu, ed_bmu, ed_wlv, ed_blv,
                                dz_w1, dz_b1,
                                o_z, o_dz, o_muz, o_scz, o_mud, o_scd);
    k3_mma<<<BB / 64, 256, K3_SMEM_BYTES>>>(dz_b2, o_shat, o_diff, o_pu);
}